// round 14
// baseline (speedup 1.0000x reference)
#include <cuda_runtime.h>
#include <cuda_fp16.h>
#include <math.h>
#include <stdint.h>

#define Bb 2
#define Tt 2048
#define DM 2048
#define Hh 16
#define HD 128
#define KVL 512
#define QL 1024
#define Rr 64
#define MROWS (Bb*Tt)
#define BH (Bb*Hh)
#define HHD (Hh*HD)
#define HRr (Hh*Rr)

#if defined(__CUDA_ARCH_FEAT_SM103_ALL) || defined(__CUDA_ARCH_FEAT_SM100_ALL)
#define HAS_TCGEN05 1
#else
#define HAS_TCGEN05 0
#endif

// ---------------- scratch ----------------
__device__ __half g_xH[MROWS * DM],  g_xL[MROWS * DM];
__device__ __half g_cKVh[MROWS * KVL], g_cKVl[MROWS * KVL];
__device__ __half g_cQh[MROWS * QL],   g_cQl[MROWS * QL];
__device__ __half g_Qch[MROWS * HHD],  g_Qcl[MROWS * HHD];
__device__ __half g_Qrh[MROWS * HRr],  g_Qrl[MROWS * HRr];
__device__ __half g_Kch[MROWS * HHD],  g_Kcl[MROWS * HHD];
__device__ __half g_Krh[MROWS * Rr],   g_Krl[MROWS * Rr];
__device__ __half g_Vth[BH * HD * Tt], g_Vtl[BH * HD * Tt];
__device__ __half g_AOh[MROWS * HHD],  g_AOl[MROWS * HHD];
#define O_DKV 0
#define O_UK  (O_DKV + 512*2048)
#define O_UV  (O_UK  + 2048*512)
#define O_DQ  (O_UV  + 2048*512)
#define O_UQ  (O_DQ  + 1024*2048)
#define O_QR  (O_UQ  + 2048*1024)
#define O_O   (O_QR  + 2048*1024)
#define O_KRP (O_O   + 2048*2048)
#define WT_TOTAL (O_KRP + 256*2048)
__device__ __half g_WtH[WT_TOTAL], g_WtL[WT_TOTAL];   // zero-init: KRP pad rows stay 0

// ---------------- helpers ----------------
__device__ __forceinline__ uint32_t smem_u32(const void* p) {
    uint32_t a;
    asm("{ .reg .u64 t; cvta.to.shared.u64 t, %1; cvt.u32.u64 %0, t; }"
        : "=r"(a) : "l"(p));
    return a;
}
__device__ __forceinline__ void split_pair(float a, float b,
                                           uint32_t& hi, uint32_t& lo) {
    __half ha = __float2half_rn(a), hb = __float2half_rn(b);
    hi = ((uint32_t)__half_as_ushort(hb) << 16) | __half_as_ushort(ha);
    lo = ((uint32_t)__half_as_ushort(__float2half_rn(b - __half2float(hb))) << 16)
       | __half_as_ushort(__float2half_rn(a - __half2float(ha)));
}

#if HAS_TCGEN05
__device__ __forceinline__ bool elect1() {
    uint32_t r;
    asm volatile("{\n\t.reg .pred p;\n\telect.sync _|p, 0xFFFFFFFF;\n\t"
                 "selp.b32 %0,1,0,p;\n\t}" : "=r"(r));
    return r != 0;
}
#define MBAR_INIT(a, c) \
    asm volatile("mbarrier.init.shared.b64 [%0], %1;" :: "r"(a), "r"(c) : "memory")
#define MBAR_WAIT(a, ph) do { \
    uint32_t _m = (a), _p = (uint32_t)(ph), _d; \
    asm volatile("{\n\t.reg .pred p;\n\t" \
        "mbarrier.try_wait.parity.acquire.cta.shared::cta.b64 p, [%1], %2;\n\t" \
        "selp.b32 %0,1,0,p;\n\t}" : "=r"(_d) : "r"(_m), "r"(_p) : "memory"); \
    while (!_d) { \
        asm volatile("{\n\t.reg .pred p;\n\t" \
            "mbarrier.try_wait.parity.acquire.cta.shared::cta.b64 p, [%1], %2, 0x989680;\n\t" \
            "selp.b32 %0,1,0,p;\n\t}" : "=r"(_d) : "r"(_m), "r"(_p) : "memory"); \
    } } while (0)
#define T5_COMMIT(a) \
    asm volatile("tcgen05.commit.cta_group::1.mbarrier::arrive::one.shared::cluster.b64 [%0];" \
                 :: "r"(a) : "memory")
#define T5_ALLOC(a, n) \
    asm volatile("tcgen05.alloc.cta_group::1.sync.aligned.shared::cta.b32 [%0], %1;" \
                 :: "r"(a), "r"(n) : "memory")
#define T5_DEALLOC(t, n) \
    asm volatile("tcgen05.dealloc.cta_group::1.sync.aligned.b32 %0, %1;" :: "r"(t), "r"(n))
#define T5_RELINQ() \
    asm volatile("tcgen05.relinquish_alloc_permit.cta_group::1.sync.aligned;")
#define T5_WAIT_LD()   asm volatile("tcgen05.wait::ld.sync.aligned;" ::: "memory")
#define T5_FENCE_AFTER() asm volatile("tcgen05.fence::after_thread_sync;" ::: "memory")
#define T5_FENCE_BEFORE() asm volatile("tcgen05.fence::before_thread_sync;" ::: "memory")
#define FENCE_ASYNC()  asm volatile("fence.proxy.async.shared::cta;" ::: "memory")
#define CP_ASYNC16(dst, src) \
    asm volatile("cp.async.cg.shared.global [%0], [%1], 16;" \
                 :: "r"(dst), "l"(src) : "memory")
#define CP_COMMIT() asm volatile("cp.async.commit_group;" ::: "memory")
#define CP_WAIT(n)  asm volatile("cp.async.wait_group %0;" :: "n"(n) : "memory")

#define LDTM_X32(r, addr) \
    asm volatile("tcgen05.ld.sync.aligned.32x32b.x32.b32 " \
        "{%0, %1, %2, %3, %4, %5, %6, %7, %8, %9, %10, %11, %12, %13, %14, %15, " \
        "%16, %17, %18, %19, %20, %21, %22, %23, %24, %25, %26, %27, %28, %29, %30, %31}, [%32];" \
        : "=r"((r)[0]),  "=r"((r)[1]),  "=r"((r)[2]),  "=r"((r)[3]), \
          "=r"((r)[4]),  "=r"((r)[5]),  "=r"((r)[6]),  "=r"((r)[7]), \
          "=r"((r)[8]),  "=r"((r)[9]),  "=r"((r)[10]), "=r"((r)[11]), \
          "=r"((r)[12]), "=r"((r)[13]), "=r"((r)[14]), "=r"((r)[15]), \
          "=r"((r)[16]), "=r"((r)[17]), "=r"((r)[18]), "=r"((r)[19]), \
          "=r"((r)[20]), "=r"((r)[21]), "=r"((r)[22]), "=r"((r)[23]), \
          "=r"((r)[24]), "=r"((r)[25]), "=r"((r)[26]), "=r"((r)[27]), \
          "=r"((r)[28]), "=r"((r)[29]), "=r"((r)[30]), "=r"((r)[31]) \
        : "r"(addr))

__device__ __forceinline__ void mma_f16(uint32_t d, uint64_t ad, uint64_t bd,
                                        uint32_t idesc, uint32_t en) {
    asm volatile("{\n\t.reg .pred p;\n\tsetp.ne.u32 p, %4, 0;\n\t"
        "tcgen05.mma.cta_group::1.kind::f16 [%0], %1, %2, %3, p;\n\t}"
        :: "r"(d), "l"(ad), "l"(bd), "r"(idesc), "r"(en) : "memory");
}
__device__ __forceinline__ uint64_t mk_desc(uint32_t addr) {
    return ((uint64_t)2 << 61) | ((uint64_t)1 << 46) | ((uint64_t)64 << 32)
         | ((uint64_t)1 << 16) | ((addr >> 4) & 0x3FFF);
}
__device__ __forceinline__ void sts128(uint32_t addr, uint32_t a, uint32_t b,
                                       uint32_t c, uint32_t d) {
    asm volatile("st.shared.v4.b32 [%0], {%1,%2,%3,%4};"
                 :: "r"(addr), "r"(a), "r"(b), "r"(c), "r"(d) : "memory");
}
struct MmaCtx { uint32_t mb, mb_done, tmem, tiles; };
__device__ __forceinline__ MmaCtx mma_begin(char* smem, int ncols) {
    MmaCtx cx;
    uint32_t sbase = smem_u32(smem);
    cx.mb = sbase;
    cx.mb_done = sbase + 24;
    cx.tiles = (sbase + 64 + 1023) & ~1023u;
    if (threadIdx.x == 0) {
        MBAR_INIT(cx.mb + 0, 1);
        MBAR_INIT(cx.mb + 8, 1);
        MBAR_INIT(cx.mb + 16, 1);
        MBAR_INIT(cx.mb_done, 1);
    }
    if (threadIdx.x < 32) { T5_ALLOC(sbase + 32, ncols); T5_RELINQ(); }
    __syncthreads();
    asm volatile("ld.shared.b32 %0, [%1];" : "=r"(cx.tmem) : "r"(sbase + 32));
    return cx;
}
// 12 MMAs (hh, hl, lh) for one K=64 chunk (flash kernel, N=128)
__device__ __forceinline__ void mma_chunk(uint32_t tmem, uint32_t mbar,
                                          uint64_t ah, uint64_t al,
                                          uint64_t bh, uint64_t bl,
                                          uint32_t idesc, bool first) {
    if (threadIdx.x < 32 && elect1()) {
        #pragma unroll
        for (int q = 0; q < 4; q++)
            mma_f16(tmem, ah + 2*q, bh + 2*q, idesc, (first && q == 0) ? 0u : 1u);
        #pragma unroll
        for (int q = 0; q < 4; q++)
            mma_f16(tmem, ah + 2*q, bl + 2*q, idesc, 1u);
        #pragma unroll
        for (int q = 0; q < 4; q++)
            mma_f16(tmem, al + 2*q, bh + 2*q, idesc, 1u);
        T5_COMMIT(mbar);
    }
}

// ---------------- N=256 GEMM mainloop: 2-stage, K-chunk 64 ----------------
// Stage: A hi(16K)|A lo(16K)|B hi(32K)|B lo(32K) = 96 KB.
__device__ __forceinline__ void issue_chunk_cp256(
    const __half* const psrc[4], int K, int k0, uint32_t st)
{
    const int tid = threadIdx.x;
    #pragma unroll
    for (int i = 0; i < 24; i++) {
        int u = i * 256 + tid;                 // 0..6143 (16B units)
        int t, ul;
        uint32_t tb;
        if (u < 2048) { t = u >> 10; ul = u & 1023; tb = (uint32_t)t * 16384u; }
        else {
            int v2 = u - 2048;
            t = 2 + (v2 >> 11);
            ul = v2 & 2047;
            tb = 32768u + (uint32_t)(t - 2) * 32768u;
        }
        int row = ul >> 3, seg = ul & 7;
        uint32_t bofs = row * 128 + seg * 16;
        uint32_t da = st + tb + (bofs ^ ((bofs >> 3) & 0x70));
        CP_ASYNC16(da, psrc[t] + (size_t)row * K + k0 + seg * 8);
    }
    CP_COMMIT();
}

__device__ __forceinline__ MmaCtx gemm_main256(
    const __half* Ah, const __half* Al,
    const __half* Bh, const __half* Bl, int K)
{
    constexpr int STAGE = 98304;
    extern __shared__ char smem[];
    MmaCtx cx = mma_begin(smem, 256);
    const int tid = threadIdx.x;
    const uint32_t idesc = (1u << 4) | (32u << 17) | (8u << 24);   // N=256
    const int nc = K >> 6;
    const __half* psrc[4] = {Ah, Al, Bh, Bl};

    issue_chunk_cp256(psrc, K, 0, cx.tiles);
    issue_chunk_cp256(psrc, K, 64, cx.tiles + STAGE);

    for (int c = 0; c < nc; c++) {
        const int s = c & 1;
        const uint32_t st = cx.tiles + s * STAGE;
        if (c == nc - 1) CP_WAIT(0); else CP_WAIT(1);
        FENCE_ASYNC();
        __syncthreads();
        if (tid < 32 && elect1()) {
            uint64_t ah = mk_desc(st),           al = mk_desc(st + 16384);
            uint64_t bh = mk_desc(st + 32768),   bl = mk_desc(st + 65536);
            #pragma unroll
            for (int q = 0; q < 4; q++)
                mma_f16(cx.tmem, ah + 2*q, bh + 2*q, idesc,
                        (c == 0 && q == 0) ? 0u : 1u);
            #pragma unroll
            for (int q = 0; q < 4; q++)
                mma_f16(cx.tmem, ah + 2*q, bl + 2*q, idesc, 1u);
            #pragma unroll
            for (int q = 0; q < 4; q++)
                mma_f16(cx.tmem, al + 2*q, bh + 2*q, idesc, 1u);
            T5_COMMIT(cx.mb + 8 * s);
        }
        const int cn = c + 2;
        if (cn < nc) {
            MBAR_WAIT(cx.mb + 8 * s, (c >> 1) & 1);   // MMA(c) done -> stage free
            issue_chunk_cp256(psrc, K, cn * 64, st);
        }
    }
    if (tid < 32 && elect1()) T5_COMMIT(cx.mb_done);
    MBAR_WAIT(cx.mb_done, 0);
    T5_FENCE_AFTER();
    return cx;
}
#else
__device__ __forceinline__ float dot_hl(
    const __half* Ah, const __half* Al,
    const __half* Bh, const __half* Bl, int K, int r, int c)
{
    float acc = 0.f;
    for (int k = 0; k < K; k++)
        acc += (__half2float(Ah[(size_t)r*K+k]) + __half2float(Al[(size_t)r*K+k]))
             * (__half2float(Bh[(size_t)c*K+k]) + __half2float(Bl[(size_t)c*K+k]));
    return acc;
}
#endif

// ---------------- producers ----------------
__global__ __launch_bounds__(256) void split_x_kernel(
    const float* __restrict__ x, __half* __restrict__ xh, __half* __restrict__ xl)
{
    size_t i = (size_t)(blockIdx.x * 256 + threadIdx.x) * 4;
    float4 v = *reinterpret_cast<const float4*>(&x[i]);
    uint32_t h0, l0, h1, l1;
    split_pair(v.x, v.y, h0, l0);
    split_pair(v.z, v.w, h1, l1);
    *reinterpret_cast<uint2*>(&xh[i]) = make_uint2(h0, h1);
    *reinterpret_cast<uint2*>(&xl[i]) = make_uint2(l0, l1);
}

struct TSJob { const float* W; __half* H; __half* L; int K; int N; int tile0; };
struct TSJobs { TSJob a[8]; };

__global__ __launch_bounds__(256) void tsplit_all_kernel(TSJobs jobs)
{
    __shared__ float t[32][33];
    int bx = blockIdx.x;
    int ji = 0;
    #pragma unroll
    for (int i = 1; i < 8; i++)
        if (bx >= jobs.a[i].tile0) ji = i;
    TSJob j = jobs.a[ji];
    int tl = bx - j.tile0;
    int ntN = j.N >> 5;
    int n0 = (tl % ntN) * 32, k0 = (tl / ntN) * 32;
    int tx = threadIdx.x & 31, ty = threadIdx.x >> 5;
    #pragma unroll
    for (int i = ty; i < 32; i += 8)
        t[i][tx] = j.W[(size_t)(k0 + i) * j.N + n0 + tx];
    __syncthreads();
    #pragma unroll
    for (int i = ty; i < 32; i += 8) {
        float v = t[tx][i];
        __half h = __float2half_rn(v);
        j.H[(size_t)(n0 + i) * j.K + k0 + tx] = h;
        j.L[(size_t)(n0 + i) * j.K + k0 + tx] = __float2half_rn(v - __half2float(h));
    }
}

// ---------------- xproj: bx 0-1 cKV | 2-5 cQ | 6 KR(+rope) ----------------
__global__ __launch_bounds__(256) void xproj_kernel(
    const __half* __restrict__ xh, const __half* __restrict__ xl,
    const __half* __restrict__ WtH, const __half* __restrict__ WtL,
    const float* __restrict__ freqs,
    float* __restrict__ cKVf, __half* __restrict__ cKVh, __half* __restrict__ cKVl,
    __half* __restrict__ cQh, __half* __restrict__ cQl,
    float* __restrict__ KRo, __half* __restrict__ Krh, __half* __restrict__ Krl)
{
    const int bx = blockIdx.x, bm = blockIdx.y * 128;
#if HAS_TCGEN05
    const __half* Ah = xh + (size_t)bm * DM;
    const __half* Al = xl + (size_t)bm * DM;
    size_t bo = (bx < 2) ? O_DKV + (size_t)(bx * 256) * DM
              : (bx < 6) ? O_DQ + (size_t)((bx - 2) * 256) * DM
              : (size_t)O_KRP;
    MmaCtx cx = gemm_main256(Ah, Al, WtH + bo, WtL + bo, DM);

    const int w = threadIdx.x >> 5, l2 = threadIdx.x & 31;
    const int sub = w & 3, colh = w >> 2;
    const int rowl = sub * 32 + l2;
    const int m = bm + rowl;
    if (bx < 6) {
        for (int b2 = colh * 4; b2 < colh * 4 + 4; b2++) {
            uint32_t r[32];
            LDTM_X32(r, cx.tmem + b2 * 32);
            T5_WAIT_LD();
            if (bx < 2) {
                size_t off = (size_t)m * KVL + bx * 256 + b2 * 32;
                #pragma unroll
                for (int j = 0; j < 32; j += 4)
                    *reinterpret_cast<float4*>(&cKVf[off + j]) = make_float4(
                        __uint_as_float(r[j]), __uint_as_float(r[j+1]),
                        __uint_as_float(r[j+2]), __uint_as_float(r[j+3]));
                #pragma unroll
                for (int j = 0; j < 32; j += 8) {
                    uint4 hv, lv;
                    split_pair(__uint_as_float(r[j+0]), __uint_as_float(r[j+1]), hv.x, lv.x);
                    split_pair(__uint_as_float(r[j+2]), __uint_as_float(r[j+3]), hv.y, lv.y);
                    split_pair(__uint_as_float(r[j+4]), __uint_as_float(r[j+5]), hv.z, lv.z);
                    split_pair(__uint_as_float(r[j+6]), __uint_as_float(r[j+7]), hv.w, lv.w);
                    *reinterpret_cast<uint4*>(&cKVh[off + j]) = hv;
                    *reinterpret_cast<uint4*>(&cKVl[off + j]) = lv;
                }
            } else {
                size_t off = (size_t)m * QL + (bx - 2) * 256 + b2 * 32;
                #pragma unroll
                for (int j = 0; j < 32; j += 8) {
                    uint4 hv, lv;
                    split_pair(__uint_as_float(r[j+0]), __uint_as_float(r[j+1]), hv.x, lv.x);
                    split_pair(__uint_as_float(r[j+2]), __uint_as_float(r[j+3]), hv.y, lv.y);
                    split_pair(__uint_as_float(r[j+4]), __uint_as_float(r[j+5]), hv.z, lv.z);
                    split_pair(__uint_as_float(r[j+6]), __uint_as_float(r[j+7]), hv.w, lv.w);
                    *reinterpret_cast<uint4*>(&cQh[off + j]) = hv;
                    *reinterpret_cast<uint4*>(&cQl[off + j]) = lv;
                }
            }
        }
    } else if (colh == 0) {
        // KR: cols 0..63 real (weight rows 64..255 are zero pad)
        const int t = m & (Tt - 1);
        for (int b2 = 0; b2 < 2; b2++) {
            uint32_t r[32];
            LDTM_X32(r, cx.tmem + b2 * 32);
            T5_WAIT_LD();
            #pragma unroll
            for (int j = 0; j < 32; j += 2) {
                int col = b2 * 32 + j;
                float f = freqs[t * (Rr / 2) + (col >> 1)], s, c;
                sincosf(f, &s, &c);
                float x0 = __uint_as_float(r[j]), x1 = __uint_as_float(r[j + 1]);
                float y0 = x0 * c - x1 * s, y1 = x0 * s + x1 * c;
                size_t off = (size_t)m * Rr + col;
                KRo[off] = y0;
                KRo[off + 1] = y1;
                uint32_t hi, lo;
                split_pair(y0, y1, hi, lo);
                *reinterpret_cast<uint32_t*>(&Krh[off]) = hi;
                *reinterpret_cast<uint32_t*>(&Krl[off]) = lo;
            }
        }
    }
    __syncthreads();
    if (threadIdx.x < 32) T5_DEALLOC(cx.tmem, 256);
#else
    const int tid = threadIdx.x;
    for (int e = tid; e < 128 * 256; e += 256) {
        int rr = e >> 8, cc = e & 255;
        int m = bm + rr;
        if (bx < 2) {
            float acc = dot_hl(xh + (size_t)bm*DM, xl + (size_t)bm*DM,
                               g_WtH + O_DKV + (size_t)(bx*256)*DM,
                               g_WtL + O_DKV + (size_t)(bx*256)*DM, DM, rr, cc);
            size_t off = (size_t)m * KVL + bx * 256 + cc;
            cKVf[off] = acc;
            __half h = __float2half_rn(acc);
            cKVh[off] = h;
            cKVl[off] = __float2half_rn(acc - __half2float(h));
        } else if (bx < 6) {
            float acc = dot_hl(xh + (size_t)bm*DM, xl + (size_t)bm*DM,
                               g_WtH + O_DQ + (size_t)((bx-2)*256)*DM,
                               g_WtL + O_DQ + (size_t)((bx-2)*256)*DM, DM, rr, cc);
            size_t off = (size_t)m * QL + (bx - 2) * 256 + cc;
            __half h = __float2half_rn(acc);
            cQh[off] = h;
            cQl[off] = __float2half_rn(acc - __half2float(h));
        } else if (cc < Rr && (cc & 1) == 0) {
            float x0 = dot_hl(xh + (size_t)bm*DM, xl + (size_t)bm*DM,
                              g_WtH + O_KRP, g_WtL + O_KRP, DM, rr, cc);
            float x1 = dot_hl(xh + (size_t)bm*DM, xl + (size_t)bm*DM,
                              g_WtH + O_KRP, g_WtL + O_KRP, DM, rr, cc + 1);
            int t = m & (Tt - 1);
            float f = freqs[t * (Rr / 2) + (cc >> 1)], s, c;
            sincosf(f, &s, &c);
            float y0 = x0 * c - x1 * s, y1 = x0 * s + x1 * c;
            size_t off = (size_t)m * Rr + cc;
            KRo[off] = y0; KRo[off + 1] = y1;
            __half h0 = __float2half_rn(y0), h1 = __float2half_rn(y1);
            Krh[off] = h0; Krh[off + 1] = h1;
            Krl[off] = __float2half_rn(y0 - __half2float(h0));
            Krl[off + 1] = __float2half_rn(y1 - __half2float(h1));
        }
    }
#endif
}

// ---------------- kqproj: bx 0-7 UK | 8-15 UV | 16-23 UQ | 24-27 QR -------
__global__ __launch_bounds__(256) void kqproj_kernel(
    const __half* __restrict__ cKVh, const __half* __restrict__ cKVl,
    const __half* __restrict__ cQh, const __half* __restrict__ cQl,
    const __half* __restrict__ WtH, const __half* __restrict__ WtL,
    const float* __restrict__ freqs,
    __half* __restrict__ Kch, __half* __restrict__ Kcl,
    __half* __restrict__ Vth, __half* __restrict__ Vtl,
    __half* __restrict__ Qch, __half* __restrict__ Qcl,
    __half* __restrict__ Qrh, __half* __restrict__ Qrl)
{
    const int bx = blockIdx.x, bm = blockIdx.y * 128;
#if HAS_TCGEN05
    const __half *Ah, *Al;
    size_t bo;
    int K;
    if (bx < 16) {
        Ah = cKVh + (size_t)bm * KVL;
        Al = cKVl + (size_t)bm * KVL;
        K = KVL;
        bo = (bx < 8) ? O_UK + (size_t)(bx * 256) * KVL
                      : O_UV + (size_t)((bx - 8) * 256) * KVL;
    } else {
        Ah = cQh + (size_t)bm * QL;
        Al = cQl + (size_t)bm * QL;
        K = QL;
        bo = (bx < 24) ? O_UQ + (size_t)((bx - 16) * 256) * QL
                       : O_QR + (size_t)((bx - 24) * 256) * QL;
    }
    MmaCtx cx = gemm_main256(Ah, Al, WtH + bo, WtL + bo, K);

    const int w = threadIdx.x >> 5, l2 = threadIdx.x & 31;
    const int sub = w & 3, colh = w >> 2;
    const int rowl = sub * 32 + l2;
    const int m = bm + rowl;
    const int t = m & (Tt - 1);
    for (int b2 = colh * 4; b2 < colh * 4 + 4; b2++) {
        uint32_t r[32];
        LDTM_X32(r, cx.tmem + b2 * 32);
        T5_WAIT_LD();
        if (bx < 8) {
            size_t off = (size_t)m * HHD + bx * 256 + b2 * 32;
            #pragma unroll
            for (int j = 0; j < 32; j += 8) {
                uint4 hv, lv;
                split_pair(__uint_as_float(r[j+0]), __uint_as_float(r[j+1]), hv.x, lv.x);
                split_pair(__uint_as_float(r[j+2]), __uint_as_float(r[j+3]), hv.y, lv.y);
                split_pair(__uint_as_float(r[j+4]), __uint_as_float(r[j+5]), hv.z, lv.z);
                split_pair(__uint_as_float(r[j+6]), __uint_as_float(r[j+7]), hv.w, lv.w);
                *reinterpret_cast<uint4*>(&Kch[off + j]) = hv;
                *reinterpret_cast<uint4*>(&Kcl[off + j]) = lv;
            }
        } else if (bx < 16) {
            const int bq = m >> 11, tloc = m & (Tt - 1);
            #pragma unroll
            for (int j = 0; j < 32; j++) {
                int gcol = (bx - 8) * 256 + b2 * 32 + j;
                int hh2 = gcol >> 7, d = gcol & 127;
                float v = __uint_as_float(r[j]);
                __half vh = __float2half_rn(v);
                size_t off = ((size_t)(bq * Hh + hh2) * HD + d) * Tt + tloc;
                Vth[off] = vh;
                Vtl[off] = __float2half_rn(v - __half2float(vh));
            }
        } else if (bx < 24) {
            size_t off = (size_t)m * HHD + (bx - 16) * 256 + b2 * 32;
            #pragma unroll
            for (int j = 0; j < 32; j += 8) {
                uint4 hv, lv;
                split_pair(__uint_as_float(r[j+0]), __uint_as_float(r[j+1]), hv.x, lv.x);
                split_pair(__uint_as_float(r[j+2]), __uint_as_float(r[j+3]), hv.y, lv.y);
                split_pair(__uint_as_float(r[j+4]), __uint_as_float(r[j+5]), hv.z, lv.z);
                split_pair(__uint_as_float(r[j+6]), __uint_as_float(r[j+7]), hv.w, lv.w);
                *reinterpret_cast<uint4*>(&Qch[off + j]) = hv;
                *reinterpret_cast<uint4*>(&Qcl[off + j]) = lv;
            }
        } else {
            #pragma unroll
            for (int j = 0; j < 32; j += 2) {
                int gcol = (bx - 24) * 256 + b2 * 32 + j;
                float f = freqs[t * (Rr / 2) + ((gcol & 63) >> 1)], s, c;
                sincosf(f, &s, &c);
                float x0 = __uint_as_float(r[j]), x1 = __uint_as_float(r[j + 1]);
                float y0 = x0 * c - x1 * s, y1 = x0 * s + x1 * c;
                uint32_t hi, lo;
                split_pair(y0, y1, hi, lo);
                size_t off = (size_t)m * HRr + gcol;
                *reinterpret_cast<uint32_t*>(&Qrh[off]) = hi;
                *reinterpret_cast<uint32_t*>(&Qrl[off]) = lo;
            }
        }
    }
    __syncthreads();
    if (threadIdx.x < 32) T5_DEALLOC(cx.tmem, 256);
#else
    const int tid = threadIdx.x;
    for (int e = tid; e < 128 * 256; e += 256) {
        int rr = e >> 8, cc = e & 255;
        int m = bm + rr;
        if (bx < 8) {
            float acc = dot_hl(cKVh + (size_t)bm*KVL, cKVl + (size_t)bm*KVL,
                               g_WtH + O_UK + (size_t)(bx*256)*KVL,
                               g_WtL + O_UK + (size_t)(bx*256)*KVL, KVL, rr, cc);
            size_t off = (size_t)m * HHD + bx * 256 + cc;
            __half h = __float2half_rn(acc);
            Kch[off] = h;
            Kcl[off] = __float2half_rn(acc - __half2float(h));
        } else if (bx < 16) {
            float acc = dot_hl(cKVh + (size_t)bm*KVL, cKVl + (size_t)bm*KVL,
                               g_WtH + O_UV + (size_t)((bx-8)*256)*KVL,
                               g_WtL + O_UV + (size_t)((bx-8)*256)*KVL, KVL, rr, cc);
            int gcol = (bx - 8) * 256 + cc;
            int hh2 = gcol >> 7, d = gcol & 127;
            int bq = m >> 11, tloc = m & (Tt - 1);
            size_t off = ((size_t)(bq * Hh + hh2) * HD + d) * Tt + tloc;
            __half h = __float2half_rn(acc);
            Vth[off] = h;
            Vtl[off] = __float2half_rn(acc - __half2float(h));
        } else if (bx < 24) {
            float acc = dot_hl(cQh + (size_t)bm*QL, cQl + (size_t)bm*QL,
                               g_WtH + O_UQ + (size_t)((bx-16)*256)*QL,
                               g_WtL + O_UQ + (size_t)((bx-16)*256)*QL, QL, rr, cc);
            size_t off = (size_t)m * HHD + (bx - 16) * 256 + cc;
            __half h = __float2half_rn(acc);
            Qch[off] = h;
            Qcl[off] = __float2half_rn(acc - __half2float(h));
        } else if ((cc & 1) == 0) {
            float x0 = dot_hl(cQh + (size_t)bm*QL, cQl + (size_t)bm*QL,
                              g_WtH + O_QR + (size_t)((bx-24)*256)*QL,
                              g_WtL + O_QR + (size_t)((bx-24)*256)*QL, QL, rr, cc);
            float x1 = dot_hl(cQh + (size_t)bm*QL, cQl + (size_t)bm*QL,
                              g_WtH + O_QR + (size_t)((bx-24)*256)*QL,
                              g_WtL + O_QR + (size_t)((bx-24)*256)*QL, QL, rr, cc + 1);
            int gcol = (bx - 24) * 256 + cc;
            int t = m & (Tt - 1);
            float f = freqs[t * (Rr / 2) + ((gcol & 63) >> 1)], s, c;
            sincosf(f, &s, &c);
            float y0 = x0 * c - x1 * s, y1 = x0 * s + x1 * c;
            size_t off = (size_t)m * HRr + gcol;
            __half h0 = __float2half_rn(y0), h1 = __float2half_rn(y1);
            Qrh[off] = h0; Qrh[off + 1] = h1;
            Qrl[off] = __float2half_rn(y0 - __half2float(h0));
            Qrl[off + 1] = __float2half_rn(y1 - __half2float(h1));
        }
    }
#endif
}

// ---------------- wo: y = AO @ W_O (N=256 tiles) ----------------
__global__ __launch_bounds__(256) void wo_kernel(
    const __half* __restrict__ AOh, const __half* __restrict__ AOl,
    const __half* __restrict__ WtH, const __half* __restrict__ WtL,
    float* __restrict__ y)
{
    const int bx = blockIdx.x, bm = blockIdx.y * 128;
#if HAS_TCGEN05
    size_t bo = O_O + (size_t)(bx * 256) * HHD;
    MmaCtx cx = gemm_main256(AOh + (size_t)bm * HHD, AOl + (size_t)bm * HHD,
                             WtH + bo, WtL + bo, HHD);
    const int w = threadIdx.x >> 5, l2 = threadIdx.x & 31;
    const int sub = w & 3, colh = w >> 2;
    const int m = bm + sub * 32 + l2;
    for (int b2 = colh * 4; b2 < colh * 4 + 4; b2++) {
        uint32_t r[32];
        LDTM_X32(r, cx.tmem + b2 * 32);
        T5_WAIT_LD();
        size_t off = (size_t)m * DM + bx * 256 + b2 * 32;
        #pragma unroll
        for (int j = 0; j < 32; j += 4)
            *reinterpret_cast<float4*>(&y[off + j]) = make_float4(
                __uint_as_float(r[j]), __uint_as_float(r[j+1]),
                __uint_as_float(r[j+2]), __uint_as_float(r[j+3]));
    }
    __syncthreads();
    if (threadIdx.x < 32) T5_DEALLOC(cx.tmem, 256);
#else
    const int tid = threadIdx.x;
    for (int e = tid; e < 128 * 256; e += 256) {
        int rr = e >> 8, cc = e & 255;
        float acc = dot_hl(AOh + (size_t)bm*HHD, AOl + (size_t)bm*HHD,
                           g_WtH + O_O + (size_t)(bx*256)*HHD,
                           g_WtL + O_O + (size_t)(bx*256)*HHD, HHD, rr, cc);
        y[(size_t)(bm + rr) * DM + bx * 256 + cc] = acc;
    }
#endif
}

// ---------------- fused flash attention (unchanged) ----------------
__global__ __launch_bounds__(256) void flash_kernel(
    const __half* __restrict__ Qch, const __half* __restrict__ Qcl,
    const __half* __restrict__ Qrh, const __half* __restrict__ Qrl,
    const __half* __restrict__ Kch, const __half* __restrict__ Kcl,
    const __half* __restrict__ Krh, const __half* __restrict__ Krl,
    const __half* __restrict__ Vth, const __half* __restrict__ Vtl,
    __half* __restrict__ AOh, __half* __restrict__ AOl)
{
    const int qt = 15 - blockIdx.x, bh = blockIdx.y;
    const int tid = threadIdx.x;
    const int b = bh >> 4, h = bh & 15;
    const float scale = 0.07216878364870323f;   // 1/sqrt(192)
#if HAS_TCGEN05
    constexpr int T_BYTES = 16384;
    extern __shared__ char smem[];
    MmaCtx cx = mma_begin(smem, 256);
    const uint32_t qbase  = cx.tiles;
    const uint32_t pbase  = qbase + 6 * T_BYTES;
    const uint32_t redmax = pbase + 2 * T_BYTES;
    const uint32_t redsum = redmax + 1024;
    const uint32_t bufb   = redsum + 1024;
    const uint32_t idesc = (1u << 4) | (16u << 17) | (8u << 24);
    const uint32_t tmemS = cx.tmem, tmemO = cx.tmem + 128;
    const size_t qrow0 = (size_t)(b * Tt + qt * 128);

    {
        const __half* qsrc[6] = {
            Qch + qrow0 * HHD + h * HD,       Qcl + qrow0 * HHD + h * HD,
            Qch + qrow0 * HHD + h * HD + 64,  Qcl + qrow0 * HHD + h * HD + 64,
            Qrh + qrow0 * HRr + h * Rr,       Qrl + qrow0 * HRr + h * Rr };
        const int qstr[6] = {HHD, HHD, HHD, HHD, HRr, HRr};
        #pragma unroll
        for (int i = 0; i < 24; i++) {
            int u = i * 256 + tid;
            int t = u >> 10, ul = u & 1023;
            int row = ul >> 3, seg = ul & 7;
            uint4 v = *reinterpret_cast<const uint4*>(
                qsrc[t] + (size_t)row * qstr[t] + seg * 8);
            uint32_t bo = row * 128 + seg * 16;
            sts128(qbase + t * T_BYTES + (bo ^ ((bo >> 3) & 0x70)),
                   v.x, v.y, v.z, v.w);
        }
    }

    const int w = tid >> 5, l2 = tid & 31, sub = w & 3, halfi = w >> 2;
    const int rowl = sub * 32 + l2;
    const int qglob = qt * 128 + rowl;
    float oacc[64];
    #pragma unroll
    for (int j = 0; j < 64; j++) oacc[j] = 0.f;
    float mrow = -INFINITY, lrow = 0.f;
    int u0 = 0, u1 = 0;

    for (int kt = 0; kt <= qt; kt++) {
        const size_t krow0 = (size_t)(b * Tt + kt * 128);
        for (int c = 0; c < 3; c++) {
            const int bid = c & 1;
            int cnt = bid ? u1 : u0;
            const uint32_t st = bufb + bid * 2 * T_BYTES;
            const __half* kh = (c < 2) ? Kch + krow0 * HHD + h * HD + c * 64
                                       : Krh + krow0 * Rr;
            const __half* kl = (c < 2) ? Kcl + krow0 * HHD + h * HD + c * 64
                                       : Krl + krow0 * Rr;
            const int str = (c < 2) ? HHD : Rr;
            uint4 v[8];
            uint32_t da[8];
            #pragma unroll
            for (int i = 0; i < 8; i++) {
                int u = i * 256 + tid;
                int t = u >> 10, ul = u & 1023;
                int row = ul >> 3, seg = ul & 7;
                const __half* src = t ? kl : kh;
                v[i] = *reinterpret_cast<const uint4*>(
                    src + (size_t)row * str + seg * 8);
                uint32_t bo = row * 128 + seg * 16;
                da[i] = st + t * T_BYTES + (bo ^ ((bo >> 3) & 0x70));
            }
            if (cnt > 0) MBAR_WAIT(cx.mb + 8 * bid, (cnt - 1) & 1);
            #pragma unroll
            for (int i = 0; i < 8; i++)
                sts128(da[i], v[i].x, v[i].y, v[i].z, v[i].w);
            FENCE_ASYNC();
            __syncthreads();
            mma_chunk(tmemS, cx.mb + 8 * bid,
                      mk_desc(qbase + (2 * c) * T_BYTES),
                      mk_desc(qbase + (2 * c + 1) * T_BYTES),
                      mk_desc(st), mk_desc(st + T_BYTES), idesc, c == 0);
            if (bid) u1++; else u0++;
        }
        MBAR_WAIT(cx.mb + 0, (u0 - 1) & 1);
        T5_FENCE_AFTER();

        uint32_t sr[32];
        float sv[64];
        LDTM_X32(sr, tmemS + halfi * 64);
        T5_WAIT_LD();
        #pragma unroll
        for (int j = 0; j < 32; j++) sv[j] = __uint_as_float(sr[j]) * scale;
        LDTM_X32(sr, tmemS + halfi * 64 + 32);
        T5_WAIT_LD();
        #pragma unroll
        for (int j = 0; j < 32; j++) sv[32 + j] = __uint_as_float(sr[j]) * scale;
        T5_FENCE_BEFORE();
        if (kt == qt) {
            int cbase = kt * 128 + halfi * 64;
            #pragma unroll
            for (int j = 0; j < 64; j++)
                if (cbase + j > qglob) sv[j] = -INFINITY;
        }
        float pmax = -INFINITY;
        #pragma unroll
        for (int j = 0; j < 64; j++) pmax = fmaxf(pmax, sv[j]);
        asm volatile("st.shared.f32 [%0], %1;"
                     :: "r"(redmax + (halfi * 128 + rowl) * 4), "f"(pmax) : "memory");
        __syncthreads();
        float omax;
        asm volatile("ld.shared.f32 %0, [%1];"
                     : "=f"(omax) : "r"(redmax + ((1 - halfi) * 128 + rowl) * 4));
        float mnew = fmaxf(mrow, fmaxf(pmax, omax));
        float alpha = __expf(mrow - mnew);
        mrow = mnew;
        float psum = 0.f;
        uint32_t pw[32];
        #pragma unroll
        for (int j = 0; j < 32; j++) {
            float p0 = __expf(sv[2 * j] - mnew);
            float p1 = __expf(sv[2 * j + 1] - mnew);
            psum += p0 + p1;
            pw[j] = ((uint32_t)__half_as_ushort(__float2half_rn(p1)) << 16)
                  | __half_as_ushort(__float2half_rn(p0));
        }
        #pragma unroll
        for (int sgm = 0; sgm < 8; sgm++) {
            uint32_t bo = rowl * 128 + sgm * 16;
            sts128(pbase + halfi * T_BYTES + (bo ^ ((bo >> 3) & 0x70)),
                   pw[sgm * 4], pw[sgm * 4 + 1], pw[sgm * 4 + 2], pw[sgm * 4 + 3]);
        }
        asm volatile("st.shared.f32 [%0], %1;"
                     :: "r"(redsum + (halfi * 128 + rowl) * 4), "f"(psum) : "memory");
        FENCE_ASYNC();
        __syncthreads();
        float osum;
        asm volatile("ld.shared.f32 %0, [%1];"
                     : "=f"(osum) : "r"(redsum + ((1 - halfi) * 128 + rowl) * 4));
        lrow = lrow * alpha + psum + osum;

        for (int c = 0; c < 2; c++) {
            const int bid = c;
            int cnt = bid ? u1 : u0;
            const uint32_t st = bufb + bid * 2 * T_BYTES;
            const __half* vh = Vth + (size_t)bh * HD * Tt + kt * 128 + c * 64;
            const __half* vl = Vtl + (size_t)bh * HD * Tt + kt * 128 + c * 64;
            uint4 v[8];
            uint32_t da[8];
            #pragma unroll
            for (int i = 0; i < 8; i++) {
                int u = i * 256 + tid;
                int t = u >> 10, ul = u & 1023;
                int row = ul >> 3, seg = ul & 7;
                const __half* src = t ? vl : vh;
                v[i] = *reinterpret_cast<const uint4*>(
                    src + (size_t)row * Tt + seg * 8);
                uint32_t bo = row * 128 + seg * 16;
                da[i] = st + t * T_BYTES + (bo ^ ((bo >> 3) & 0x70));
            }
            if (cnt > 0) MBAR_WAIT(cx.mb + 8 * bid, (cnt - 1) & 1);
            #pragma unroll
            for (int i = 0; i < 8; i++)
                sts128(da[i], v[i].x, v[i].y, v[i].z, v[i].w);
            FENCE_ASYNC();
            __syncthreads();
            if (tid < 32 && elect1()) {
                uint64_t pd = mk_desc(pbase + c * T_BYTES);
                uint64_t vhd = mk_desc(st), vld = mk_desc(st + T_BYTES);
                #pragma unroll
                for (int q = 0; q < 4; q++)
                    mma_f16(tmemO, pd + 2 * q, vhd + 2 * q, idesc,
                            (c == 0 && q == 0) ? 0u : 1u);
                #pragma unroll
                for (int q = 0; q < 4; q++)
                    mma_f16(tmemO, pd + 2 * q, vld + 2 * q, idesc, 1u);
                T5_COMMIT(cx.mb + 8 * bid);
            }
            if (bid) u1++; else u0++;
        }
        MBAR_WAIT(cx.mb + 8, (u1 - 1) & 1);
        T5_FENCE_AFTER();
        LDTM_X32(sr, tmemO + halfi * 64);
        T5_WAIT_LD();
        #pragma unroll
        for (int j = 0; j < 32; j++)
            oacc[j] = oacc[j] * alpha + __uint_as_float(sr[j]);
        LDTM_X32(sr, tmemO + halfi * 64 + 32);
        T5_WAIT_LD();
        #pragma unroll
        for (int j = 0; j < 32; j++)
            oacc[32 + j] = oacc[32 + j] * alpha + __uint_as_float(sr[j]);
        T5_FENCE_BEFORE();
        __syncthreads();
    }

    const float invl = 1.0f / lrow;
    const size_t off = (size_t)(b * Tt + qt * 128 + rowl) * HHD + h * HD + halfi * 64;
    #pragma unroll
    for (int j = 0; j < 64; j += 8) {
        uint4 hv, lv;
        split_pair(oacc[j+0] * invl, oacc[j+1] * invl, hv.x, lv.x);
        split_pair(oacc[j+2] * invl, oacc[j+3] * invl, hv.y, lv.y);
        split_pair(oacc[j+4] * invl, oacc[j+5] * invl, hv.z, lv.z);
        split_pair(oacc[j+6] * invl, oacc[j+7] * invl, hv.w, lv.w);
        *reinterpret_cast<uint4*>(&AOh[off + j]) = hv;
        *reinterpret_cast<uint4*>(&AOl[off + j]) = lv;
    }
    __syncthreads();
    if (tid < 32) T5_DEALLOC(cx.tmem, 256);
#else
    for (int e = tid; e < 128 * 128; e += 256) {
        int r = e >> 7, d = e & 127;
        int qg = qt * 128 + r;
        size_t qoC = (size_t)(b * Tt + qg) * HHD + h * HD;
        size_t qoR = (size_t)(b * Tt + qg) * HRr + h * Rr;
        float m = -1e30f;
        for (int k = 0; k <= qg; k++) {
            size_t koC = (size_t)(b * Tt + k) * HHD + h * HD;
            size_t koR = (size_t)(b * Tt + k) * Rr;
            float s = 0.f;
            for (int dd = 0; dd < HD; dd++)
                s += (__half2float(Qch[qoC+dd]) + __half2float(Qcl[qoC+dd]))
                   * (__half2float(Kch[koC+dd]) + __half2float(Kcl[koC+dd]));
            for (int dd = 0; dd < Rr; dd++)
                s += (__half2float(Qrh[qoR+dd]) + __half2float(Qrl[qoR+dd]))
                   * (__half2float(Krh[koR+dd]) + __half2float(Krl[koR+dd]));
            s *= scale;
            if (s > m) m = s;
        }
        float l = 0.f, o = 0.f;
        for (int k = 0; k <= qg; k++) {
            size_t koC = (size_t)(b * Tt + k) * HHD + h * HD;
            size_t koR = (size_t)(b * Tt + k) * Rr;
            float s = 0.f;
            for (int dd = 0; dd < HD; dd++)
                s += (__half2float(Qch[qoC+dd]) + __half2float(Qcl[qoC+dd]))
                   * (__half2float(Kch[koC+dd]) + __half2float(Kcl[koC+dd]));
            for (int dd = 0; dd < Rr; dd++)
                s += (__half2float(Qrh[qoR+dd]) + __half2float(Qrl[qoR+dd]))
                   * (__half2float(Krh[koR+dd]) + __half2float(Krl[koR+dd]));
            float p = expf(s * scale - m);
            l += p;
            o += p * (__half2float(Vth[((size_t)bh*HD + d)*Tt + k])
                    + __half2float(Vtl[((size_t)bh*HD + d)*Tt + k]));
        }
        o /= l;
        size_t off = (size_t)(b * Tt + qg) * HHD + h * HD + d;
        __half hh = __float2half_rn(o);
        AOh[off] = hh;
        AOl[off] = __float2half_rn(o - __half2float(hh));
    }
#endif
}

// ---------------- launch ----------------
#define MMA_SMEM 198656      // ctx + 2 x 96KB stages
#define FLASH_SMEM 202752

extern "C" void kernel_launch(void* const* d_in, const int* in_sizes, int n_in,
                              void* d_out, int out_size)
{
    const float* x     = (const float*)d_in[0];
    const float* freqs = (const float*)d_in[1];
    const float* W_DKV = (const float*)d_in[2];
    const float* W_UK  = (const float*)d_in[3];
    const float* W_UV  = (const float*)d_in[4];
    const float* W_KR  = (const float*)d_in[5];
    const float* W_DQ  = (const float*)d_in[6];
    const float* W_UQ  = (const float*)d_in[7];
    const float* W_QR  = (const float*)d_in[8];
    const float* W_O   = (const float*)d_in[9];

    float* y   = (float*)d_out;
    float* cKV = y   + (size_t)Bb * Tt * DM;
    float* KRo = cKV + (size_t)Bb * Tt * KVL;

    __half *pxH, *pxL, *pWtH, *pWtL, *pcKVh, *pcKVl, *pcQh, *pcQl;
    __half *pQch, *pQcl, *pQrh, *pQrl, *pKch, *pKcl, *pKrh, *pKrl;
    __half *pVth, *pVtl, *pAOh, *pAOl;
    cudaGetSymbolAddress((void**)&pxH,  g_xH);
    cudaGetSymbolAddress((void**)&pxL,  g_xL);
    cudaGetSymbolAddress((void**)&pWtH, g_WtH);
    cudaGetSymbolAddress((void**)&pWtL, g_WtL);
    cudaGetSymbolAddress((void**)&pcKVh, g_cKVh);
    cudaGetSymbolAddress((void**)&pcKVl, g_cKVl);
    cudaGetSymbolAddress((void**)&pcQh, g_cQh);
    cudaGetSymbolAddress((void**)&pcQl, g_cQl);
    cudaGetSymbolAddress((void**)&pQch, g_Qch);
    cudaGetSymbolAddress((void**)&pQcl, g_Qcl);
    cudaGetSymbolAddress((void**)&pQrh, g_Qrh);
    cudaGetSymbolAddress((void**)&pQrl, g_Qrl);
    cudaGetSymbolAddress((void**)&pKch, g_Kch);
    cudaGetSymbolAddress((void**)&pKcl, g_Kcl);
    cudaGetSymbolAddress((void**)&pKrh, g_Krh);
    cudaGetSymbolAddress((void**)&pKrl, g_Krl);
    cudaGetSymbolAddress((void**)&pVth, g_Vth);
    cudaGetSymbolAddress((void**)&pVtl, g_Vtl);
    cudaGetSymbolAddress((void**)&pAOh, g_AOh);
    cudaGetSymbolAddress((void**)&pAOl, g_AOl);

    cudaFuncSetAttribute(xproj_kernel,  cudaFuncAttributeMaxDynamicSharedMemorySize, MMA_SMEM);
    cudaFuncSetAttribute(kqproj_kernel, cudaFuncAttributeMaxDynamicSharedMemorySize, MMA_SMEM);
    cudaFuncSetAttribute(wo_kernel,     cudaFuncAttributeMaxDynamicSharedMemorySize, MMA_SMEM);
    cudaFuncSetAttribute(flash_kernel,  cudaFuncAttributeMaxDynamicSharedMemorySize, FLASH_SMEM);

    // #1: split x
    split_x_kernel<<<(MROWS * DM / 4) / 256, 256>>>(x, pxH, pxL);

    // #2: all weight transposes (KR padded to 256-col tile; pad rows stay 0)
    TSJobs jobs;
    int tiles = 0;
    auto addjob = [&](int i, const float* W, size_t off, int K, int N) {
        jobs.a[i] = {W, pWtH + off, pWtL + off, K, N, tiles};
        tiles += (K / 32) * (N / 32);
    };
    addjob(0, W_DKV, O_DKV, DM, KVL);
    addjob(1, W_UK,  O_UK,  KVL, HHD);
    addjob(2, W_UV,  O_UV,  KVL, HHD);
    addjob(3, W_DQ,  O_DQ,  DM, QL);
    addjob(4, W_UQ,  O_UQ,  QL, HHD);
    addjob(5, W_QR,  O_QR,  QL, HRr);
    addjob(6, W_O,   O_O,   HHD, DM);
    addjob(7, W_KR,  O_KRP, DM, Rr);
    tsplit_all_kernel<<<tiles, 256>>>(jobs);

    // #3: xproj (cKV | cQ | KR+rope), N=256 tiles
    xproj_kernel<<<dim3(7, MROWS/128), 256, MMA_SMEM>>>(
        pxH, pxL, pWtH, pWtL, freqs, cKV, pcKVh, pcKVl, pcQh, pcQl,
        KRo, pKrh, pKrl);
    // #4: merged kv+q projections (UK|UV|UQ|QR), N=256 tiles
    kqproj_kernel<<<dim3(28, MROWS/128), 256, MMA_SMEM>>>(
        pcKVh, pcKVl, pcQh, pcQl, pWtH, pWtL, freqs,
        pKch, pKcl, pVth, pVtl, pQch, pQcl, pQrh, pQrl);
    // #5: fused flash attention
    flash_kernel<<<dim3(16, BH), 256, FLASH_SMEM>>>(
        pQch, pQcl, pQrh, pQrl, pKch, pKcl, pKrh, pKrl, pVth, pVtl, pAOh, pAOl);
    // #6: y = AO @ W_O, N=256 tiles
    wo_kernel<<<dim3(8, MROWS/128), 256, MMA_SMEM>>>(pAOh, pAOl, pWtH, pWtL, y);
}

// round 15
// speedup vs baseline: 1.0608x; 1.0608x over previous
#include <cuda_runtime.h>
#include <cuda_fp16.h>
#include <math.h>
#include <stdint.h>

#define Bb 2
#define Tt 2048
#define DM 2048
#define Hh 16
#define HD 128
#define KVL 512
#define QL 1024
#define Rr 64
#define MROWS (Bb*Tt)
#define BH (Bb*Hh)
#define HHD (Hh*HD)
#define HRr (Hh*Rr)

#if defined(__CUDA_ARCH_FEAT_SM103_ALL) || defined(__CUDA_ARCH_FEAT_SM100_ALL)
#define HAS_TCGEN05 1
#else
#define HAS_TCGEN05 0
#endif

// ---------------- scratch ----------------
__device__ __half g_xH[MROWS * DM],  g_xL[MROWS * DM];
__device__ __half g_cKVh[MROWS * KVL], g_cKVl[MROWS * KVL];
__device__ __half g_cQh[MROWS * QL],   g_cQl[MROWS * QL];
__device__ __half g_Qch[MROWS * HHD],  g_Qcl[MROWS * HHD];
__device__ __half g_Qrh[MROWS * HRr],  g_Qrl[MROWS * HRr];
__device__ __half g_Kch[MROWS * HHD],  g_Kcl[MROWS * HHD];
__device__ __half g_Krh[MROWS * Rr],   g_Krl[MROWS * Rr];
__device__ __half g_Vth[BH * HD * Tt], g_Vtl[BH * HD * Tt];
__device__ __half g_AOh[MROWS * HHD],  g_AOl[MROWS * HHD];
#define O_DKV 0
#define O_UK  (O_DKV + 512*2048)
#define O_UV  (O_UK  + 2048*512)
#define O_DQ  (O_UV  + 2048*512)
#define O_UQ  (O_DQ  + 1024*2048)
#define O_QR  (O_UQ  + 2048*1024)
#define O_O   (O_QR  + 2048*1024)
#define O_KRP (O_O   + 2048*2048)
#define WT_TOTAL (O_KRP + 128*2048)
__device__ __half g_WtH[WT_TOTAL], g_WtL[WT_TOTAL];   // zero-init: KRP pad rows stay 0

// ---------------- helpers ----------------
__device__ __forceinline__ uint32_t smem_u32(const void* p) {
    uint32_t a;
    asm("{ .reg .u64 t; cvta.to.shared.u64 t, %1; cvt.u32.u64 %0, t; }"
        : "=r"(a) : "l"(p));
    return a;
}
__device__ __forceinline__ void split_pair(float a, float b,
                                           uint32_t& hi, uint32_t& lo) {
    __half ha = __float2half_rn(a), hb = __float2half_rn(b);
    hi = ((uint32_t)__half_as_ushort(hb) << 16) | __half_as_ushort(ha);
    lo = ((uint32_t)__half_as_ushort(__float2half_rn(b - __half2float(hb))) << 16)
       | __half_as_ushort(__float2half_rn(a - __half2float(ha)));
}

#if HAS_TCGEN05
__device__ __forceinline__ bool elect1() {
    uint32_t r;
    asm volatile("{\n\t.reg .pred p;\n\telect.sync _|p, 0xFFFFFFFF;\n\t"
                 "selp.b32 %0,1,0,p;\n\t}" : "=r"(r));
    return r != 0;
}
#define MBAR_INIT(a, c) \
    asm volatile("mbarrier.init.shared.b64 [%0], %1;" :: "r"(a), "r"(c) : "memory")
#define MBAR_WAIT(a, ph) do { \
    uint32_t _m = (a), _p = (uint32_t)(ph), _d; \
    asm volatile("{\n\t.reg .pred p;\n\t" \
        "mbarrier.try_wait.parity.acquire.cta.shared::cta.b64 p, [%1], %2;\n\t" \
        "selp.b32 %0,1,0,p;\n\t}" : "=r"(_d) : "r"(_m), "r"(_p) : "memory"); \
    while (!_d) { \
        asm volatile("{\n\t.reg .pred p;\n\t" \
            "mbarrier.try_wait.parity.acquire.cta.shared::cta.b64 p, [%1], %2, 0x989680;\n\t" \
            "selp.b32 %0,1,0,p;\n\t}" : "=r"(_d) : "r"(_m), "r"(_p) : "memory"); \
    } } while (0)
#define T5_COMMIT(a) \
    asm volatile("tcgen05.commit.cta_group::1.mbarrier::arrive::one.shared::cluster.b64 [%0];" \
                 :: "r"(a) : "memory")
#define T5_ALLOC(a, n) \
    asm volatile("tcgen05.alloc.cta_group::1.sync.aligned.shared::cta.b32 [%0], %1;" \
                 :: "r"(a), "r"(n) : "memory")
#define T5_DEALLOC(t, n) \
    asm volatile("tcgen05.dealloc.cta_group::1.sync.aligned.b32 %0, %1;" :: "r"(t), "r"(n))
#define T5_RELINQ() \
    asm volatile("tcgen05.relinquish_alloc_permit.cta_group::1.sync.aligned;")
#define T5_WAIT_LD()   asm volatile("tcgen05.wait::ld.sync.aligned;" ::: "memory")
#define T5_FENCE_AFTER() asm volatile("tcgen05.fence::after_thread_sync;" ::: "memory")
#define T5_FENCE_BEFORE() asm volatile("tcgen05.fence::before_thread_sync;" ::: "memory")
#define FENCE_ASYNC()  asm volatile("fence.proxy.async.shared::cta;" ::: "memory")
#define CP_ASYNC16(dst, src) \
    asm volatile("cp.async.cg.shared.global [%0], [%1], 16;" \
                 :: "r"(dst), "l"(src) : "memory")
#define CP_COMMIT() asm volatile("cp.async.commit_group;" ::: "memory")
#define CP_WAIT(n)  asm volatile("cp.async.wait_group %0;" :: "n"(n) : "memory")

#define LDTM_X32(r, addr) \
    asm volatile("tcgen05.ld.sync.aligned.32x32b.x32.b32 " \
        "{%0, %1, %2, %3, %4, %5, %6, %7, %8, %9, %10, %11, %12, %13, %14, %15, " \
        "%16, %17, %18, %19, %20, %21, %22, %23, %24, %25, %26, %27, %28, %29, %30, %31}, [%32];" \
        : "=r"((r)[0]),  "=r"((r)[1]),  "=r"((r)[2]),  "=r"((r)[3]), \
          "=r"((r)[4]),  "=r"((r)[5]),  "=r"((r)[6]),  "=r"((r)[7]), \
          "=r"((r)[8]),  "=r"((r)[9]),  "=r"((r)[10]), "=r"((r)[11]), \
          "=r"((r)[12]), "=r"((r)[13]), "=r"((r)[14]), "=r"((r)[15]), \
          "=r"((r)[16]), "=r"((r)[17]), "=r"((r)[18]), "=r"((r)[19]), \
          "=r"((r)[20]), "=r"((r)[21]), "=r"((r)[22]), "=r"((r)[23]), \
          "=r"((r)[24]), "=r"((r)[25]), "=r"((r)[26]), "=r"((r)[27]), \
          "=r"((r)[28]), "=r"((r)[29]), "=r"((r)[30]), "=r"((r)[31]) \
        : "r"(addr))

__device__ __forceinline__ void mma_f16(uint32_t d, uint64_t ad, uint64_t bd,
                                        uint32_t idesc, uint32_t en) {
    asm volatile("{\n\t.reg .pred p;\n\tsetp.ne.u32 p, %4, 0;\n\t"
        "tcgen05.mma.cta_group::1.kind::f16 [%0], %1, %2, %3, p;\n\t}"
        :: "r"(d), "l"(ad), "l"(bd), "r"(idesc), "r"(en) : "memory");
}
__device__ __forceinline__ uint64_t mk_desc(uint32_t addr) {
    return ((uint64_t)2 << 61) | ((uint64_t)1 << 46) | ((uint64_t)64 << 32)
         | ((uint64_t)1 << 16) | ((addr >> 4) & 0x3FFF);
}
__device__ __forceinline__ void sts128(uint32_t addr, uint32_t a, uint32_t b,
                                       uint32_t c, uint32_t d) {
    asm volatile("st.shared.v4.b32 [%0], {%1,%2,%3,%4};"
                 :: "r"(addr), "r"(a), "r"(b), "r"(c), "r"(d) : "memory");
}
struct MmaCtx { uint32_t mb, mb_done, tmem, tiles; };
__device__ __forceinline__ MmaCtx mma_begin(char* smem, int ncols) {
    MmaCtx cx;
    uint32_t sbase = smem_u32(smem);
    cx.mb = sbase;
    cx.mb_done = sbase + 24;
    cx.tiles = (sbase + 64 + 1023) & ~1023u;
    if (threadIdx.x == 0) {
        MBAR_INIT(cx.mb + 0, 1);
        MBAR_INIT(cx.mb + 8, 1);
        MBAR_INIT(cx.mb + 16, 1);
        MBAR_INIT(cx.mb_done, 1);
    }
    if (threadIdx.x < 32) { T5_ALLOC(sbase + 32, ncols); T5_RELINQ(); }
    __syncthreads();
    asm volatile("ld.shared.b32 %0, [%1];" : "=r"(cx.tmem) : "r"(sbase + 32));
    return cx;
}
// 12 MMAs (hh, hl, lh) for one K=64 chunk
__device__ __forceinline__ void mma_chunk(uint32_t tmem, uint32_t mbar,
                                          uint64_t ah, uint64_t al,
                                          uint64_t bh, uint64_t bl,
                                          uint32_t idesc, bool first) {
    if (threadIdx.x < 32 && elect1()) {
        #pragma unroll
        for (int q = 0; q < 4; q++)
            mma_f16(tmem, ah + 2*q, bh + 2*q, idesc, (first && q == 0) ? 0u : 1u);
        #pragma unroll
        for (int q = 0; q < 4; q++)
            mma_f16(tmem, ah + 2*q, bl + 2*q, idesc, 1u);
        #pragma unroll
        for (int q = 0; q < 4; q++)
            mma_f16(tmem, al + 2*q, bh + 2*q, idesc, 1u);
        T5_COMMIT(mbar);
    }
}

// ---------------- GEMM mainloop: decoupled refill (MMA stays queued) ------
__device__ __forceinline__ void issue_chunk_cp(
    const __half* const psrc[4], int K, int k0, uint32_t st)
{
    constexpr int T_BYTES = 128 * 128;
    const int tid = threadIdx.x;
    #pragma unroll
    for (int i = 0; i < 16; i++) {
        int u = i * 256 + tid;
        int t = u >> 10, ul = u & 1023;
        int row = ul >> 3, seg = ul & 7;
        uint32_t bofs = row * 128 + seg * 16;
        uint32_t da = st + t * T_BYTES + (bofs ^ ((bofs >> 3) & 0x70));
        CP_ASYNC16(da, psrc[t] + (size_t)row * K + k0 + seg * 8);
    }
    CP_COMMIT();
}

__device__ __forceinline__ MmaCtx gemm_main(
    const __half* Ah, const __half* Al,
    const __half* Bh, const __half* Bl, int K)
{
    constexpr int T_BYTES = 128 * 128;
    constexpr int STAGE = 4 * T_BYTES;
    extern __shared__ char smem[];
    MmaCtx cx = mma_begin(smem, 128);
    const int tid = threadIdx.x;
    const uint32_t idesc = (1u << 4) | (16u << 17) | (8u << 24);
    const int nc = K >> 6;
    const __half* psrc[4] = {Ah, Al, Bh, Bl};

    for (int c = 0; c < 3; c++)
        issue_chunk_cp(psrc, K, c * 64, cx.tiles + c * STAGE);

    for (int c = 0; c < nc; c++) {
        const int s = c - (c / 3) * 3;
        const uint32_t st = cx.tiles + s * STAGE;
        if (c == 0)           CP_WAIT(2);
        else if (c == nc - 1) CP_WAIT(0);
        else                  CP_WAIT(1);
        FENCE_ASYNC();
        __syncthreads();
        mma_chunk(cx.tmem, cx.mb + 8 * s,
                  mk_desc(st), mk_desc(st + T_BYTES),
                  mk_desc(st + 2 * T_BYTES), mk_desc(st + 3 * T_BYTES),
                  idesc, c == 0);
        if (c >= 1) {
            const int cn = c + 2;
            if (cn < nc) {
                const int sp = (c - 1) - ((c - 1) / 3) * 3;
                MBAR_WAIT(cx.mb + 8 * sp, ((c - 1) / 3) & 1);
                issue_chunk_cp(psrc, K, cn * 64, cx.tiles + sp * STAGE);
            }
        }
    }
    if (tid < 32 && elect1()) T5_COMMIT(cx.mb_done);
    MBAR_WAIT(cx.mb_done, 0);
    T5_FENCE_AFTER();
    return cx;
}
#else
__device__ __forceinline__ float dot_hl(
    const __half* Ah, const __half* Al,
    const __half* Bh, const __half* Bl, int K, int r, int c)
{
    float acc = 0.f;
    for (int k = 0; k < K; k++)
        acc += (__half2float(Ah[(size_t)r*K+k]) + __half2float(Al[(size_t)r*K+k]))
             * (__half2float(Bh[(size_t)c*K+k]) + __half2float(Bl[(size_t)c*K+k]));
    return acc;
}
#endif

// ---------------- producers ----------------
__global__ __launch_bounds__(256) void split_x_kernel(
    const float* __restrict__ x, __half* __restrict__ xh, __half* __restrict__ xl)
{
    size_t i = (size_t)(blockIdx.x * 256 + threadIdx.x) * 4;
    float4 v = *reinterpret_cast<const float4*>(&x[i]);
    uint32_t h0, l0, h1, l1;
    split_pair(v.x, v.y, h0, l0);
    split_pair(v.z, v.w, h1, l1);
    *reinterpret_cast<uint2*>(&xh[i]) = make_uint2(h0, h1);
    *reinterpret_cast<uint2*>(&xl[i]) = make_uint2(l0, l1);
}

struct TSJob { const float* W; __half* H; __half* L; int K; int N; int tile0; };
struct TSJobs { TSJob a[8]; };

__global__ __launch_bounds__(256) void tsplit_all_kernel(TSJobs jobs)
{
    __shared__ float t[32][33];
    int bx = blockIdx.x;
    int ji = 0;
    #pragma unroll
    for (int i = 1; i < 8; i++)
        if (bx >= jobs.a[i].tile0) ji = i;
    TSJob j = jobs.a[ji];
    int tl = bx - j.tile0;
    int ntN = j.N >> 5;
    int n0 = (tl % ntN) * 32, k0 = (tl / ntN) * 32;
    int tx = threadIdx.x & 31, ty = threadIdx.x >> 5;
    #pragma unroll
    for (int i = ty; i < 32; i += 8)
        t[i][tx] = j.W[(size_t)(k0 + i) * j.N + n0 + tx];
    __syncthreads();
    #pragma unroll
    for (int i = ty; i < 32; i += 8) {
        float v = t[tx][i];
        __half h = __float2half_rn(v);
        j.H[(size_t)(n0 + i) * j.K + k0 + tx] = h;
        j.L[(size_t)(n0 + i) * j.K + k0 + tx] = __float2half_rn(v - __half2float(h));
    }
}

// ---------------- xproj: cKV | cQ | KR(+rope) ----------------
__global__ __launch_bounds__(256) void xproj_kernel(
    const __half* __restrict__ xh, const __half* __restrict__ xl,
    const __half* __restrict__ WtH, const __half* __restrict__ WtL,
    const float* __restrict__ freqs,
    float* __restrict__ cKVf, __half* __restrict__ cKVh, __half* __restrict__ cKVl,
    __half* __restrict__ cQh, __half* __restrict__ cQl,
    float* __restrict__ KRo, __half* __restrict__ Krh, __half* __restrict__ Krl)
{
    const int bx = blockIdx.x, bm = blockIdx.y * 128;
#if HAS_TCGEN05
    const __half* Ah = xh + (size_t)bm * DM;
    const __half* Al = xl + (size_t)bm * DM;
    size_t bo = (bx < 4) ? O_DKV + (size_t)(bx * 128) * DM
              : (bx < 12) ? O_DQ + (size_t)((bx - 4) * 128) * DM
              : (size_t)O_KRP;
    MmaCtx cx = gemm_main(Ah, Al, WtH + bo, WtL + bo, DM);

    const int w = threadIdx.x >> 5, l2 = threadIdx.x & 31;
    const int sub = w & 3, halfi = w >> 2;
    const int rowl = sub * 32 + l2;
    const int m = bm + rowl;
    if (bx < 12) {
        for (int b2 = halfi * 2; b2 < halfi * 2 + 2; b2++) {
            uint32_t r[32];
            LDTM_X32(r, cx.tmem + b2 * 32);
            T5_WAIT_LD();
            if (bx < 4) {
                size_t off = (size_t)m * KVL + bx * 128 + b2 * 32;
                #pragma unroll
                for (int j = 0; j < 32; j += 4)
                    *reinterpret_cast<float4*>(&cKVf[off + j]) = make_float4(
                        __uint_as_float(r[j]), __uint_as_float(r[j+1]),
                        __uint_as_float(r[j+2]), __uint_as_float(r[j+3]));
                #pragma unroll
                for (int j = 0; j < 32; j += 8) {
                    uint4 hv, lv;
                    split_pair(__uint_as_float(r[j+0]), __uint_as_float(r[j+1]), hv.x, lv.x);
                    split_pair(__uint_as_float(r[j+2]), __uint_as_float(r[j+3]), hv.y, lv.y);
                    split_pair(__uint_as_float(r[j+4]), __uint_as_float(r[j+5]), hv.z, lv.z);
                    split_pair(__uint_as_float(r[j+6]), __uint_as_float(r[j+7]), hv.w, lv.w);
                    *reinterpret_cast<uint4*>(&cKVh[off + j]) = hv;
                    *reinterpret_cast<uint4*>(&cKVl[off + j]) = lv;
                }
            } else {
                size_t off = (size_t)m * QL + (bx - 4) * 128 + b2 * 32;
                #pragma unroll
                for (int j = 0; j < 32; j += 8) {
                    uint4 hv, lv;
                    split_pair(__uint_as_float(r[j+0]), __uint_as_float(r[j+1]), hv.x, lv.x);
                    split_pair(__uint_as_float(r[j+2]), __uint_as_float(r[j+3]), hv.y, lv.y);
                    split_pair(__uint_as_float(r[j+4]), __uint_as_float(r[j+5]), hv.z, lv.z);
                    split_pair(__uint_as_float(r[j+6]), __uint_as_float(r[j+7]), hv.w, lv.w);
                    *reinterpret_cast<uint4*>(&cQh[off + j]) = hv;
                    *reinterpret_cast<uint4*>(&cQl[off + j]) = lv;
                }
            }
        }
    } else if (halfi == 0) {
        const int t = m & (Tt - 1);
        for (int b2 = 0; b2 < 2; b2++) {
            uint32_t r[32];
            LDTM_X32(r, cx.tmem + b2 * 32);
            T5_WAIT_LD();
            #pragma unroll
            for (int j = 0; j < 32; j += 2) {
                int col = b2 * 32 + j;
                float f = freqs[t * (Rr / 2) + (col >> 1)], s, c;
                sincosf(f, &s, &c);
                float x0 = __uint_as_float(r[j]), x1 = __uint_as_float(r[j + 1]);
                float y0 = x0 * c - x1 * s, y1 = x0 * s + x1 * c;
                size_t off = (size_t)m * Rr + col;
                KRo[off] = y0;
                KRo[off + 1] = y1;
                uint32_t hi, lo;
                split_pair(y0, y1, hi, lo);
                *reinterpret_cast<uint32_t*>(&Krh[off]) = hi;
                *reinterpret_cast<uint32_t*>(&Krl[off]) = lo;
            }
        }
    }
    __syncthreads();
    if (threadIdx.x < 32) T5_DEALLOC(cx.tmem, 128);
#else
    const int tid = threadIdx.x;
    for (int e = tid; e < 128 * 128; e += 256) {
        int rr = e >> 7, cc = e & 127;
        int m = bm + rr;
        if (bx < 4) {
            float acc = dot_hl(xh + (size_t)bm*DM, xl + (size_t)bm*DM,
                               g_WtH + O_DKV + (size_t)(bx*128)*DM,
                               g_WtL + O_DKV + (size_t)(bx*128)*DM, DM, rr, cc);
            size_t off = (size_t)m * KVL + bx * 128 + cc;
            cKVf[off] = acc;
            __half h = __float2half_rn(acc);
            cKVh[off] = h;
            cKVl[off] = __float2half_rn(acc - __half2float(h));
        } else if (bx < 12) {
            float acc = dot_hl(xh + (size_t)bm*DM, xl + (size_t)bm*DM,
                               g_WtH + O_DQ + (size_t)((bx-4)*128)*DM,
                               g_WtL + O_DQ + (size_t)((bx-4)*128)*DM, DM, rr, cc);
            size_t off = (size_t)m * QL + (bx - 4) * 128 + cc;
            __half h = __float2half_rn(acc);
            cQh[off] = h;
            cQl[off] = __float2half_rn(acc - __half2float(h));
        } else if (cc < Rr && (cc & 1) == 0) {
            float x0 = dot_hl(xh + (size_t)bm*DM, xl + (size_t)bm*DM,
                              g_WtH + O_KRP, g_WtL + O_KRP, DM, rr, cc);
            float x1 = dot_hl(xh + (size_t)bm*DM, xl + (size_t)bm*DM,
                              g_WtH + O_KRP, g_WtL + O_KRP, DM, rr, cc + 1);
            int t = m & (Tt - 1);
            float f = freqs[t * (Rr / 2) + (cc >> 1)], s, c;
            sincosf(f, &s, &c);
            float y0 = x0 * c - x1 * s, y1 = x0 * s + x1 * c;
            size_t off = (size_t)m * Rr + cc;
            KRo[off] = y0; KRo[off + 1] = y1;
            __half h0 = __float2half_rn(y0), h1 = __float2half_rn(y1);
            Krh[off] = h0; Krh[off + 1] = h1;
            Krl[off] = __float2half_rn(y0 - __half2float(h0));
            Krl[off + 1] = __float2half_rn(y1 - __half2float(h1));
        }
    }
#endif
}

// ---------------- kqproj: merged kvproj + qproj ----------------
__global__ __launch_bounds__(256) void kqproj_kernel(
    const __half* __restrict__ cKVh, const __half* __restrict__ cKVl,
    const __half* __restrict__ cQh, const __half* __restrict__ cQl,
    const __half* __restrict__ WtH, const __half* __restrict__ WtL,
    const float* __restrict__ freqs,
    __half* __restrict__ Kch, __half* __restrict__ Kcl,
    __half* __restrict__ Vth, __half* __restrict__ Vtl,
    __half* __restrict__ Qch, __half* __restrict__ Qcl,
    __half* __restrict__ Qrh, __half* __restrict__ Qrl)
{
    const int bx = blockIdx.x, bm = blockIdx.y * 128;
#if HAS_TCGEN05
    const __half *Ah, *Al;
    size_t bo;
    int K;
    if (bx < 32) {
        Ah = cKVh + (size_t)bm * KVL;
        Al = cKVl + (size_t)bm * KVL;
        K = KVL;
        bo = (bx < 16) ? O_UK + (size_t)(bx * 128) * KVL
                       : O_UV + (size_t)((bx - 16) * 128) * KVL;
    } else {
        Ah = cQh + (size_t)bm * QL;
        Al = cQl + (size_t)bm * QL;
        K = QL;
        bo = (bx < 48) ? O_UQ + (size_t)((bx - 32) * 128) * QL
                       : O_QR + (size_t)((bx - 48) * 128) * QL;
    }
    MmaCtx cx = gemm_main(Ah, Al, WtH + bo, WtL + bo, K);

    const int w = threadIdx.x >> 5, l2 = threadIdx.x & 31;
    const int sub = w & 3, halfi = w >> 2;
    const int rowl = sub * 32 + l2;
    const int m = bm + rowl;
    const int t = m & (Tt - 1);
    for (int b2 = halfi * 2; b2 < halfi * 2 + 2; b2++) {
        uint32_t r[32];
        LDTM_X32(r, cx.tmem + b2 * 32);
        T5_WAIT_LD();
        if (bx < 16) {
            size_t off = (size_t)m * HHD + bx * 128 + b2 * 32;
            #pragma unroll
            for (int j = 0; j < 32; j += 8) {
                uint4 hv, lv;
                split_pair(__uint_as_float(r[j+0]), __uint_as_float(r[j+1]), hv.x, lv.x);
                split_pair(__uint_as_float(r[j+2]), __uint_as_float(r[j+3]), hv.y, lv.y);
                split_pair(__uint_as_float(r[j+4]), __uint_as_float(r[j+5]), hv.z, lv.z);
                split_pair(__uint_as_float(r[j+6]), __uint_as_float(r[j+7]), hv.w, lv.w);
                *reinterpret_cast<uint4*>(&Kch[off + j]) = hv;
                *reinterpret_cast<uint4*>(&Kcl[off + j]) = lv;
            }
        } else if (bx < 32) {
            const int bq = m >> 11, tloc = m & (Tt - 1);
            #pragma unroll
            for (int j = 0; j < 32; j++) {
                int gcol = (bx - 16) * 128 + b2 * 32 + j;
                int hh2 = gcol >> 7, d = gcol & 127;
                float v = __uint_as_float(r[j]);
                __half vh = __float2half_rn(v);
                size_t off = ((size_t)(bq * Hh + hh2) * HD + d) * Tt + tloc;
                Vth[off] = vh;
                Vtl[off] = __float2half_rn(v - __half2float(vh));
            }
        } else if (bx < 48) {
            size_t off = (size_t)m * HHD + (bx - 32) * 128 + b2 * 32;
            #pragma unroll
            for (int j = 0; j < 32; j += 8) {
                uint4 hv, lv;
                split_pair(__uint_as_float(r[j+0]), __uint_as_float(r[j+1]), hv.x, lv.x);
                split_pair(__uint_as_float(r[j+2]), __uint_as_float(r[j+3]), hv.y, lv.y);
                split_pair(__uint_as_float(r[j+4]), __uint_as_float(r[j+5]), hv.z, lv.z);
                split_pair(__uint_as_float(r[j+6]), __uint_as_float(r[j+7]), hv.w, lv.w);
                *reinterpret_cast<uint4*>(&Qch[off + j]) = hv;
                *reinterpret_cast<uint4*>(&Qcl[off + j]) = lv;
            }
        } else {
            #pragma unroll
            for (int j = 0; j < 32; j += 2) {
                int gcol = (bx - 48) * 128 + b2 * 32 + j;
                float f = freqs[t * (Rr / 2) + ((gcol & 63) >> 1)], s, c;
                sincosf(f, &s, &c);
                float x0 = __uint_as_float(r[j]), x1 = __uint_as_float(r[j + 1]);
                float y0 = x0 * c - x1 * s, y1 = x0 * s + x1 * c;
                uint32_t hi, lo;
                split_pair(y0, y1, hi, lo);
                size_t off = (size_t)m * HRr + gcol;
                *reinterpret_cast<uint32_t*>(&Qrh[off]) = hi;
                *reinterpret_cast<uint32_t*>(&Qrl[off]) = lo;
            }
        }
    }
    __syncthreads();
    if (threadIdx.x < 32) T5_DEALLOC(cx.tmem, 128);
#else
    const int tid = threadIdx.x;
    for (int e = tid; e < 128 * 128; e += 256) {
        int rr = e >> 7, cc = e & 127;
        int m = bm + rr;
        if (bx < 16) {
            float acc = dot_hl(cKVh + (size_t)bm*KVL, cKVl + (size_t)bm*KVL,
                               g_WtH + O_UK + (size_t)(bx*128)*KVL,
                               g_WtL + O_UK + (size_t)(bx*128)*KVL, KVL, rr, cc);
            size_t off = (size_t)m * HHD + bx * 128 + cc;
            __half h = __float2half_rn(acc);
            Kch[off] = h;
            Kcl[off] = __float2half_rn(acc - __half2float(h));
        } else if (bx < 32) {
            float acc = dot_hl(cKVh + (size_t)bm*KVL, cKVl + (size_t)bm*KVL,
                               g_WtH + O_UV + (size_t)((bx-16)*128)*KVL,
                               g_WtL + O_UV + (size_t)((bx-16)*128)*KVL, KVL, rr, cc);
            int gcol = (bx - 16) * 128 + cc;
            int hh2 = gcol >> 7, d = gcol & 127;
            int bq = m >> 11, tloc = m & (Tt - 1);
            size_t off = ((size_t)(bq * Hh + hh2) * HD + d) * Tt + tloc;
            __half h = __float2half_rn(acc);
            Vth[off] = h;
            Vtl[off] = __float2half_rn(acc - __half2float(h));
        } else if (bx < 48) {
            float acc = dot_hl(cQh + (size_t)bm*QL, cQl + (size_t)bm*QL,
                               g_WtH + O_UQ + (size_t)((bx-32)*128)*QL,
                               g_WtL + O_UQ + (size_t)((bx-32)*128)*QL, QL, rr, cc);
            size_t off = (size_t)m * HHD + (bx - 32) * 128 + cc;
            __half h = __float2half_rn(acc);
            Qch[off] = h;
            Qcl[off] = __float2half_rn(acc - __half2float(h));
        } else if ((cc & 1) == 0) {
            float x0 = dot_hl(cQh + (size_t)bm*QL, cQl + (size_t)bm*QL,
                              g_WtH + O_QR + (size_t)((bx-48)*128)*QL,
                              g_WtL + O_QR + (size_t)((bx-48)*128)*QL, QL, rr, cc);
            float x1 = dot_hl(cQh + (size_t)bm*QL, cQl + (size_t)bm*QL,
                              g_WtH + O_QR + (size_t)((bx-48)*128)*QL,
                              g_WtL + O_QR + (size_t)((bx-48)*128)*QL, QL, rr, cc + 1);
            int gcol = (bx - 48) * 128 + cc;
            int t = m & (Tt - 1);
            float f = freqs[t * (Rr / 2) + ((gcol & 63) >> 1)], s, c;
            sincosf(f, &s, &c);
            float y0 = x0 * c - x1 * s, y1 = x0 * s + x1 * c;
            size_t off = (size_t)m * HRr + gcol;
            __half h0 = __float2half_rn(y0), h1 = __float2half_rn(y1);
            Qrh[off] = h0; Qrh[off + 1] = h1;
            Qrl[off] = __float2half_rn(y0 - __half2float(h0));
            Qrl[off + 1] = __float2half_rn(y1 - __half2float(h1));
        }
    }
#endif
}

// ---------------- wo: y = AO @ W_O ----------------
__global__ __launch_bounds__(256) void wo_kernel(
    const __half* __restrict__ AOh, const __half* __restrict__ AOl,
    const __half* __restrict__ WtH, const __half* __restrict__ WtL,
    float* __restrict__ y)
{
    const int bx = blockIdx.x, bm = blockIdx.y * 128;
#if HAS_TCGEN05
    size_t bo = O_O + (size_t)(bx * 128) * HHD;
    MmaCtx cx = gemm_main(AOh + (size_t)bm * HHD, AOl + (size_t)bm * HHD,
                          WtH + bo, WtL + bo, HHD);
    const int w = threadIdx.x >> 5, l2 = threadIdx.x & 31;
    const int sub = w & 3, halfi = w >> 2;
    const int m = bm + sub * 32 + l2;
    for (int b2 = halfi * 2; b2 < halfi * 2 + 2; b2++) {
        uint32_t r[32];
        LDTM_X32(r, cx.tmem + b2 * 32);
        T5_WAIT_LD();
        size_t off = (size_t)m * DM + bx * 128 + b2 * 32;
        #pragma unroll
        for (int j = 0; j < 32; j += 4)
            *reinterpret_cast<float4*>(&y[off + j]) = make_float4(
                __uint_as_float(r[j]), __uint_as_float(r[j+1]),
                __uint_as_float(r[j+2]), __uint_as_float(r[j+3]));
    }
    __syncthreads();
    if (threadIdx.x < 32) T5_DEALLOC(cx.tmem, 128);
#else
    const int tid = threadIdx.x;
    for (int e = tid; e < 128 * 128; e += 256) {
        int rr = e >> 7, cc = e & 127;
        float acc = dot_hl(AOh + (size_t)bm*HHD, AOl + (size_t)bm*HHD,
                           g_WtH + O_O + (size_t)(bx*128)*HHD,
                           g_WtL + O_O + (size_t)(bx*128)*HHD, HHD, rr, cc);
        y[(size_t)(bm + rr) * DM + bx * 128 + cc] = acc;
    }
#endif
}

// ---------------- fused flash attention (V c0 prefetched over softmax) ----
__global__ __launch_bounds__(256) void flash_kernel(
    const __half* __restrict__ Qch, const __half* __restrict__ Qcl,
    const __half* __restrict__ Qrh, const __half* __restrict__ Qrl,
    const __half* __restrict__ Kch, const __half* __restrict__ Kcl,
    const __half* __restrict__ Krh, const __half* __restrict__ Krl,
    const __half* __restrict__ Vth, const __half* __restrict__ Vtl,
    __half* __restrict__ AOh, __half* __restrict__ AOl)
{
    const int qt = 15 - blockIdx.x, bh = blockIdx.y;
    const int tid = threadIdx.x;
    const int b = bh >> 4, h = bh & 15;
    const float scale = 0.07216878364870323f;   // 1/sqrt(192)
#if HAS_TCGEN05
    constexpr int T_BYTES = 16384;
    extern __shared__ char smem[];
    MmaCtx cx = mma_begin(smem, 256);
    const uint32_t qbase  = cx.tiles;
    const uint32_t pbase  = qbase + 6 * T_BYTES;
    const uint32_t redmax = pbase + 2 * T_BYTES;
    const uint32_t redsum = redmax + 1024;
    const uint32_t bufb   = redsum + 1024;
    const uint32_t idesc = (1u << 4) | (16u << 17) | (8u << 24);
    const uint32_t tmemS = cx.tmem, tmemO = cx.tmem + 128;
    const size_t qrow0 = (size_t)(b * Tt + qt * 128);

    {
        const __half* qsrc[6] = {
            Qch + qrow0 * HHD + h * HD,       Qcl + qrow0 * HHD + h * HD,
            Qch + qrow0 * HHD + h * HD + 64,  Qcl + qrow0 * HHD + h * HD + 64,
            Qrh + qrow0 * HRr + h * Rr,       Qrl + qrow0 * HRr + h * Rr };
        const int qstr[6] = {HHD, HHD, HHD, HHD, HRr, HRr};
        #pragma unroll
        for (int i = 0; i < 24; i++) {
            int u = i * 256 + tid;
            int t = u >> 10, ul = u & 1023;
            int row = ul >> 3, seg = ul & 7;
            uint4 v = *reinterpret_cast<const uint4*>(
                qsrc[t] + (size_t)row * qstr[t] + seg * 8);
            uint32_t bo = row * 128 + seg * 16;
            sts128(qbase + t * T_BYTES + (bo ^ ((bo >> 3) & 0x70)),
                   v.x, v.y, v.z, v.w);
        }
    }

    const int w = tid >> 5, l2 = tid & 31, sub = w & 3, halfi = w >> 2;
    const int rowl = sub * 32 + l2;
    const int qglob = qt * 128 + rowl;
    float oacc[64];
    #pragma unroll
    for (int j = 0; j < 64; j++) oacc[j] = 0.f;
    float mrow = -INFINITY, lrow = 0.f;
    int u0 = 0, u1 = 0;

    for (int kt = 0; kt <= qt; kt++) {
        const size_t krow0 = (size_t)(b * Tt + kt * 128);
        // ---- QK^T: 3 chunks ----
        for (int c = 0; c < 3; c++) {
            const int bid = c & 1;
            int cnt = bid ? u1 : u0;
            const uint32_t st = bufb + bid * 2 * T_BYTES;
            const __half* kh = (c < 2) ? Kch + krow0 * HHD + h * HD + c * 64
                                       : Krh + krow0 * Rr;
            const __half* kl = (c < 2) ? Kcl + krow0 * HHD + h * HD + c * 64
                                       : Krl + krow0 * Rr;
            const int str = (c < 2) ? HHD : Rr;
            uint4 v[8];
            uint32_t da[8];
            #pragma unroll
            for (int i = 0; i < 8; i++) {
                int u = i * 256 + tid;
                int t = u >> 10, ul = u & 1023;
                int row = ul >> 3, seg = ul & 7;
                const __half* src = t ? kl : kh;
                v[i] = *reinterpret_cast<const uint4*>(
                    src + (size_t)row * str + seg * 8);
                uint32_t bo = row * 128 + seg * 16;
                da[i] = st + t * T_BYTES + (bo ^ ((bo >> 3) & 0x70));
            }
            if (cnt > 0) MBAR_WAIT(cx.mb + 8 * bid, (cnt - 1) & 1);
            #pragma unroll
            for (int i = 0; i < 8; i++)
                sts128(da[i], v[i].x, v[i].y, v[i].z, v[i].w);
            FENCE_ASYNC();
            __syncthreads();
            mma_chunk(tmemS, cx.mb + 8 * bid,
                      mk_desc(qbase + (2 * c) * T_BYTES),
                      mk_desc(qbase + (2 * c + 1) * T_BYTES),
                      mk_desc(st), mk_desc(st + T_BYTES), idesc, c == 0);
            if (bid) u1++; else u0++;
        }
        // ---- prefetch V c0 LDGs (land during softmax) ----
        uint4 vv0[8];
        uint32_t vda0[8];
        {
            const __half* vh = Vth + (size_t)bh * HD * Tt + kt * 128;
            const __half* vl = Vtl + (size_t)bh * HD * Tt + kt * 128;
            const uint32_t st = bufb;    // buf0
            #pragma unroll
            for (int i = 0; i < 8; i++) {
                int u = i * 256 + tid;
                int t = u >> 10, ul = u & 1023;
                int row = ul >> 3, seg = ul & 7;
                const __half* src = t ? vl : vh;
                vv0[i] = *reinterpret_cast<const uint4*>(
                    src + (size_t)row * Tt + seg * 8);
                uint32_t bo = row * 128 + seg * 16;
                vda0[i] = st + t * T_BYTES + (bo ^ ((bo >> 3) & 0x70));
            }
        }
        MBAR_WAIT(cx.mb + 0, (u0 - 1) & 1);   // QK c2 done (S ready, buf0 free)
        T5_FENCE_AFTER();

        // ---- softmax ----
        uint32_t sr[32];
        float sv[64];
        LDTM_X32(sr, tmemS + halfi * 64);
        T5_WAIT_LD();
        #pragma unroll
        for (int j = 0; j < 32; j++) sv[j] = __uint_as_float(sr[j]) * scale;
        LDTM_X32(sr, tmemS + halfi * 64 + 32);
        T5_WAIT_LD();
        #pragma unroll
        for (int j = 0; j < 32; j++) sv[32 + j] = __uint_as_float(sr[j]) * scale;
        T5_FENCE_BEFORE();
        if (kt == qt) {
            int cbase = kt * 128 + halfi * 64;
            #pragma unroll
            for (int j = 0; j < 64; j++)
                if (cbase + j > qglob) sv[j] = -INFINITY;
        }
        float pmax = -INFINITY;
        #pragma unroll
        for (int j = 0; j < 64; j++) pmax = fmaxf(pmax, sv[j]);
        asm volatile("st.shared.f32 [%0], %1;"
                     :: "r"(redmax + (halfi * 128 + rowl) * 4), "f"(pmax) : "memory");
        __syncthreads();
        float omax;
        asm volatile("ld.shared.f32 %0, [%1];"
                     : "=f"(omax) : "r"(redmax + ((1 - halfi) * 128 + rowl) * 4));
        float mnew = fmaxf(mrow, fmaxf(pmax, omax));
        float alpha = __expf(mrow - mnew);
        mrow = mnew;
        float psum = 0.f;
        uint32_t pw[32];
        #pragma unroll
        for (int j = 0; j < 32; j++) {
            float p0 = __expf(sv[2 * j] - mnew);
            float p1 = __expf(sv[2 * j + 1] - mnew);
            psum += p0 + p1;
            pw[j] = ((uint32_t)__half_as_ushort(__float2half_rn(p1)) << 16)
                  | __half_as_ushort(__float2half_rn(p0));
        }
        #pragma unroll
        for (int sgm = 0; sgm < 8; sgm++) {
            uint32_t bo = rowl * 128 + sgm * 16;
            sts128(pbase + halfi * T_BYTES + (bo ^ ((bo >> 3) & 0x70)),
                   pw[sgm * 4], pw[sgm * 4 + 1], pw[sgm * 4 + 2], pw[sgm * 4 + 3]);
        }
        asm volatile("st.shared.f32 [%0], %1;"
                     :: "r"(redsum + (halfi * 128 + rowl) * 4), "f"(psum) : "memory");
        FENCE_ASYNC();
        __syncthreads();
        float osum;
        asm volatile("ld.shared.f32 %0, [%1];"
                     : "=f"(osum) : "r"(redsum + ((1 - halfi) * 128 + rowl) * 4));
        lrow = lrow * alpha + psum + osum;

        // ---- PV c0: STS prefetched V, MMA (buf0 drain confirmed pre-softmax)
        #pragma unroll
        for (int i = 0; i < 8; i++)
            sts128(vda0[i], vv0[i].x, vv0[i].y, vv0[i].z, vv0[i].w);
        FENCE_ASYNC();
        __syncthreads();
        if (tid < 32 && elect1()) {
            uint64_t pd = mk_desc(pbase);
            uint64_t vhd = mk_desc(bufb), vld = mk_desc(bufb + T_BYTES);
            #pragma unroll
            for (int q = 0; q < 4; q++)
                mma_f16(tmemO, pd + 2 * q, vhd + 2 * q, idesc, q == 0 ? 0u : 1u);
            #pragma unroll
            for (int q = 0; q < 4; q++)
                mma_f16(tmemO, pd + 2 * q, vld + 2 * q, idesc, 1u);
            T5_COMMIT(cx.mb + 0);
        }
        u0++;

        // ---- PV c1 ----
        {
            const uint32_t st = bufb + 2 * T_BYTES;   // buf1
            const __half* vh = Vth + (size_t)bh * HD * Tt + kt * 128 + 64;
            const __half* vl = Vtl + (size_t)bh * HD * Tt + kt * 128 + 64;
            uint4 v[8];
            uint32_t da[8];
            #pragma unroll
            for (int i = 0; i < 8; i++) {
                int u = i * 256 + tid;
                int t = u >> 10, ul = u & 1023;
                int row = ul >> 3, seg = ul & 7;
                const __half* src = t ? vl : vh;
                v[i] = *reinterpret_cast<const uint4*>(
                    src + (size_t)row * Tt + seg * 8);
                uint32_t bo = row * 128 + seg * 16;
                da[i] = st + t * T_BYTES + (bo ^ ((bo >> 3) & 0x70));
            }
            MBAR_WAIT(cx.mb + 8, (u1 - 1) & 1);   // QK c1 MMA done (buf1 free)
            #pragma unroll
            for (int i = 0; i < 8; i++)
                sts128(da[i], v[i].x, v[i].y, v[i].z, v[i].w);
            FENCE_ASYNC();
            __syncthreads();
            if (tid < 32 && elect1()) {
                uint64_t pd = mk_desc(pbase + T_BYTES);
                uint64_t vhd = mk_desc(st), vld = mk_desc(st + T_BYTES);
                #pragma unroll
                for (int q = 0; q < 4; q++)
                    mma_f16(tmemO, pd + 2 * q, vhd + 2 * q, idesc, 1u);
                #pragma unroll
                for (int q = 0; q < 4; q++)
                    mma_f16(tmemO, pd + 2 * q, vld + 2 * q, idesc, 1u);
                T5_COMMIT(cx.mb + 8);
            }
            u1++;
        }
        MBAR_WAIT(cx.mb + 8, (u1 - 1) & 1);   // PV done (in-order => c0 done too)
        T5_FENCE_AFTER();
        LDTM_X32(sr, tmemO + halfi * 64);
        T5_WAIT_LD();
        #pragma unroll
        for (int j = 0; j < 32; j++)
            oacc[j] = oacc[j] * alpha + __uint_as_float(sr[j]);
        LDTM_X32(sr, tmemO + halfi * 64 + 32);
        T5_WAIT_LD();
        #pragma unroll
        for (int j = 0; j < 32; j++)
            oacc[32 + j] = oacc[32 + j] * alpha + __uint_as_float(sr[j]);
        T5_FENCE_BEFORE();
        __syncthreads();
    }

    const float invl = 1.0f / lrow;
    const size_t off = (size_t)(b * Tt + qt * 128 + rowl) * HHD + h * HD + halfi * 64;
    #pragma unroll
    for (int j = 0; j < 64; j += 8) {
        uint4 hv, lv;
        split_pair(oacc[j+0] * invl, oacc[j+1] * invl, hv.x, lv.x);
        split_pair(oacc[j+2] * invl, oacc[j+3] * invl, hv.y, lv.y);
        split_pair(oacc[j+4] * invl, oacc[j+5] * invl, hv.z, lv.z);
        split_pair(oacc[j+6] * invl, oacc[j+7] * invl, hv.w, lv.w);
        *reinterpret_cast<uint4*>(&AOh[off + j]) = hv;
        *reinterpret_cast<uint4*>(&AOl[off + j]) = lv;
    }
    __syncthreads();
    if (tid < 32) T5_DEALLOC(cx.tmem, 256);
#else
    for (int e = tid; e < 128 * 128; e += 256) {
        int r = e >> 7, d = e & 127;
        int qg = qt * 128 + r;
        size_t qoC = (size_t)(b * Tt + qg) * HHD + h * HD;
        size_t qoR = (size_t)(b * Tt + qg) * HRr + h * Rr;
        float m = -1e30f;
        for (int k = 0; k <= qg; k++) {
            size_t koC = (size_t)(b * Tt + k) * HHD + h * HD;
            size_t koR = (size_t)(b * Tt + k) * Rr;
            float s = 0.f;
            for (int dd = 0; dd < HD; dd++)
                s += (__half2float(Qch[qoC+dd]) + __half2float(Qcl[qoC+dd]))
                   * (__half2float(Kch[koC+dd]) + __half2float(Kcl[koC+dd]));
            for (int dd = 0; dd < Rr; dd++)
                s += (__half2float(Qrh[qoR+dd]) + __half2float(Qrl[qoR+dd]))
                   * (__half2float(Krh[koR+dd]) + __half2float(Krl[koR+dd]));
            s *= scale;
            if (s > m) m = s;
        }
        float l = 0.f, o = 0.f;
        for (int k = 0; k <= qg; k++) {
            size_t koC = (size_t)(b * Tt + k) * HHD + h * HD;
            size_t koR = (size_t)(b * Tt + k) * Rr;
            float s = 0.f;
            for (int dd = 0; dd < HD; dd++)
                s += (__half2float(Qch[qoC+dd]) + __half2float(Qcl[qoC+dd]))
                   * (__half2float(Kch[koC+dd]) + __half2float(Kcl[koC+dd]));
            for (int dd = 0; dd < Rr; dd++)
                s += (__half2float(Qrh[qoR+dd]) + __half2float(Qrl[qoR+dd]))
                   * (__half2float(Krh[koR+dd]) + __half2float(Krl[koR+dd]));
            float p = expf(s * scale - m);
            l += p;
            o += p * (__half2float(Vth[((size_t)bh*HD + d)*Tt + k])
                    + __half2float(Vtl[((size_t)bh*HD + d)*Tt + k]));
        }
        o /= l;
        size_t off = (size_t)(b * Tt + qg) * HHD + h * HD + d;
        __half hh = __float2half_rn(o);
        AOh[off] = hh;
        AOl[off] = __float2half_rn(o - __half2float(hh));
    }
#endif
}

// ---------------- launch ----------------
#define MMA_SMEM 200704
#define FLASH_SMEM 202752

extern "C" void kernel_launch(void* const* d_in, const int* in_sizes, int n_in,
                              void* d_out, int out_size)
{
    const float* x     = (const float*)d_in[0];
    const float* freqs = (const float*)d_in[1];
    const float* W_DKV = (const float*)d_in[2];
    const float* W_UK  = (const float*)d_in[3];
    const float* W_UV  = (const float*)d_in[4];
    const float* W_KR  = (const float*)d_in[5];
    const float* W_DQ  = (const float*)d_in[6];
    const float* W_UQ  = (const float*)d_in[7];
    const float* W_QR  = (const float*)d_in[8];
    const float* W_O   = (const float*)d_in[9];

    float* y   = (float*)d_out;
    float* cKV = y   + (size_t)Bb * Tt * DM;
    float* KRo = cKV + (size_t)Bb * Tt * KVL;

    __half *pxH, *pxL, *pWtH, *pWtL, *pcKVh, *pcKVl, *pcQh, *pcQl;
    __half *pQch, *pQcl, *pQrh, *pQrl, *pKch, *pKcl, *pKrh, *pKrl;
    __half *pVth, *pVtl, *pAOh, *pAOl;
    cudaGetSymbolAddress((void**)&pxH,  g_xH);
    cudaGetSymbolAddress((void**)&pxL,  g_xL);
    cudaGetSymbolAddress((void**)&pWtH, g_WtH);
    cudaGetSymbolAddress((void**)&pWtL, g_WtL);
    cudaGetSymbolAddress((void**)&pcKVh, g_cKVh);
    cudaGetSymbolAddress((void**)&pcKVl, g_cKVl);
    cudaGetSymbolAddress((void**)&pcQh, g_cQh);
    cudaGetSymbolAddress((void**)&pcQl, g_cQl);
    cudaGetSymbolAddress((void**)&pQch, g_Qch);
    cudaGetSymbolAddress((void**)&pQcl, g_Qcl);
    cudaGetSymbolAddress((void**)&pQrh, g_Qrh);
    cudaGetSymbolAddress((void**)&pQrl, g_Qrl);
    cudaGetSymbolAddress((void**)&pKch, g_Kch);
    cudaGetSymbolAddress((void**)&pKcl, g_Kcl);
    cudaGetSymbolAddress((void**)&pKrh, g_Krh);
    cudaGetSymbolAddress((void**)&pKrl, g_Krl);
    cudaGetSymbolAddress((void**)&pVth, g_Vth);
    cudaGetSymbolAddress((void**)&pVtl, g_Vtl);
    cudaGetSymbolAddress((void**)&pAOh, g_AOh);
    cudaGetSymbolAddress((void**)&pAOl, g_AOl);

    cudaFuncSetAttribute(xproj_kernel,  cudaFuncAttributeMaxDynamicSharedMemorySize, MMA_SMEM);
    cudaFuncSetAttribute(kqproj_kernel, cudaFuncAttributeMaxDynamicSharedMemorySize, MMA_SMEM);
    cudaFuncSetAttribute(wo_kernel,     cudaFuncAttributeMaxDynamicSharedMemorySize, MMA_SMEM);
    cudaFuncSetAttribute(flash_kernel,  cudaFuncAttributeMaxDynamicSharedMemorySize, FLASH_SMEM);

    // #1: split x
    split_x_kernel<<<(MROWS * DM / 4) / 256, 256>>>(x, pxH, pxL);

    // #2: all weight transposes (KR padded; pad rows stay zero from static init)
    TSJobs jobs;
    int tiles = 0;
    auto addjob = [&](int i, const float* W, size_t off, int K, int N) {
        jobs.a[i] = {W, pWtH + off, pWtL + off, K, N, tiles};
        tiles += (K / 32) * (N / 32);
    };
    addjob(0, W_DKV, O_DKV, DM, KVL);
    addjob(1, W_UK,  O_UK,  KVL, HHD);
    addjob(2, W_UV,  O_UV,  KVL, HHD);
    addjob(3, W_DQ,  O_DQ,  DM, QL);
    addjob(4, W_UQ,  O_UQ,  QL, HHD);
    addjob(5, W_QR,  O_QR,  QL, HRr);
    addjob(6, W_O,   O_O,   HHD, DM);
    addjob(7, W_KR,  O_KRP, DM, Rr);
    tsplit_all_kernel<<<tiles, 256>>>(jobs);

    // #3: xproj (cKV | cQ | KR+rope)
    xproj_kernel<<<dim3(13, MROWS/128), 256, MMA_SMEM>>>(
        pxH, pxL, pWtH, pWtL, freqs, cKV, pcKVh, pcKVl, pcQh, pcQl,
        KRo, pKrh, pKrl);
    // #4: merged kv+q projections (UK|UV|UQ|QR)
    kqproj_kernel<<<dim3(56, MROWS/128), 256, MMA_SMEM>>>(
        pcKVh, pcKVl, pcQh, pcQl, pWtH, pWtL, freqs,
        pKch, pKcl, pVth, pVtl, pQch, pQcl, pQrh, pQrl);
    // #5: fused flash attention
    flash_kernel<<<dim3(16, BH), 256, FLASH_SMEM>>>(
        pQch, pQcl, pQrh, pQrl, pKch, pKcl, pKrh, pKrl, pVth, pVtl, pAOh, pAOl);
    // #6: y = AO @ W_O
    wo_kernel<<<dim3(16, MROWS/128), 256, MMA_SMEM>>>(pAOh, pAOl, pWtH, pWtL, y);
}

// round 16
// speedup vs baseline: 1.0850x; 1.0229x over previous
#include <cuda_runtime.h>
#include <cuda_fp16.h>
#include <math.h>
#include <stdint.h>

#define Bb 2
#define Tt 2048
#define DM 2048
#define Hh 16
#define HD 128
#define KVL 512
#define QL 1024
#define Rr 64
#define MROWS (Bb*Tt)
#define BH (Bb*Hh)
#define HHD (Hh*HD)
#define HRr (Hh*Rr)

#if defined(__CUDA_ARCH_FEAT_SM103_ALL) || defined(__CUDA_ARCH_FEAT_SM100_ALL)
#define HAS_TCGEN05 1
#else
#define HAS_TCGEN05 0
#endif

// ---------------- scratch ----------------
__device__ __half g_xH[MROWS * DM],  g_xL[MROWS * DM];
__device__ __half g_cKVh[MROWS * KVL], g_cKVl[MROWS * KVL];
__device__ __half g_cQh[MROWS * QL],   g_cQl[MROWS * QL];
__device__ __half g_Qch[MROWS * HHD],  g_Qcl[MROWS * HHD];
__device__ __half g_Qrh[MROWS * HRr],  g_Qrl[MROWS * HRr];
__device__ __half g_Kch[MROWS * HHD],  g_Kcl[MROWS * HHD];
__device__ __half g_Krh[MROWS * Rr],   g_Krl[MROWS * Rr];
__device__ __half g_Vth[BH * HD * Tt], g_Vtl[BH * HD * Tt];
__device__ __half g_AOh[MROWS * HHD],  g_AOl[MROWS * HHD];
#define O_DKV 0
#define O_UK  (O_DKV + 512*2048)
#define O_UV  (O_UK  + 2048*512)
#define O_DQ  (O_UV  + 2048*512)
#define O_UQ  (O_DQ  + 1024*2048)
#define O_QR  (O_UQ  + 2048*1024)
#define O_O   (O_QR  + 2048*1024)
#define O_KRP (O_O   + 2048*2048)
#define WT_TOTAL (O_KRP + 256*2048)
__device__ __half g_WtH[WT_TOTAL], g_WtL[WT_TOTAL];   // zero-init: KRP pad rows stay 0

// ---------------- helpers ----------------
__device__ __forceinline__ uint32_t smem_u32(const void* p) {
    uint32_t a;
    asm("{ .reg .u64 t; cvta.to.shared.u64 t, %1; cvt.u32.u64 %0, t; }"
        : "=r"(a) : "l"(p));
    return a;
}
__device__ __forceinline__ void split_pair(float a, float b,
                                           uint32_t& hi, uint32_t& lo) {
    __half ha = __float2half_rn(a), hb = __float2half_rn(b);
    hi = ((uint32_t)__half_as_ushort(hb) << 16) | __half_as_ushort(ha);
    lo = ((uint32_t)__half_as_ushort(__float2half_rn(b - __half2float(hb))) << 16)
       | __half_as_ushort(__float2half_rn(a - __half2float(ha)));
}

#if HAS_TCGEN05
__device__ __forceinline__ bool elect1() {
    uint32_t r;
    asm volatile("{\n\t.reg .pred p;\n\telect.sync _|p, 0xFFFFFFFF;\n\t"
                 "selp.b32 %0,1,0,p;\n\t}" : "=r"(r));
    return r != 0;
}
#define MBAR_INIT(a, c) \
    asm volatile("mbarrier.init.shared.b64 [%0], %1;" :: "r"(a), "r"(c) : "memory")
#define MBAR_WAIT(a, ph) do { \
    uint32_t _m = (a), _p = (uint32_t)(ph), _d; \
    asm volatile("{\n\t.reg .pred p;\n\t" \
        "mbarrier.try_wait.parity.acquire.cta.shared::cta.b64 p, [%1], %2;\n\t" \
        "selp.b32 %0,1,0,p;\n\t}" : "=r"(_d) : "r"(_m), "r"(_p) : "memory"); \
    while (!_d) { \
        asm volatile("{\n\t.reg .pred p;\n\t" \
            "mbarrier.try_wait.parity.acquire.cta.shared::cta.b64 p, [%1], %2, 0x989680;\n\t" \
            "selp.b32 %0,1,0,p;\n\t}" : "=r"(_d) : "r"(_m), "r"(_p) : "memory"); \
    } } while (0)
#define T5_COMMIT(a) \
    asm volatile("tcgen05.commit.cta_group::1.mbarrier::arrive::one.shared::cluster.b64 [%0];" \
                 :: "r"(a) : "memory")
#define T5_ALLOC(a, n) \
    asm volatile("tcgen05.alloc.cta_group::1.sync.aligned.shared::cta.b32 [%0], %1;" \
                 :: "r"(a), "r"(n) : "memory")
#define T5_DEALLOC(t, n) \
    asm volatile("tcgen05.dealloc.cta_group::1.sync.aligned.b32 %0, %1;" :: "r"(t), "r"(n))
#define T5_RELINQ() \
    asm volatile("tcgen05.relinquish_alloc_permit.cta_group::1.sync.aligned;")
#define T5_WAIT_LD()   asm volatile("tcgen05.wait::ld.sync.aligned;" ::: "memory")
#define T5_FENCE_AFTER() asm volatile("tcgen05.fence::after_thread_sync;" ::: "memory")
#define T5_FENCE_BEFORE() asm volatile("tcgen05.fence::before_thread_sync;" ::: "memory")
#define FENCE_ASYNC()  asm volatile("fence.proxy.async.shared::cta;" ::: "memory")
#define CP_ASYNC16(dst, src) \
    asm volatile("cp.async.cg.shared.global [%0], [%1], 16;" \
                 :: "r"(dst), "l"(src) : "memory")
#define CP_COMMIT() asm volatile("cp.async.commit_group;" ::: "memory")
#define CP_WAIT(n)  asm volatile("cp.async.wait_group %0;" :: "n"(n) : "memory")

#define LDTM_X32(r, addr) \
    asm volatile("tcgen05.ld.sync.aligned.32x32b.x32.b32 " \
        "{%0, %1, %2, %3, %4, %5, %6, %7, %8, %9, %10, %11, %12, %13, %14, %15, " \
        "%16, %17, %18, %19, %20, %21, %22, %23, %24, %25, %26, %27, %28, %29, %30, %31}, [%32];" \
        : "=r"((r)[0]),  "=r"((r)[1]),  "=r"((r)[2]),  "=r"((r)[3]), \
          "=r"((r)[4]),  "=r"((r)[5]),  "=r"((r)[6]),  "=r"((r)[7]), \
          "=r"((r)[8]),  "=r"((r)[9]),  "=r"((r)[10]), "=r"((r)[11]), \
          "=r"((r)[12]), "=r"((r)[13]), "=r"((r)[14]), "=r"((r)[15]), \
          "=r"((r)[16]), "=r"((r)[17]), "=r"((r)[18]), "=r"((r)[19]), \
          "=r"((r)[20]), "=r"((r)[21]), "=r"((r)[22]), "=r"((r)[23]), \
          "=r"((r)[24]), "=r"((r)[25]), "=r"((r)[26]), "=r"((r)[27]), \
          "=r"((r)[28]), "=r"((r)[29]), "=r"((r)[30]), "=r"((r)[31]) \
        : "r"(addr))

__device__ __forceinline__ void mma_f16(uint32_t d, uint64_t ad, uint64_t bd,
                                        uint32_t idesc, uint32_t en) {
    asm volatile("{\n\t.reg .pred p;\n\tsetp.ne.u32 p, %4, 0;\n\t"
        "tcgen05.mma.cta_group::1.kind::f16 [%0], %1, %2, %3, p;\n\t}"
        :: "r"(d), "l"(ad), "l"(bd), "r"(idesc), "r"(en) : "memory");
}
__device__ __forceinline__ uint64_t mk_desc(uint32_t addr) {
    return ((uint64_t)2 << 61) | ((uint64_t)1 << 46) | ((uint64_t)64 << 32)
         | ((uint64_t)1 << 16) | ((addr >> 4) & 0x3FFF);
}
__device__ __forceinline__ void sts128(uint32_t addr, uint32_t a, uint32_t b,
                                       uint32_t c, uint32_t d) {
    asm volatile("st.shared.v4.b32 [%0], {%1,%2,%3,%4};"
                 :: "r"(addr), "r"(a), "r"(b), "r"(c), "r"(d) : "memory");
}
struct MmaCtx { uint32_t mb, mb_done, tmem, tiles; };
__device__ __forceinline__ MmaCtx mma_begin(char* smem, int ncols) {
    MmaCtx cx;
    uint32_t sbase = smem_u32(smem);
    cx.mb = sbase;
    cx.mb_done = sbase + 24;
    cx.tiles = (sbase + 64 + 1023) & ~1023u;
    if (threadIdx.x == 0) {
        MBAR_INIT(cx.mb + 0, 1);
        MBAR_INIT(cx.mb + 8, 1);
        MBAR_INIT(cx.mb + 16, 1);
        MBAR_INIT(cx.mb_done, 1);
    }
    if (threadIdx.x < 32) { T5_ALLOC(sbase + 32, ncols); T5_RELINQ(); }
    __syncthreads();
    asm volatile("ld.shared.b32 %0, [%1];" : "=r"(cx.tmem) : "r"(sbase + 32));
    return cx;
}
// 12 MMAs (hh, hl, lh) for one K=64 chunk (flash kernel, N=128)
__device__ __forceinline__ void mma_chunk(uint32_t tmem, uint32_t mbar,
                                          uint64_t ah, uint64_t al,
                                          uint64_t bh, uint64_t bl,
                                          uint32_t idesc, bool first) {
    if (threadIdx.x < 32 && elect1()) {
        #pragma unroll
        for (int q = 0; q < 4; q++)
            mma_f16(tmem, ah + 2*q, bh + 2*q, idesc, (first && q == 0) ? 0u : 1u);
        #pragma unroll
        for (int q = 0; q < 4; q++)
            mma_f16(tmem, ah + 2*q, bl + 2*q, idesc, 1u);
        #pragma unroll
        for (int q = 0; q < 4; q++)
            mma_f16(tmem, al + 2*q, bh + 2*q, idesc, 1u);
        T5_COMMIT(mbar);
    }
}

// ---------------- 256x256 GEMM mainloop: K-chunk 32, packed hi|lo rows ----
// Stage (64KB): A 256 rows x [32h|32l] fp16 (32KB) @0, B same @32768.
__device__ __forceinline__ void issue_chunk2(
    const __half* Ah, const __half* Al,
    const __half* Bh, const __half* Bl, int K, int k0, uint32_t st)
{
    const int tid = threadIdx.x;
    #pragma unroll
    for (int i = 0; i < 16; i++) {
        int u = i * 256 + tid;              // 0..4095 (16B units)
        int isB = u >> 11;
        int ul = u & 2047;
        int row = ul >> 3, seg = ul & 7;    // seg 0-3 hi, 4-7 lo
        const __half* src = isB ? ((seg & 4) ? Bl : Bh)
                                : ((seg & 4) ? Al : Ah);
        uint32_t bofs = row * 128 + seg * 16;
        uint32_t da = st + (uint32_t)isB * 32768u + (bofs ^ ((bofs >> 3) & 0x70));
        CP_ASYNC16(da, src + (size_t)row * K + k0 + (seg & 3) * 8);
    }
    CP_COMMIT();
}

__device__ __forceinline__ MmaCtx gemm_main2(
    const __half* Ah, const __half* Al,
    const __half* Bh, const __half* Bl, int K)
{
    constexpr int STAGE = 65536;
    extern __shared__ char smem[];
    MmaCtx cx = mma_begin(smem, 512);
    const int tid = threadIdx.x;
    const uint32_t idesc = (1u << 4) | (32u << 17) | (8u << 24);   // N=256
    const int nc = K >> 5;                 // all call sites have nc >= 16
    for (int c = 0; c < 3; c++)
        issue_chunk2(Ah, Al, Bh, Bl, K, c * 32, cx.tiles + c * STAGE);

    for (int c = 0; c < nc; c++) {
        const int s = c - (c / 3) * 3;
        const uint32_t st = cx.tiles + s * STAGE;
        if (c == 0)           CP_WAIT(2);
        else if (c == nc - 1) CP_WAIT(0);
        else                  CP_WAIT(1);
        FENCE_ASYNC();
        __syncthreads();
        if (tid < 32 && elect1()) {
            uint64_t bhd = mk_desc(st + 32768), bld = bhd + 4;
            #pragma unroll
            for (int s2 = 0; s2 < 2; s2++) {
                uint64_t ah = mk_desc(st + s2 * 16384), al = ah + 4;
                uint32_t d = cx.tmem + s2 * 256;
                #pragma unroll
                for (int q = 0; q < 2; q++)
                    mma_f16(d, ah + 2*q, bhd + 2*q, idesc,
                            (c == 0 && q == 0) ? 0u : 1u);
                #pragma unroll
                for (int q = 0; q < 2; q++)
                    mma_f16(d, ah + 2*q, bld + 2*q, idesc, 1u);
                #pragma unroll
                for (int q = 0; q < 2; q++)
                    mma_f16(d, al + 2*q, bhd + 2*q, idesc, 1u);
            }
            T5_COMMIT(cx.mb + 8 * s);
        }
        if (c >= 1) {
            const int cn = c + 2;
            if (cn < nc) {
                const int sp = (c - 1) - ((c - 1) / 3) * 3;
                MBAR_WAIT(cx.mb + 8 * sp, ((c - 1) / 3) & 1);
                issue_chunk2(Ah, Al, Bh, Bl, K, cn * 32, cx.tiles + sp * STAGE);
            }
        }
    }
    if (tid < 32 && elect1()) T5_COMMIT(cx.mb_done);
    MBAR_WAIT(cx.mb_done, 0);
    T5_FENCE_AFTER();
    return cx;
}
#else
__device__ __forceinline__ float dot_hl(
    const __half* Ah, const __half* Al,
    const __half* Bh, const __half* Bl, int K, int r, int c)
{
    float acc = 0.f;
    for (int k = 0; k < K; k++)
        acc += (__half2float(Ah[(size_t)r*K+k]) + __half2float(Al[(size_t)r*K+k]))
             * (__half2float(Bh[(size_t)c*K+k]) + __half2float(Bl[(size_t)c*K+k]));
    return acc;
}
#endif

// ---------------- producers ----------------
__global__ __launch_bounds__(256) void split_x_kernel(
    const float* __restrict__ x, __half* __restrict__ xh, __half* __restrict__ xl)
{
    size_t i = (size_t)(blockIdx.x * 256 + threadIdx.x) * 4;
    float4 v = *reinterpret_cast<const float4*>(&x[i]);
    uint32_t h0, l0, h1, l1;
    split_pair(v.x, v.y, h0, l0);
    split_pair(v.z, v.w, h1, l1);
    *reinterpret_cast<uint2*>(&xh[i]) = make_uint2(h0, h1);
    *reinterpret_cast<uint2*>(&xl[i]) = make_uint2(l0, l1);
}

struct TSJob { const float* W; __half* H; __half* L; int K; int N; int tile0; };
struct TSJobs { TSJob a[8]; };

__global__ __launch_bounds__(256) void tsplit_all_kernel(TSJobs jobs)
{
    __shared__ float t[32][33];
    int bx = blockIdx.x;
    int ji = 0;
    #pragma unroll
    for (int i = 1; i < 8; i++)
        if (bx >= jobs.a[i].tile0) ji = i;
    TSJob j = jobs.a[ji];
    int tl = bx - j.tile0;
    int ntN = j.N >> 5;
    int n0 = (tl % ntN) * 32, k0 = (tl / ntN) * 32;
    int tx = threadIdx.x & 31, ty = threadIdx.x >> 5;
    #pragma unroll
    for (int i = ty; i < 32; i += 8)
        t[i][tx] = j.W[(size_t)(k0 + i) * j.N + n0 + tx];
    __syncthreads();
    #pragma unroll
    for (int i = ty; i < 32; i += 8) {
        float v = t[tx][i];
        __half h = __float2half_rn(v);
        j.H[(size_t)(n0 + i) * j.K + k0 + tx] = h;
        j.L[(size_t)(n0 + i) * j.K + k0 + tx] = __float2half_rn(v - __half2float(h));
    }
}

// ---------------- xproj: bx 0-1 cKV | 2-5 cQ | 6 KR(+rope). M=256,N=256 ----
__global__ __launch_bounds__(256) void xproj_kernel(
    const __half* __restrict__ xh, const __half* __restrict__ xl,
    const __half* __restrict__ WtH, const __half* __restrict__ WtL,
    const float* __restrict__ freqs,
    float* __restrict__ cKVf, __half* __restrict__ cKVh, __half* __restrict__ cKVl,
    __half* __restrict__ cQh, __half* __restrict__ cQl,
    float* __restrict__ KRo, __half* __restrict__ Krh, __half* __restrict__ Krl)
{
    const int bx = blockIdx.x, bm = blockIdx.y * 256;
#if HAS_TCGEN05
    const __half* Ah = xh + (size_t)bm * DM;
    const __half* Al = xl + (size_t)bm * DM;
    size_t bo = (bx < 2) ? O_DKV + (size_t)(bx * 256) * DM
              : (bx < 6) ? O_DQ + (size_t)((bx - 2) * 256) * DM
              : (size_t)O_KRP;
    MmaCtx cx = gemm_main2(Ah, Al, WtH + bo, WtL + bo, DM);

    const int w = threadIdx.x >> 5, l2 = threadIdx.x & 31;
    const int s2 = w >> 2, sub = w & 3;
    const int m = bm + s2 * 128 + sub * 32 + l2;
    const int t = m & (Tt - 1);
    const int b2max = (bx < 6) ? 8 : 2;        // KR: only cols 0..63
    for (int b2 = 0; b2 < b2max; b2++) {
        uint32_t r[32];
        LDTM_X32(r, cx.tmem + s2 * 256 + b2 * 32);
        T5_WAIT_LD();
        if (bx < 2) {
            size_t off = (size_t)m * KVL + bx * 256 + b2 * 32;
            #pragma unroll
            for (int j = 0; j < 32; j += 4)
                *reinterpret_cast<float4*>(&cKVf[off + j]) = make_float4(
                    __uint_as_float(r[j]), __uint_as_float(r[j+1]),
                    __uint_as_float(r[j+2]), __uint_as_float(r[j+3]));
            #pragma unroll
            for (int j = 0; j < 32; j += 8) {
                uint4 hv, lv;
                split_pair(__uint_as_float(r[j+0]), __uint_as_float(r[j+1]), hv.x, lv.x);
                split_pair(__uint_as_float(r[j+2]), __uint_as_float(r[j+3]), hv.y, lv.y);
                split_pair(__uint_as_float(r[j+4]), __uint_as_float(r[j+5]), hv.z, lv.z);
                split_pair(__uint_as_float(r[j+6]), __uint_as_float(r[j+7]), hv.w, lv.w);
                *reinterpret_cast<uint4*>(&cKVh[off + j]) = hv;
                *reinterpret_cast<uint4*>(&cKVl[off + j]) = lv;
            }
        } else if (bx < 6) {
            size_t off = (size_t)m * QL + (bx - 2) * 256 + b2 * 32;
            #pragma unroll
            for (int j = 0; j < 32; j += 8) {
                uint4 hv, lv;
                split_pair(__uint_as_float(r[j+0]), __uint_as_float(r[j+1]), hv.x, lv.x);
                split_pair(__uint_as_float(r[j+2]), __uint_as_float(r[j+3]), hv.y, lv.y);
                split_pair(__uint_as_float(r[j+4]), __uint_as_float(r[j+5]), hv.z, lv.z);
                split_pair(__uint_as_float(r[j+6]), __uint_as_float(r[j+7]), hv.w, lv.w);
                *reinterpret_cast<uint4*>(&cQh[off + j]) = hv;
                *reinterpret_cast<uint4*>(&cQl[off + j]) = lv;
            }
        } else {
            // KR rope on cols 0..63
            #pragma unroll
            for (int j = 0; j < 32; j += 2) {
                int col = b2 * 32 + j;
                float f = freqs[t * (Rr / 2) + (col >> 1)], s, c;
                sincosf(f, &s, &c);
                float x0 = __uint_as_float(r[j]), x1 = __uint_as_float(r[j + 1]);
                float y0 = x0 * c - x1 * s, y1 = x0 * s + x1 * c;
                size_t off = (size_t)m * Rr + col;
                KRo[off] = y0;
                KRo[off + 1] = y1;
                uint32_t hi, lo;
                split_pair(y0, y1, hi, lo);
                *reinterpret_cast<uint32_t*>(&Krh[off]) = hi;
                *reinterpret_cast<uint32_t*>(&Krl[off]) = lo;
            }
        }
    }
    __syncthreads();
    if (threadIdx.x < 32) T5_DEALLOC(cx.tmem, 512);
#else
    const int tid = threadIdx.x;
    for (int e = tid; e < 256 * 256; e += 256) {
        int rr = e >> 8, cc = e & 255;
        int m = bm + rr;
        if (bx < 2) {
            float acc = dot_hl(xh + (size_t)bm*DM, xl + (size_t)bm*DM,
                               g_WtH + O_DKV + (size_t)(bx*256)*DM,
                               g_WtL + O_DKV + (size_t)(bx*256)*DM, DM, rr, cc);
            size_t off = (size_t)m * KVL + bx * 256 + cc;
            cKVf[off] = acc;
            __half h = __float2half_rn(acc);
            cKVh[off] = h;
            cKVl[off] = __float2half_rn(acc - __half2float(h));
        } else if (bx < 6) {
            float acc = dot_hl(xh + (size_t)bm*DM, xl + (size_t)bm*DM,
                               g_WtH + O_DQ + (size_t)((bx-2)*256)*DM,
                               g_WtL + O_DQ + (size_t)((bx-2)*256)*DM, DM, rr, cc);
            size_t off = (size_t)m * QL + (bx - 2) * 256 + cc;
            __half h = __float2half_rn(acc);
            cQh[off] = h;
            cQl[off] = __float2half_rn(acc - __half2float(h));
        } else if (cc < Rr && (cc & 1) == 0) {
            float x0 = dot_hl(xh + (size_t)bm*DM, xl + (size_t)bm*DM,
                              g_WtH + O_KRP, g_WtL + O_KRP, DM, rr, cc);
            float x1 = dot_hl(xh + (size_t)bm*DM, xl + (size_t)bm*DM,
                              g_WtH + O_KRP, g_WtL + O_KRP, DM, rr, cc + 1);
            int t = m & (Tt - 1);
            float f = freqs[t * (Rr / 2) + (cc >> 1)], s, c;
            sincosf(f, &s, &c);
            float y0 = x0 * c - x1 * s, y1 = x0 * s + x1 * c;
            size_t off = (size_t)m * Rr + cc;
            KRo[off] = y0; KRo[off + 1] = y1;
            __half h0 = __float2half_rn(y0), h1 = __float2half_rn(y1);
            Krh[off] = h0; Krh[off + 1] = h1;
            Krl[off] = __float2half_rn(y0 - __half2float(h0));
            Krl[off + 1] = __float2half_rn(y1 - __half2float(h1));
        }
    }
#endif
}

// ---------------- kqproj: bx 0-7 UK | 8-15 UV | 16-23 UQ | 24-27 QR. 256x256
__global__ __launch_bounds__(256) void kqproj_kernel(
    const __half* __restrict__ cKVh, const __half* __restrict__ cKVl,
    const __half* __restrict__ cQh, const __half* __restrict__ cQl,
    const __half* __restrict__ WtH, const __half* __restrict__ WtL,
    const float* __restrict__ freqs,
    __half* __restrict__ Kch, __half* __restrict__ Kcl,
    __half* __restrict__ Vth, __half* __restrict__ Vtl,
    __half* __restrict__ Qch, __half* __restrict__ Qcl,
    __half* __restrict__ Qrh, __half* __restrict__ Qrl)
{
    const int bx = blockIdx.x, bm = blockIdx.y * 256;
#if HAS_TCGEN05
    const __half *Ah, *Al;
    size_t bo;
    int K;
    if (bx < 16) {
        Ah = cKVh + (size_t)bm * KVL;
        Al = cKVl + (size_t)bm * KVL;
        K = KVL;
        bo = (bx < 8) ? O_UK + (size_t)(bx * 256) * KVL
                      : O_UV + (size_t)((bx - 8) * 256) * KVL;
    } else {
        Ah = cQh + (size_t)bm * QL;
        Al = cQl + (size_t)bm * QL;
        K = QL;
        bo = (bx < 24) ? O_UQ + (size_t)((bx - 16) * 256) * QL
                       : O_QR + (size_t)((bx - 24) * 256) * QL;
    }
    MmaCtx cx = gemm_main2(Ah, Al, WtH + bo, WtL + bo, K);

    const int w = threadIdx.x >> 5, l2 = threadIdx.x & 31;
    const int s2 = w >> 2, sub = w & 3;
    const int m = bm + s2 * 128 + sub * 32 + l2;
    const int t = m & (Tt - 1);
    for (int b2 = 0; b2 < 8; b2++) {
        uint32_t r[32];
        LDTM_X32(r, cx.tmem + s2 * 256 + b2 * 32);
        T5_WAIT_LD();
        if (bx < 8) {
            size_t off = (size_t)m * HHD + bx * 256 + b2 * 32;
            #pragma unroll
            for (int j = 0; j < 32; j += 8) {
                uint4 hv, lv;
                split_pair(__uint_as_float(r[j+0]), __uint_as_float(r[j+1]), hv.x, lv.x);
                split_pair(__uint_as_float(r[j+2]), __uint_as_float(r[j+3]), hv.y, lv.y);
                split_pair(__uint_as_float(r[j+4]), __uint_as_float(r[j+5]), hv.z, lv.z);
                split_pair(__uint_as_float(r[j+6]), __uint_as_float(r[j+7]), hv.w, lv.w);
                *reinterpret_cast<uint4*>(&Kch[off + j]) = hv;
                *reinterpret_cast<uint4*>(&Kcl[off + j]) = lv;
            }
        } else if (bx < 16) {
            const int bq = m >> 11, tloc = m & (Tt - 1);
            #pragma unroll
            for (int j = 0; j < 32; j++) {
                int gcol = (bx - 8) * 256 + b2 * 32 + j;
                int hh2 = gcol >> 7, d = gcol & 127;
                float v = __uint_as_float(r[j]);
                __half vh = __float2half_rn(v);
                size_t off = ((size_t)(bq * Hh + hh2) * HD + d) * Tt + tloc;
                Vth[off] = vh;
                Vtl[off] = __float2half_rn(v - __half2float(vh));
            }
        } else if (bx < 24) {
            size_t off = (size_t)m * HHD + (bx - 16) * 256 + b2 * 32;
            #pragma unroll
            for (int j = 0; j < 32; j += 8) {
                uint4 hv, lv;
                split_pair(__uint_as_float(r[j+0]), __uint_as_float(r[j+1]), hv.x, lv.x);
                split_pair(__uint_as_float(r[j+2]), __uint_as_float(r[j+3]), hv.y, lv.y);
                split_pair(__uint_as_float(r[j+4]), __uint_as_float(r[j+5]), hv.z, lv.z);
                split_pair(__uint_as_float(r[j+6]), __uint_as_float(r[j+7]), hv.w, lv.w);
                *reinterpret_cast<uint4*>(&Qch[off + j]) = hv;
                *reinterpret_cast<uint4*>(&Qcl[off + j]) = lv;
            }
        } else {
            #pragma unroll
            for (int j = 0; j < 32; j += 2) {
                int gcol = (bx - 24) * 256 + b2 * 32 + j;
                float f = freqs[t * (Rr / 2) + ((gcol & 63) >> 1)], s, c;
                sincosf(f, &s, &c);
                float x0 = __uint_as_float(r[j]), x1 = __uint_as_float(r[j + 1]);
                float y0 = x0 * c - x1 * s, y1 = x0 * s + x1 * c;
                uint32_t hi, lo;
                split_pair(y0, y1, hi, lo);
                size_t off = (size_t)m * HRr + gcol;
                *reinterpret_cast<uint32_t*>(&Qrh[off]) = hi;
                *reinterpret_cast<uint32_t*>(&Qrl[off]) = lo;
            }
        }
    }
    __syncthreads();
    if (threadIdx.x < 32) T5_DEALLOC(cx.tmem, 512);
#else
    const int tid = threadIdx.x;
    for (int e = tid; e < 256 * 256; e += 256) {
        int rr = e >> 8, cc = e & 255;
        int m = bm + rr;
        if (bx < 8) {
            float acc = dot_hl(cKVh + (size_t)bm*KVL, cKVl + (size_t)bm*KVL,
                               g_WtH + O_UK + (size_t)(bx*256)*KVL,
                               g_WtL + O_UK + (size_t)(bx*256)*KVL, KVL, rr, cc);
            size_t off = (size_t)m * HHD + bx * 256 + cc;
            __half h = __float2half_rn(acc);
            Kch[off] = h;
            Kcl[off] = __float2half_rn(acc - __half2float(h));
        } else if (bx < 16) {
            float acc = dot_hl(cKVh + (size_t)bm*KVL, cKVl + (size_t)bm*KVL,
                               g_WtH + O_UV + (size_t)((bx-8)*256)*KVL,
                               g_WtL + O_UV + (size_t)((bx-8)*256)*KVL, KVL, rr, cc);
            int gcol = (bx - 8) * 256 + cc;
            int hh2 = gcol >> 7, d = gcol & 127;
            int bq = m >> 11, tloc = m & (Tt - 1);
            size_t off = ((size_t)(bq * Hh + hh2) * HD + d) * Tt + tloc;
            __half h = __float2half_rn(acc);
            Vth[off] = h;
            Vtl[off] = __float2half_rn(acc - __half2float(h));
        } else if (bx < 24) {
            float acc = dot_hl(cQh + (size_t)bm*QL, cQl + (size_t)bm*QL,
                               g_WtH + O_UQ + (size_t)((bx-16)*256)*QL,
                               g_WtL + O_UQ + (size_t)((bx-16)*256)*QL, QL, rr, cc);
            size_t off = (size_t)m * HHD + (bx - 16) * 256 + cc;
            __half h = __float2half_rn(acc);
            Qch[off] = h;
            Qcl[off] = __float2half_rn(acc - __half2float(h));
        } else if ((cc & 1) == 0) {
            float x0 = dot_hl(cQh + (size_t)bm*QL, cQl + (size_t)bm*QL,
                              g_WtH + O_QR + (size_t)((bx-24)*256)*QL,
                              g_WtL + O_QR + (size_t)((bx-24)*256)*QL, QL, rr, cc);
            float x1 = dot_hl(cQh + (size_t)bm*QL, cQl + (size_t)bm*QL,
                              g_WtH + O_QR + (size_t)((bx-24)*256)*QL,
                              g_WtL + O_QR + (size_t)((bx-24)*256)*QL, QL, rr, cc + 1);
            int gcol = (bx - 24) * 256 + cc;
            int t = m & (Tt - 1);
            float f = freqs[t * (Rr / 2) + ((gcol & 63) >> 1)], s, c;
            sincosf(f, &s, &c);
            float y0 = x0 * c - x1 * s, y1 = x0 * s + x1 * c;
            size_t off = (size_t)m * HRr + gcol;
            __half h0 = __float2half_rn(y0), h1 = __float2half_rn(y1);
            Qrh[off] = h0; Qrh[off + 1] = h1;
            Qrl[off] = __float2half_rn(y0 - __half2float(h0));
            Qrl[off + 1] = __float2half_rn(y1 - __half2float(h1));
        }
    }
#endif
}

// ---------------- wo: y = AO @ W_O (256x256 tiles) ----------------
__global__ __launch_bounds__(256) void wo_kernel(
    const __half* __restrict__ AOh, const __half* __restrict__ AOl,
    const __half* __restrict__ WtH, const __half* __restrict__ WtL,
    float* __restrict__ y)
{
    const int bx = blockIdx.x, bm = blockIdx.y * 256;
#if HAS_TCGEN05
    size_t bo = O_O + (size_t)(bx * 256) * HHD;
    MmaCtx cx = gemm_main2(AOh + (size_t)bm * HHD, AOl + (size_t)bm * HHD,
                           WtH + bo, WtL + bo, HHD);
    const int w = threadIdx.x >> 5, l2 = threadIdx.x & 31;
    const int s2 = w >> 2, sub = w & 3;
    const int m = bm + s2 * 128 + sub * 32 + l2;
    for (int b2 = 0; b2 < 8; b2++) {
        uint32_t r[32];
        LDTM_X32(r, cx.tmem + s2 * 256 + b2 * 32);
        T5_WAIT_LD();
        size_t off = (size_t)m * DM + bx * 256 + b2 * 32;
        #pragma unroll
        for (int j = 0; j < 32; j += 4)
            *reinterpret_cast<float4*>(&y[off + j]) = make_float4(
                __uint_as_float(r[j]), __uint_as_float(r[j+1]),
                __uint_as_float(r[j+2]), __uint_as_float(r[j+3]));
    }
    __syncthreads();
    if (threadIdx.x < 32) T5_DEALLOC(cx.tmem, 512);
#else
    const int tid = threadIdx.x;
    for (int e = tid; e < 256 * 256; e += 256) {
        int rr = e >> 8, cc = e & 255;
        float acc = dot_hl(AOh + (size_t)bm*HHD, AOl + (size_t)bm*HHD,
                           g_WtH + O_O + (size_t)(bx*256)*HHD,
                           g_WtL + O_O + (size_t)(bx*256)*HHD, HHD, rr, cc);
        y[(size_t)(bm + rr) * DM + bx * 256 + cc] = acc;
    }
#endif
}

// ---------------- fused flash attention (V c0 prefetched over softmax) ----
__global__ __launch_bounds__(256) void flash_kernel(
    const __half* __restrict__ Qch, const __half* __restrict__ Qcl,
    const __half* __restrict__ Qrh, const __half* __restrict__ Qrl,
    const __half* __restrict__ Kch, const __half* __restrict__ Kcl,
    const __half* __restrict__ Krh, const __half* __restrict__ Krl,
    const __half* __restrict__ Vth, const __half* __restrict__ Vtl,
    __half* __restrict__ AOh, __half* __restrict__ AOl)
{
    const int qt = 15 - blockIdx.x, bh = blockIdx.y;
    const int tid = threadIdx.x;
    const int b = bh >> 4, h = bh & 15;
    const float scale = 0.07216878364870323f;   // 1/sqrt(192)
#if HAS_TCGEN05
    constexpr int T_BYTES = 16384;
    extern __shared__ char smem[];
    MmaCtx cx = mma_begin(smem, 256);
    const uint32_t qbase  = cx.tiles;
    const uint32_t pbase  = qbase + 6 * T_BYTES;
    const uint32_t redmax = pbase + 2 * T_BYTES;
    const uint32_t redsum = redmax + 1024;
    const uint32_t bufb   = redsum + 1024;
    const uint32_t idesc = (1u << 4) | (16u << 17) | (8u << 24);
    const uint32_t tmemS = cx.tmem, tmemO = cx.tmem + 128;
    const size_t qrow0 = (size_t)(b * Tt + qt * 128);

    {
        const __half* qsrc[6] = {
            Qch + qrow0 * HHD + h * HD,       Qcl + qrow0 * HHD + h * HD,
            Qch + qrow0 * HHD + h * HD + 64,  Qcl + qrow0 * HHD + h * HD + 64,
            Qrh + qrow0 * HRr + h * Rr,       Qrl + qrow0 * HRr + h * Rr };
        const int qstr[6] = {HHD, HHD, HHD, HHD, HRr, HRr};
        #pragma unroll
        for (int i = 0; i < 24; i++) {
            int u = i * 256 + tid;
            int t = u >> 10, ul = u & 1023;
            int row = ul >> 3, seg = ul & 7;
            uint4 v = *reinterpret_cast<const uint4*>(
                qsrc[t] + (size_t)row * qstr[t] + seg * 8);
            uint32_t bo = row * 128 + seg * 16;
            sts128(qbase + t * T_BYTES + (bo ^ ((bo >> 3) & 0x70)),
                   v.x, v.y, v.z, v.w);
        }
    }

    const int w = tid >> 5, l2 = tid & 31, sub = w & 3, halfi = w >> 2;
    const int rowl = sub * 32 + l2;
    const int qglob = qt * 128 + rowl;
    float oacc[64];
    #pragma unroll
    for (int j = 0; j < 64; j++) oacc[j] = 0.f;
    float mrow = -INFINITY, lrow = 0.f;
    int u0 = 0, u1 = 0;

    for (int kt = 0; kt <= qt; kt++) {
        const size_t krow0 = (size_t)(b * Tt + kt * 128);
        for (int c = 0; c < 3; c++) {
            const int bid = c & 1;
            int cnt = bid ? u1 : u0;
            const uint32_t st = bufb + bid * 2 * T_BYTES;
            const __half* kh = (c < 2) ? Kch + krow0 * HHD + h * HD + c * 64
                                       : Krh + krow0 * Rr;
            const __half* kl = (c < 2) ? Kcl + krow0 * HHD + h * HD + c * 64
                                       : Krl + krow0 * Rr;
            const int str = (c < 2) ? HHD : Rr;
            uint4 v[8];
            uint32_t da[8];
            #pragma unroll
            for (int i = 0; i < 8; i++) {
                int u = i * 256 + tid;
                int t = u >> 10, ul = u & 1023;
                int row = ul >> 3, seg = ul & 7;
                const __half* src = t ? kl : kh;
                v[i] = *reinterpret_cast<const uint4*>(
                    src + (size_t)row * str + seg * 8);
                uint32_t bo = row * 128 + seg * 16;
                da[i] = st + t * T_BYTES + (bo ^ ((bo >> 3) & 0x70));
            }
            if (cnt > 0) MBAR_WAIT(cx.mb + 8 * bid, (cnt - 1) & 1);
            #pragma unroll
            for (int i = 0; i < 8; i++)
                sts128(da[i], v[i].x, v[i].y, v[i].z, v[i].w);
            FENCE_ASYNC();
            __syncthreads();
            mma_chunk(tmemS, cx.mb + 8 * bid,
                      mk_desc(qbase + (2 * c) * T_BYTES),
                      mk_desc(qbase + (2 * c + 1) * T_BYTES),
                      mk_desc(st), mk_desc(st + T_BYTES), idesc, c == 0);
            if (bid) u1++; else u0++;
        }
        // ---- prefetch V c0 LDGs (land during softmax) ----
        uint4 vv0[8];
        uint32_t vda0[8];
        {
            const __half* vh = Vth + (size_t)bh * HD * Tt + kt * 128;
            const __half* vl = Vtl + (size_t)bh * HD * Tt + kt * 128;
            const uint32_t st = bufb;
            #pragma unroll
            for (int i = 0; i < 8; i++) {
                int u = i * 256 + tid;
                int t = u >> 10, ul = u & 1023;
                int row = ul >> 3, seg = ul & 7;
                const __half* src = t ? vl : vh;
                vv0[i] = *reinterpret_cast<const uint4*>(
                    src + (size_t)row * Tt + seg * 8);
                uint32_t bo = row * 128 + seg * 16;
                vda0[i] = st + t * T_BYTES + (bo ^ ((bo >> 3) & 0x70));
            }
        }
        MBAR_WAIT(cx.mb + 0, (u0 - 1) & 1);
        T5_FENCE_AFTER();

        uint32_t sr[32];
        float sv[64];
        LDTM_X32(sr, tmemS + halfi * 64);
        T5_WAIT_LD();
        #pragma unroll
        for (int j = 0; j < 32; j++) sv[j] = __uint_as_float(sr[j]) * scale;
        LDTM_X32(sr, tmemS + halfi * 64 + 32);
        T5_WAIT_LD();
        #pragma unroll
        for (int j = 0; j < 32; j++) sv[32 + j] = __uint_as_float(sr[j]) * scale;
        T5_FENCE_BEFORE();
        if (kt == qt) {
            int cbase = kt * 128 + halfi * 64;
            #pragma unroll
            for (int j = 0; j < 64; j++)
                if (cbase + j > qglob) sv[j] = -INFINITY;
        }
        float pmax = -INFINITY;
        #pragma unroll
        for (int j = 0; j < 64; j++) pmax = fmaxf(pmax, sv[j]);
        asm volatile("st.shared.f32 [%0], %1;"
                     :: "r"(redmax + (halfi * 128 + rowl) * 4), "f"(pmax) : "memory");
        __syncthreads();
        float omax;
        asm volatile("ld.shared.f32 %0, [%1];"
                     : "=f"(omax) : "r"(redmax + ((1 - halfi) * 128 + rowl) * 4));
        float mnew = fmaxf(mrow, fmaxf(pmax, omax));
        float alpha = __expf(mrow - mnew);
        mrow = mnew;
        float psum = 0.f;
        uint32_t pw[32];
        #pragma unroll
        for (int j = 0; j < 32; j++) {
            float p0 = __expf(sv[2 * j] - mnew);
            float p1 = __expf(sv[2 * j + 1] - mnew);
            psum += p0 + p1;
            pw[j] = ((uint32_t)__half_as_ushort(__float2half_rn(p1)) << 16)
                  | __half_as_ushort(__float2half_rn(p0));
        }
        #pragma unroll
        for (int sgm = 0; sgm < 8; sgm++) {
            uint32_t bo = rowl * 128 + sgm * 16;
            sts128(pbase + halfi * T_BYTES + (bo ^ ((bo >> 3) & 0x70)),
                   pw[sgm * 4], pw[sgm * 4 + 1], pw[sgm * 4 + 2], pw[sgm * 4 + 3]);
        }
        asm volatile("st.shared.f32 [%0], %1;"
                     :: "r"(redsum + (halfi * 128 + rowl) * 4), "f"(psum) : "memory");
        FENCE_ASYNC();
        __syncthreads();
        float osum;
        asm volatile("ld.shared.f32 %0, [%1];"
                     : "=f"(osum) : "r"(redsum + ((1 - halfi) * 128 + rowl) * 4));
        lrow = lrow * alpha + psum + osum;

        #pragma unroll
        for (int i = 0; i < 8; i++)
            sts128(vda0[i], vv0[i].x, vv0[i].y, vv0[i].z, vv0[i].w);
        FENCE_ASYNC();
        __syncthreads();
        if (tid < 32 && elect1()) {
            uint64_t pd = mk_desc(pbase);
            uint64_t vhd = mk_desc(bufb), vld = mk_desc(bufb + T_BYTES);
            #pragma unroll
            for (int q = 0; q < 4; q++)
                mma_f16(tmemO, pd + 2 * q, vhd + 2 * q, idesc, q == 0 ? 0u : 1u);
            #pragma unroll
            for (int q = 0; q < 4; q++)
                mma_f16(tmemO, pd + 2 * q, vld + 2 * q, idesc, 1u);
            T5_COMMIT(cx.mb + 0);
        }
        u0++;

        {
            const uint32_t st = bufb + 2 * T_BYTES;
            const __half* vh = Vth + (size_t)bh * HD * Tt + kt * 128 + 64;
            const __half* vl = Vtl + (size_t)bh * HD * Tt + kt * 128 + 64;
            uint4 v[8];
            uint32_t da[8];
            #pragma unroll
            for (int i = 0; i < 8; i++) {
                int u = i * 256 + tid;
                int t = u >> 10, ul = u & 1023;
                int row = ul >> 3, seg = ul & 7;
                const __half* src = t ? vl : vh;
                v[i] = *reinterpret_cast<const uint4*>(
                    src + (size_t)row * Tt + seg * 8);
                uint32_t bo = row * 128 + seg * 16;
                da[i] = st + t * T_BYTES + (bo ^ ((bo >> 3) & 0x70));
            }
            MBAR_WAIT(cx.mb + 8, (u1 - 1) & 1);
            #pragma unroll
            for (int i = 0; i < 8; i++)
                sts128(da[i], v[i].x, v[i].y, v[i].z, v[i].w);
            FENCE_ASYNC();
            __syncthreads();
            if (tid < 32 && elect1()) {
                uint64_t pd = mk_desc(pbase + T_BYTES);
                uint64_t vhd = mk_desc(st), vld = mk_desc(st + T_BYTES);
                #pragma unroll
                for (int q = 0; q < 4; q++)
                    mma_f16(tmemO, pd + 2 * q, vhd + 2 * q, idesc, 1u);
                #pragma unroll
                for (int q = 0; q < 4; q++)
                    mma_f16(tmemO, pd + 2 * q, vld + 2 * q, idesc, 1u);
                T5_COMMIT(cx.mb + 8);
            }
            u1++;
        }
        MBAR_WAIT(cx.mb + 8, (u1 - 1) & 1);
        T5_FENCE_AFTER();
        LDTM_X32(sr, tmemO + halfi * 64);
        T5_WAIT_LD();
        #pragma unroll
        for (int j = 0; j < 32; j++)
            oacc[j] = oacc[j] * alpha + __uint_as_float(sr[j]);
        LDTM_X32(sr, tmemO + halfi * 64 + 32);
        T5_WAIT_LD();
        #pragma unroll
        for (int j = 0; j < 32; j++)
            oacc[32 + j] = oacc[32 + j] * alpha + __uint_as_float(sr[j]);
        T5_FENCE_BEFORE();
        __syncthreads();
    }

    const float invl = 1.0f / lrow;
    const size_t off = (size_t)(b * Tt + qt * 128 + rowl) * HHD + h * HD + halfi * 64;
    #pragma unroll
    for (int j = 0; j < 64; j += 8) {
        uint4 hv, lv;
        split_pair(oacc[j+0] * invl, oacc[j+1] * invl, hv.x, lv.x);
        split_pair(oacc[j+2] * invl, oacc[j+3] * invl, hv.y, lv.y);
        split_pair(oacc[j+4] * invl, oacc[j+5] * invl, hv.z, lv.z);
        split_pair(oacc[j+6] * invl, oacc[j+7] * invl, hv.w, lv.w);
        *reinterpret_cast<uint4*>(&AOh[off + j]) = hv;
        *reinterpret_cast<uint4*>(&AOl[off + j]) = lv;
    }
    __syncthreads();
    if (tid < 32) T5_DEALLOC(cx.tmem, 256);
#else
    for (int e = tid; e < 128 * 128; e += 256) {
        int r = e >> 7, d = e & 127;
        int qg = qt * 128 + r;
        size_t qoC = (size_t)(b * Tt + qg) * HHD + h * HD;
        size_t qoR = (size_t)(b * Tt + qg) * HRr + h * Rr;
        float m = -1e30f;
        for (int k = 0; k <= qg; k++) {
            size_t koC = (size_t)(b * Tt + k) * HHD + h * HD;
            size_t koR = (size_t)(b * Tt + k) * Rr;
            float s = 0.f;
            for (int dd = 0; dd < HD; dd++)
                s += (__half2float(Qch[qoC+dd]) + __half2float(Qcl[qoC+dd]))
                   * (__half2float(Kch[koC+dd]) + __half2float(Kcl[koC+dd]));
            for (int dd = 0; dd < Rr; dd++)
                s += (__half2float(Qrh[qoR+dd]) + __half2float(Qrl[qoR+dd]))
                   * (__half2float(Krh[koR+dd]) + __half2float(Krl[koR+dd]));
            s *= scale;
            if (s > m) m = s;
        }
        float l = 0.f, o = 0.f;
        for (int k = 0; k <= qg; k++) {
            size_t koC = (size_t)(b * Tt + k) * HHD + h * HD;
            size_t koR = (size_t)(b * Tt + k) * Rr;
            float s = 0.f;
            for (int dd = 0; dd < HD; dd++)
                s += (__half2float(Qch[qoC+dd]) + __half2float(Qcl[qoC+dd]))
                   * (__half2float(Kch[koC+dd]) + __half2float(Kcl[koC+dd]));
            for (int dd = 0; dd < Rr; dd++)
                s += (__half2float(Qrh[qoR+dd]) + __half2float(Qrl[qoR+dd]))
                   * (__half2float(Krh[koR+dd]) + __half2float(Krl[koR+dd]));
            float p = expf(s * scale - m);
            l += p;
            o += p * (__half2float(Vth[((size_t)bh*HD + d)*Tt + k])
                    + __half2float(Vtl[((size_t)bh*HD + d)*Tt + k]));
        }
        o /= l;
        size_t off = (size_t)(b * Tt + qg) * HHD + h * HD + d;
        __half hh = __float2half_rn(o);
        AOh[off] = hh;
        AOl[off] = __float2half_rn(o - __half2float(hh));
    }
#endif
}

// ---------------- launch ----------------
#define MMA_SMEM 198656      // ctx + 3 x 64KB stages
#define FLASH_SMEM 202752

extern "C" void kernel_launch(void* const* d_in, const int* in_sizes, int n_in,
                              void* d_out, int out_size)
{
    const float* x     = (const float*)d_in[0];
    const float* freqs = (const float*)d_in[1];
    const float* W_DKV = (const float*)d_in[2];
    const float* W_UK  = (const float*)d_in[3];
    const float* W_UV  = (const float*)d_in[4];
    const float* W_KR  = (const float*)d_in[5];
    const float* W_DQ  = (const float*)d_in[6];
    const float* W_UQ  = (const float*)d_in[7];
    const float* W_QR  = (const float*)d_in[8];
    const float* W_O   = (const float*)d_in[9];

    float* y   = (float*)d_out;
    float* cKV = y   + (size_t)Bb * Tt * DM;
    float* KRo = cKV + (size_t)Bb * Tt * KVL;

    __half *pxH, *pxL, *pWtH, *pWtL, *pcKVh, *pcKVl, *pcQh, *pcQl;
    __half *pQch, *pQcl, *pQrh, *pQrl, *pKch, *pKcl, *pKrh, *pKrl;
    __half *pVth, *pVtl, *pAOh, *pAOl;
    cudaGetSymbolAddress((void**)&pxH,  g_xH);
    cudaGetSymbolAddress((void**)&pxL,  g_xL);
    cudaGetSymbolAddress((void**)&pWtH, g_WtH);
    cudaGetSymbolAddress((void**)&pWtL, g_WtL);
    cudaGetSymbolAddress((void**)&pcKVh, g_cKVh);
    cudaGetSymbolAddress((void**)&pcKVl, g_cKVl);
    cudaGetSymbolAddress((void**)&pcQh, g_cQh);
    cudaGetSymbolAddress((void**)&pcQl, g_cQl);
    cudaGetSymbolAddress((void**)&pQch, g_Qch);
    cudaGetSymbolAddress((void**)&pQcl, g_Qcl);
    cudaGetSymbolAddress((void**)&pQrh, g_Qrh);
    cudaGetSymbolAddress((void**)&pQrl, g_Qrl);
    cudaGetSymbolAddress((void**)&pKch, g_Kch);
    cudaGetSymbolAddress((void**)&pKcl, g_Kcl);
    cudaGetSymbolAddress((void**)&pKrh, g_Krh);
    cudaGetSymbolAddress((void**)&pKrl, g_Krl);
    cudaGetSymbolAddress((void**)&pVth, g_Vth);
    cudaGetSymbolAddress((void**)&pVtl, g_Vtl);
    cudaGetSymbolAddress((void**)&pAOh, g_AOh);
    cudaGetSymbolAddress((void**)&pAOl, g_AOl);

    cudaFuncSetAttribute(xproj_kernel,  cudaFuncAttributeMaxDynamicSharedMemorySize, MMA_SMEM);
    cudaFuncSetAttribute(kqproj_kernel, cudaFuncAttributeMaxDynamicSharedMemorySize, MMA_SMEM);
    cudaFuncSetAttribute(wo_kernel,     cudaFuncAttributeMaxDynamicSharedMemorySize, MMA_SMEM);
    cudaFuncSetAttribute(flash_kernel,  cudaFuncAttributeMaxDynamicSharedMemorySize, FLASH_SMEM);

    // #1: split x
    split_x_kernel<<<(MROWS * DM / 4) / 256, 256>>>(x, pxH, pxL);

    // #2: all weight transposes (KR padded to 256-row tile; pad rows stay 0)
    TSJobs jobs;
    int tiles = 0;
    auto addjob = [&](int i, const float* W, size_t off, int K, int N) {
        jobs.a[i] = {W, pWtH + off, pWtL + off, K, N, tiles};
        tiles += (K / 32) * (N / 32);
    };
    addjob(0, W_DKV, O_DKV, DM, KVL);
    addjob(1, W_UK,  O_UK,  KVL, HHD);
    addjob(2, W_UV,  O_UV,  KVL, HHD);
    addjob(3, W_DQ,  O_DQ,  DM, QL);
    addjob(4, W_UQ,  O_UQ,  QL, HHD);
    addjob(5, W_QR,  O_QR,  QL, HRr);
    addjob(6, W_O,   O_O,   HHD, DM);
    addjob(7, W_KR,  O_KRP, DM, Rr);
    tsplit_all_kernel<<<tiles, 256>>>(jobs);

    // #3: xproj (cKV | cQ | KR+rope), 256x256 tiles
    xproj_kernel<<<dim3(7, MROWS/256), 256, MMA_SMEM>>>(
        pxH, pxL, pWtH, pWtL, freqs, cKV, pcKVh, pcKVl, pcQh, pcQl,
        KRo, pKrh, pKrl);
    // #4: merged kv+q projections (UK|UV|UQ|QR), 256x256 tiles
    kqproj_kernel<<<dim3(28, MROWS/256), 256, MMA_SMEM>>>(
        pcKVh, pcKVl, pcQh, pcQl, pWtH, pWtL, freqs,
        pKch, pKcl, pVth, pVtl, pQch, pQcl, pQrh, pQrl);
    // #5: fused flash attention
    flash_kernel<<<dim3(16, BH), 256, FLASH_SMEM>>>(
        pQch, pQcl, pQrh, pQrl, pKch, pKcl, pKrh, pKrl, pVth, pVtl, pAOh, pAOl);
    // #6: y = AO @ W_O, 256x256 tiles
    wo_kernel<<<dim3(8, MROWS/256), 256, MMA_SMEM>>>(pAOh, pAOl, pWtH, pWtL, y);
}

// round 17
// speedup vs baseline: 1.1107x; 1.0237x over previous
#include <cuda_runtime.h>
#include <cuda.h>
#include <cuda_fp16.h>
#include <math.h>
#include <stdint.h>

#define Bb 2
#define Tt 2048
#define DM 2048
#define Hh 16
#define HD 128
#define KVL 512
#define QL 1024
#define Rr 64
#define MROWS (Bb*Tt)
#define BH (Bb*Hh)
#define HHD (Hh*HD)
#define HRr (Hh*Rr)

#if defined(__CUDA_ARCH_FEAT_SM103_ALL) || defined(__CUDA_ARCH_FEAT_SM100_ALL)
#define HAS_TCGEN05 1
#else
#define HAS_TCGEN05 0
#endif

// ---------------- scratch ----------------
__device__ __align__(256) __half g_xH[MROWS * DM],  g_xL[MROWS * DM];
__device__ __align__(256) __half g_cKVh[MROWS * KVL], g_cKVl[MROWS * KVL];
__device__ __align__(256) __half g_cQh[MROWS * QL],   g_cQl[MROWS * QL];
__device__ __align__(256) __half g_Qch[MROWS * HHD],  g_Qcl[MROWS * HHD];
__device__ __align__(256) __half g_Qrh[MROWS * HRr],  g_Qrl[MROWS * HRr];
__device__ __align__(256) __half g_Kch[MROWS * HHD],  g_Kcl[MROWS * HHD];
__device__ __align__(256) __half g_Krh[MROWS * Rr],   g_Krl[MROWS * Rr];
__device__ __align__(256) __half g_Vth[BH * HD * Tt], g_Vtl[BH * HD * Tt];
__device__ __align__(256) __half g_AOh[MROWS * HHD],  g_AOl[MROWS * HHD];
#define O_DKV 0
#define O_UK  (O_DKV + 512*2048)
#define O_UV  (O_UK  + 2048*512)
#define O_DQ  (O_UV  + 2048*512)
#define O_UQ  (O_DQ  + 1024*2048)
#define O_QR  (O_UQ  + 2048*1024)
#define O_O   (O_QR  + 2048*1024)
#define O_KRP (O_O   + 2048*2048)
#define WT_TOTAL (O_KRP + 256*2048)
__device__ __align__(256) __half g_WtH[WT_TOTAL], g_WtL[WT_TOTAL];

// ---------------- tensormap bundles ----------------
struct XMaps  { CUtensorMap ah, al, b0h, b0l, b1h, b1l, b2h, b2l; };
struct KQMaps { CUtensorMap a0h, a0l, a1h, a1l,
                w0h, w0l, w1h, w1l, w2h, w2l, w3h, w3l; };
struct WOMaps { CUtensorMap ah, al, bh, bl; };

// ---------------- helpers ----------------
__device__ __forceinline__ uint32_t smem_u32(const void* p) {
    uint32_t a;
    asm("{ .reg .u64 t; cvta.to.shared.u64 t, %1; cvt.u32.u64 %0, t; }"
        : "=r"(a) : "l"(p));
    return a;
}
__device__ __forceinline__ void split_pair(float a, float b,
                                           uint32_t& hi, uint32_t& lo) {
    __half ha = __float2half_rn(a), hb = __float2half_rn(b);
    hi = ((uint32_t)__half_as_ushort(hb) << 16) | __half_as_ushort(ha);
    lo = ((uint32_t)__half_as_ushort(__float2half_rn(b - __half2float(hb))) << 16)
       | __half_as_ushort(__float2half_rn(a - __half2float(ha)));
}

#if HAS_TCGEN05
__device__ __forceinline__ bool elect1() {
    uint32_t r;
    asm volatile("{\n\t.reg .pred p;\n\telect.sync _|p, 0xFFFFFFFF;\n\t"
                 "selp.b32 %0,1,0,p;\n\t}" : "=r"(r));
    return r != 0;
}
#define MBAR_INIT(a, c) \
    asm volatile("mbarrier.init.shared.b64 [%0], %1;" :: "r"(a), "r"(c) : "memory")
#define MBAR_EXPECT(a, n) \
    asm volatile("mbarrier.arrive.expect_tx.shared.b64 _, [%0], %1;" \
                 :: "r"(a), "r"(n) : "memory")
#define MBAR_WAIT(a, ph) do { \
    uint32_t _m = (a), _p = (uint32_t)(ph), _d; \
    asm volatile("{\n\t.reg .pred p;\n\t" \
        "mbarrier.try_wait.parity.acquire.cta.shared::cta.b64 p, [%1], %2;\n\t" \
        "selp.b32 %0,1,0,p;\n\t}" : "=r"(_d) : "r"(_m), "r"(_p) : "memory"); \
    while (!_d) { \
        asm volatile("{\n\t.reg .pred p;\n\t" \
            "mbarrier.try_wait.parity.acquire.cta.shared::cta.b64 p, [%1], %2, 0x989680;\n\t" \
            "selp.b32 %0,1,0,p;\n\t}" : "=r"(_d) : "r"(_m), "r"(_p) : "memory"); \
    } } while (0)
#define TMA2D(smem, map, cx2, cy2, mbar) \
    asm volatile("cp.async.bulk.tensor.2d.shared::cta.global.tile.mbarrier::complete_tx::bytes " \
        "[%0], [%1, {%2, %3}], [%4];" \
        :: "r"(smem), "l"(map), "r"(cx2), "r"(cy2), "r"(mbar) : "memory")
#define T5_COMMIT(a) \
    asm volatile("tcgen05.commit.cta_group::1.mbarrier::arrive::one.shared::cluster.b64 [%0];" \
                 :: "r"(a) : "memory")
#define T5_ALLOC(a, n) \
    asm volatile("tcgen05.alloc.cta_group::1.sync.aligned.shared::cta.b32 [%0], %1;" \
                 :: "r"(a), "r"(n) : "memory")
#define T5_DEALLOC(t, n) \
    asm volatile("tcgen05.dealloc.cta_group::1.sync.aligned.b32 %0, %1;" :: "r"(t), "r"(n))
#define T5_RELINQ() \
    asm volatile("tcgen05.relinquish_alloc_permit.cta_group::1.sync.aligned;")
#define T5_WAIT_LD()   asm volatile("tcgen05.wait::ld.sync.aligned;" ::: "memory")
#define T5_FENCE_AFTER() asm volatile("tcgen05.fence::after_thread_sync;" ::: "memory")
#define T5_FENCE_BEFORE() asm volatile("tcgen05.fence::before_thread_sync;" ::: "memory")
#define FENCE_ASYNC()  asm volatile("fence.proxy.async.shared::cta;" ::: "memory")

#define LDTM_X32(r, addr) \
    asm volatile("tcgen05.ld.sync.aligned.32x32b.x32.b32 " \
        "{%0, %1, %2, %3, %4, %5, %6, %7, %8, %9, %10, %11, %12, %13, %14, %15, " \
        "%16, %17, %18, %19, %20, %21, %22, %23, %24, %25, %26, %27, %28, %29, %30, %31}, [%32];" \
        : "=r"((r)[0]),  "=r"((r)[1]),  "=r"((r)[2]),  "=r"((r)[3]), \
          "=r"((r)[4]),  "=r"((r)[5]),  "=r"((r)[6]),  "=r"((r)[7]), \
          "=r"((r)[8]),  "=r"((r)[9]),  "=r"((r)[10]), "=r"((r)[11]), \
          "=r"((r)[12]), "=r"((r)[13]), "=r"((r)[14]), "=r"((r)[15]), \
          "=r"((r)[16]), "=r"((r)[17]), "=r"((r)[18]), "=r"((r)[19]), \
          "=r"((r)[20]), "=r"((r)[21]), "=r"((r)[22]), "=r"((r)[23]), \
          "=r"((r)[24]), "=r"((r)[25]), "=r"((r)[26]), "=r"((r)[27]), \
          "=r"((r)[28]), "=r"((r)[29]), "=r"((r)[30]), "=r"((r)[31]) \
        : "r"(addr))

__device__ __forceinline__ void mma_f16(uint32_t d, uint64_t ad, uint64_t bd,
                                        uint32_t idesc, uint32_t en) {
    asm volatile("{\n\t.reg .pred p;\n\tsetp.ne.u32 p, %4, 0;\n\t"
        "tcgen05.mma.cta_group::1.kind::f16 [%0], %1, %2, %3, p;\n\t}"
        :: "r"(d), "l"(ad), "l"(bd), "r"(idesc), "r"(en) : "memory");
}
// SW128 K-major descriptor (flash kernel tiles)
__device__ __forceinline__ uint64_t mk_desc(uint32_t addr) {
    return ((uint64_t)2 << 61) | ((uint64_t)1 << 46) | ((uint64_t)64 << 32)
         | ((uint64_t)1 << 16) | ((addr >> 4) & 0x3FFF);
}
// SW64 K-major descriptor (TMA-fed GEMM tiles): layout=4, SBO=32, LBO=1
__device__ __forceinline__ uint64_t mk_desc64(uint32_t addr) {
    return ((uint64_t)4 << 61) | ((uint64_t)1 << 46) | ((uint64_t)32 << 32)
         | ((uint64_t)1 << 16) | ((addr >> 4) & 0x3FFF);
}
__device__ __forceinline__ void sts128(uint32_t addr, uint32_t a, uint32_t b,
                                       uint32_t c, uint32_t d) {
    asm volatile("st.shared.v4.b32 [%0], {%1,%2,%3,%4};"
                 :: "r"(addr), "r"(a), "r"(b), "r"(c), "r"(d) : "memory");
}

// ---------------- flash-kernel context (unchanged mechanics) ----------------
struct MmaCtx { uint32_t mb, mb_done, tmem, tiles; };
__device__ __forceinline__ MmaCtx mma_begin(char* smem, int ncols) {
    MmaCtx cx;
    uint32_t sbase = smem_u32(smem);
    cx.mb = sbase;
    cx.mb_done = sbase + 24;
    cx.tiles = (sbase + 64 + 1023) & ~1023u;
    if (threadIdx.x == 0) {
        MBAR_INIT(cx.mb + 0, 1);
        MBAR_INIT(cx.mb + 8, 1);
        MBAR_INIT(cx.mb + 16, 1);
        MBAR_INIT(cx.mb_done, 1);
    }
    if (threadIdx.x < 32) { T5_ALLOC(sbase + 32, ncols); T5_RELINQ(); }
    __syncthreads();
    asm volatile("ld.shared.b32 %0, [%1];" : "=r"(cx.tmem) : "r"(sbase + 32));
    return cx;
}
__device__ __forceinline__ void mma_chunk(uint32_t tmem, uint32_t mbar,
                                          uint64_t ah, uint64_t al,
                                          uint64_t bh, uint64_t bl,
                                          uint32_t idesc, bool first) {
    if (threadIdx.x < 32 && elect1()) {
        #pragma unroll
        for (int q = 0; q < 4; q++)
            mma_f16(tmem, ah + 2*q, bh + 2*q, idesc, (first && q == 0) ? 0u : 1u);
        #pragma unroll
        for (int q = 0; q < 4; q++)
            mma_f16(tmem, ah + 2*q, bl + 2*q, idesc, 1u);
        #pragma unroll
        for (int q = 0; q < 4; q++)
            mma_f16(tmem, al + 2*q, bh + 2*q, idesc, 1u);
        T5_COMMIT(mbar);
    }
}

// ---------------- TMA-fed 256x256 GEMM mainloop ----------------
// Stage 64KB: Ah@0, Al@16384, Bh@32768, Bl@49152 (each 256 rows x 64B SW64).
// Barriers: full[s]@base+8s, mma[s]@base+24+8s, done@base+48, tmem@base+56.
struct TCtx { uint32_t base, tmem, tiles; };
__device__ __forceinline__ TCtx tma_gemm_begin(char* smem) {
    TCtx cx;
    uint32_t sb = smem_u32(smem);
    cx.base = sb;
    cx.tiles = (sb + 64 + 1023) & ~1023u;
    if (threadIdx.x == 0)
        for (int i = 0; i < 7; i++) MBAR_INIT(sb + 8 * i, 1);
    if (threadIdx.x < 32) { T5_ALLOC(sb + 56, 512); T5_RELINQ(); }
    __syncthreads();
    asm volatile("ld.shared.b32 %0, [%1];" : "=r"(cx.tmem) : "r"(sb + 56));
    return cx;
}
__device__ __forceinline__ void tma4(
    const CUtensorMap* Ah, const CUtensorMap* Al,
    const CUtensorMap* Bh, const CUtensorMap* Bl,
    int k0, int am, int bn, uint32_t st, uint32_t mbar)
{
    TMA2D(st,         Ah, k0, am, mbar);
    TMA2D(st + 16384, Al, k0, am, mbar);
    TMA2D(st + 32768, Bh, k0, bn, mbar);
    TMA2D(st + 49152, Bl, k0, bn, mbar);
}
__device__ __forceinline__ TCtx gemm_tma(
    const CUtensorMap* Ahm, const CUtensorMap* Alm,
    const CUtensorMap* Bhm, const CUtensorMap* Blm,
    int K, int am, int bn)
{
    constexpr int STAGE = 65536;
    extern __shared__ char smem[];
    TCtx cx = tma_gemm_begin(smem);
    const uint32_t idesc = (1u << 4) | (32u << 17) | (8u << 24);   // N=256
    const int nc = K >> 5;
    if (threadIdx.x == 0) {
        for (int s = 0; s < 3; s++) {
            MBAR_EXPECT(cx.base + 8 * s, 65536);
            tma4(Ahm, Alm, Bhm, Blm, s * 32, am, bn,
                 cx.tiles + s * STAGE, cx.base + 8 * s);
        }
        for (int c = 0; c < nc; c++) {
            const int s = c - (c / 3) * 3;
            const uint32_t st = cx.tiles + s * STAGE;
            MBAR_WAIT(cx.base + 8 * s, (c / 3) & 1);
            uint64_t bhd = mk_desc64(st + 32768), bld = mk_desc64(st + 49152);
            #pragma unroll
            for (int s2 = 0; s2 < 2; s2++) {
                uint64_t ah = mk_desc64(st + s2 * 8192);
                uint64_t al = mk_desc64(st + 16384 + s2 * 8192);
                uint32_t d = cx.tmem + s2 * 256;
                #pragma unroll
                for (int q = 0; q < 2; q++)
                    mma_f16(d, ah + 2*q, bhd + 2*q, idesc,
                            (c == 0 && q == 0) ? 0u : 1u);
                #pragma unroll
                for (int q = 0; q < 2; q++)
                    mma_f16(d, ah + 2*q, bld + 2*q, idesc, 1u);
                #pragma unroll
                for (int q = 0; q < 2; q++)
                    mma_f16(d, al + 2*q, bhd + 2*q, idesc, 1u);
            }
            T5_COMMIT(cx.base + 24 + 8 * s);
            if (c >= 1) {
                const int cn = c + 2;
                if (cn < nc) {
                    const int sp = (c - 1) - ((c - 1) / 3) * 3;
                    MBAR_WAIT(cx.base + 24 + 8 * sp, ((c - 1) / 3) & 1);
                    MBAR_EXPECT(cx.base + 8 * sp, 65536);
                    tma4(Ahm, Alm, Bhm, Blm, cn * 32, am, bn,
                         cx.tiles + sp * STAGE, cx.base + 8 * sp);
                }
            }
        }
        T5_COMMIT(cx.base + 48);
    }
    MBAR_WAIT(cx.base + 48, 0);
    T5_FENCE_AFTER();
    return cx;
}
#else
__device__ __forceinline__ float dot_hl(
    const __half* Ah, const __half* Al,
    const __half* Bh, const __half* Bl, int K, int r, int c)
{
    float acc = 0.f;
    for (int k = 0; k < K; k++)
        acc += (__half2float(Ah[(size_t)r*K+k]) + __half2float(Al[(size_t)r*K+k]))
             * (__half2float(Bh[(size_t)c*K+k]) + __half2float(Bl[(size_t)c*K+k]));
    return acc;
}
#endif

// ---------------- producers ----------------
__global__ __launch_bounds__(256) void split_x_kernel(
    const float* __restrict__ x, __half* __restrict__ xh, __half* __restrict__ xl)
{
    size_t i = (size_t)(blockIdx.x * 256 + threadIdx.x) * 4;
    float4 v = *reinterpret_cast<const float4*>(&x[i]);
    uint32_t h0, l0, h1, l1;
    split_pair(v.x, v.y, h0, l0);
    split_pair(v.z, v.w, h1, l1);
    *reinterpret_cast<uint2*>(&xh[i]) = make_uint2(h0, h1);
    *reinterpret_cast<uint2*>(&xl[i]) = make_uint2(l0, l1);
}

struct TSJob { const float* W; __half* H; __half* L; int K; int N; int tile0; };
struct TSJobs { TSJob a[8]; };

__global__ __launch_bounds__(256) void tsplit_all_kernel(TSJobs jobs)
{
    __shared__ float t[32][33];
    int bx = blockIdx.x;
    int ji = 0;
    #pragma unroll
    for (int i = 1; i < 8; i++)
        if (bx >= jobs.a[i].tile0) ji = i;
    TSJob j = jobs.a[ji];
    int tl = bx - j.tile0;
    int ntN = j.N >> 5;
    int n0 = (tl % ntN) * 32, k0 = (tl / ntN) * 32;
    int tx = threadIdx.x & 31, ty = threadIdx.x >> 5;
    #pragma unroll
    for (int i = ty; i < 32; i += 8)
        t[i][tx] = j.W[(size_t)(k0 + i) * j.N + n0 + tx];
    __syncthreads();
    #pragma unroll
    for (int i = ty; i < 32; i += 8) {
        float v = t[tx][i];
        __half h = __float2half_rn(v);
        j.H[(size_t)(n0 + i) * j.K + k0 + tx] = h;
        j.L[(size_t)(n0 + i) * j.K + k0 + tx] = __float2half_rn(v - __half2float(h));
    }
}

// ---------------- xproj: bx 0-1 cKV | 2-5 cQ | 6 KR(+rope). 256x256 -------
__global__ __launch_bounds__(256) void xproj_kernel(
    const __grid_constant__ XMaps maps,
    const __half* __restrict__ xh, const __half* __restrict__ xl,
    const float* __restrict__ freqs,
    float* __restrict__ cKVf, __half* __restrict__ cKVh, __half* __restrict__ cKVl,
    __half* __restrict__ cQh, __half* __restrict__ cQl,
    float* __restrict__ KRo, __half* __restrict__ Krh, __half* __restrict__ Krl)
{
    const int bx = blockIdx.x, bm = blockIdx.y * 256;
#if HAS_TCGEN05
    const CUtensorMap *Bh2, *Bl2;
    int bn;
    if (bx < 2)      { Bh2 = &maps.b0h; Bl2 = &maps.b0l; bn = bx * 256; }
    else if (bx < 6) { Bh2 = &maps.b1h; Bl2 = &maps.b1l; bn = (bx - 2) * 256; }
    else             { Bh2 = &maps.b2h; Bl2 = &maps.b2l; bn = 0; }
    TCtx cx = gemm_tma(&maps.ah, &maps.al, Bh2, Bl2, DM, bm, bn);

    const int w = threadIdx.x >> 5, l2 = threadIdx.x & 31;
    const int s2 = w >> 2, sub = w & 3;
    const int m = bm + s2 * 128 + sub * 32 + l2;
    const int t = m & (Tt - 1);
    const int b2max = (bx < 6) ? 8 : 2;
    for (int b2 = 0; b2 < b2max; b2++) {
        uint32_t r[32];
        LDTM_X32(r, cx.tmem + s2 * 256 + b2 * 32);
        T5_WAIT_LD();
        if (bx < 2) {
            size_t off = (size_t)m * KVL + bx * 256 + b2 * 32;
            #pragma unroll
            for (int j = 0; j < 32; j += 4)
                *reinterpret_cast<float4*>(&cKVf[off + j]) = make_float4(
                    __uint_as_float(r[j]), __uint_as_float(r[j+1]),
                    __uint_as_float(r[j+2]), __uint_as_float(r[j+3]));
            #pragma unroll
            for (int j = 0; j < 32; j += 8) {
                uint4 hv, lv;
                split_pair(__uint_as_float(r[j+0]), __uint_as_float(r[j+1]), hv.x, lv.x);
                split_pair(__uint_as_float(r[j+2]), __uint_as_float(r[j+3]), hv.y, lv.y);
                split_pair(__uint_as_float(r[j+4]), __uint_as_float(r[j+5]), hv.z, lv.z);
                split_pair(__uint_as_float(r[j+6]), __uint_as_float(r[j+7]), hv.w, lv.w);
                *reinterpret_cast<uint4*>(&cKVh[off + j]) = hv;
                *reinterpret_cast<uint4*>(&cKVl[off + j]) = lv;
            }
        } else if (bx < 6) {
            size_t off = (size_t)m * QL + (bx - 2) * 256 + b2 * 32;
            #pragma unroll
            for (int j = 0; j < 32; j += 8) {
                uint4 hv, lv;
                split_pair(__uint_as_float(r[j+0]), __uint_as_float(r[j+1]), hv.x, lv.x);
                split_pair(__uint_as_float(r[j+2]), __uint_as_float(r[j+3]), hv.y, lv.y);
                split_pair(__uint_as_float(r[j+4]), __uint_as_float(r[j+5]), hv.z, lv.z);
                split_pair(__uint_as_float(r[j+6]), __uint_as_float(r[j+7]), hv.w, lv.w);
                *reinterpret_cast<uint4*>(&cQh[off + j]) = hv;
                *reinterpret_cast<uint4*>(&cQl[off + j]) = lv;
            }
        } else {
            #pragma unroll
            for (int j = 0; j < 32; j += 2) {
                int col = b2 * 32 + j;
                float f = freqs[t * (Rr / 2) + (col >> 1)], s, c;
                sincosf(f, &s, &c);
                float x0 = __uint_as_float(r[j]), x1 = __uint_as_float(r[j + 1]);
                float y0 = x0 * c - x1 * s, y1 = x0 * s + x1 * c;
                size_t off = (size_t)m * Rr + col;
                KRo[off] = y0;
                KRo[off + 1] = y1;
                uint32_t hi, lo;
                split_pair(y0, y1, hi, lo);
                *reinterpret_cast<uint32_t*>(&Krh[off]) = hi;
                *reinterpret_cast<uint32_t*>(&Krl[off]) = lo;
            }
        }
    }
    __syncthreads();
    if (threadIdx.x < 32) T5_DEALLOC(cx.tmem, 512);
#else
    const int tid = threadIdx.x;
    for (int e = tid; e < 256 * 256; e += 256) {
        int rr = e >> 8, cc = e & 255;
        int m = bm + rr;
        if (bx < 2) {
            float acc = dot_hl(xh + (size_t)bm*DM, xl + (size_t)bm*DM,
                               g_WtH + O_DKV + (size_t)(bx*256)*DM,
                               g_WtL + O_DKV + (size_t)(bx*256)*DM, DM, rr, cc);
            size_t off = (size_t)m * KVL + bx * 256 + cc;
            cKVf[off] = acc;
            __half h = __float2half_rn(acc);
            cKVh[off] = h;
            cKVl[off] = __float2half_rn(acc - __half2float(h));
        } else if (bx < 6) {
            float acc = dot_hl(xh + (size_t)bm*DM, xl + (size_t)bm*DM,
                               g_WtH + O_DQ + (size_t)((bx-2)*256)*DM,
                               g_WtL + O_DQ + (size_t)((bx-2)*256)*DM, DM, rr, cc);
            size_t off = (size_t)m * QL + (bx - 2) * 256 + cc;
            __half h = __float2half_rn(acc);
            cQh[off] = h;
            cQl[off] = __float2half_rn(acc - __half2float(h));
        } else if (cc < Rr && (cc & 1) == 0) {
            float x0 = dot_hl(xh + (size_t)bm*DM, xl + (size_t)bm*DM,
                              g_WtH + O_KRP, g_WtL + O_KRP, DM, rr, cc);
            float x1 = dot_hl(xh + (size_t)bm*DM, xl + (size_t)bm*DM,
                              g_WtH + O_KRP, g_WtL + O_KRP, DM, rr, cc + 1);
            int t = m & (Tt - 1);
            float f = freqs[t * (Rr / 2) + (cc >> 1)], s, c;
            sincosf(f, &s, &c);
            float y0 = x0 * c - x1 * s, y1 = x0 * s + x1 * c;
            size_t off = (size_t)m * Rr + cc;
            KRo[off] = y0; KRo[off + 1] = y1;
            __half h0 = __float2half_rn(y0), h1 = __float2half_rn(y1);
            Krh[off] = h0; Krh[off + 1] = h1;
            Krl[off] = __float2half_rn(y0 - __half2float(h0));
            Krl[off + 1] = __float2half_rn(y1 - __half2float(h1));
        }
    }
#endif
}

// ---------------- kqproj: bx 0-7 UK | 8-15 UV | 16-23 UQ | 24-27 QR -------
__global__ __launch_bounds__(256) void kqproj_kernel(
    const __grid_constant__ KQMaps maps,
    const __half* __restrict__ cKVh, const __half* __restrict__ cKVl,
    const __half* __restrict__ cQh, const __half* __restrict__ cQl,
    const float* __restrict__ freqs,
    __half* __restrict__ Kch, __half* __restrict__ Kcl,
    __half* __restrict__ Vth, __half* __restrict__ Vtl,
    __half* __restrict__ Qch, __half* __restrict__ Qcl,
    __half* __restrict__ Qrh, __half* __restrict__ Qrl)
{
    const int bx = blockIdx.x, bm = blockIdx.y * 256;
#if HAS_TCGEN05
    const CUtensorMap *Ah2, *Al2, *Bh2, *Bl2;
    int bn, K;
    if (bx < 16) {
        Ah2 = &maps.a0h; Al2 = &maps.a0l; K = KVL;
        if (bx < 8) { Bh2 = &maps.w0h; Bl2 = &maps.w0l; bn = bx * 256; }
        else        { Bh2 = &maps.w1h; Bl2 = &maps.w1l; bn = (bx - 8) * 256; }
    } else {
        Ah2 = &maps.a1h; Al2 = &maps.a1l; K = QL;
        if (bx < 24) { Bh2 = &maps.w2h; Bl2 = &maps.w2l; bn = (bx - 16) * 256; }
        else         { Bh2 = &maps.w3h; Bl2 = &maps.w3l; bn = (bx - 24) * 256; }
    }
    TCtx cx = gemm_tma(Ah2, Al2, Bh2, Bl2, K, bm, bn);

    const int w = threadIdx.x >> 5, l2 = threadIdx.x & 31;
    const int s2 = w >> 2, sub = w & 3;
    const int m = bm + s2 * 128 + sub * 32 + l2;
    const int t = m & (Tt - 1);
    for (int b2 = 0; b2 < 8; b2++) {
        uint32_t r[32];
        LDTM_X32(r, cx.tmem + s2 * 256 + b2 * 32);
        T5_WAIT_LD();
        if (bx < 8) {
            size_t off = (size_t)m * HHD + bx * 256 + b2 * 32;
            #pragma unroll
            for (int j = 0; j < 32; j += 8) {
                uint4 hv, lv;
                split_pair(__uint_as_float(r[j+0]), __uint_as_float(r[j+1]), hv.x, lv.x);
                split_pair(__uint_as_float(r[j+2]), __uint_as_float(r[j+3]), hv.y, lv.y);
                split_pair(__uint_as_float(r[j+4]), __uint_as_float(r[j+5]), hv.z, lv.z);
                split_pair(__uint_as_float(r[j+6]), __uint_as_float(r[j+7]), hv.w, lv.w);
                *reinterpret_cast<uint4*>(&Kch[off + j]) = hv;
                *reinterpret_cast<uint4*>(&Kcl[off + j]) = lv;
            }
        } else if (bx < 16) {
            const int bq = m >> 11, tloc = m & (Tt - 1);
            #pragma unroll
            for (int j = 0; j < 32; j++) {
                int gcol = (bx - 8) * 256 + b2 * 32 + j;
                int hh2 = gcol >> 7, d = gcol & 127;
                float v = __uint_as_float(r[j]);
                __half vh = __float2half_rn(v);
                size_t off = ((size_t)(bq * Hh + hh2) * HD + d) * Tt + tloc;
                Vth[off] = vh;
                Vtl[off] = __float2half_rn(v - __half2float(vh));
            }
        } else if (bx < 24) {
            size_t off = (size_t)m * HHD + (bx - 16) * 256 + b2 * 32;
            #pragma unroll
            for (int j = 0; j < 32; j += 8) {
                uint4 hv, lv;
                split_pair(__uint_as_float(r[j+0]), __uint_as_float(r[j+1]), hv.x, lv.x);
                split_pair(__uint_as_float(r[j+2]), __uint_as_float(r[j+3]), hv.y, lv.y);
                split_pair(__uint_as_float(r[j+4]), __uint_as_float(r[j+5]), hv.z, lv.z);
                split_pair(__uint_as_float(r[j+6]), __uint_as_float(r[j+7]), hv.w, lv.w);
                *reinterpret_cast<uint4*>(&Qch[off + j]) = hv;
                *reinterpret_cast<uint4*>(&Qcl[off + j]) = lv;
            }
        } else {
            #pragma unroll
            for (int j = 0; j < 32; j += 2) {
                int gcol = (bx - 24) * 256 + b2 * 32 + j;
                float f = freqs[t * (Rr / 2) + ((gcol & 63) >> 1)], s, c;
                sincosf(f, &s, &c);
                float x0 = __uint_as_float(r[j]), x1 = __uint_as_float(r[j + 1]);
                float y0 = x0 * c - x1 * s, y1 = x0 * s + x1 * c;
                uint32_t hi, lo;
                split_pair(y0, y1, hi, lo);
                size_t off = (size_t)m * HRr + gcol;
                *reinterpret_cast<uint32_t*>(&Qrh[off]) = hi;
                *reinterpret_cast<uint32_t*>(&Qrl[off]) = lo;
            }
        }
    }
    __syncthreads();
    if (threadIdx.x < 32) T5_DEALLOC(cx.tmem, 512);
#else
    const int tid = threadIdx.x;
    for (int e = tid; e < 256 * 256; e += 256) {
        int rr = e >> 8, cc = e & 255;
        int m = bm + rr;
        if (bx < 8) {
            float acc = dot_hl(cKVh + (size_t)bm*KVL, cKVl + (size_t)bm*KVL,
                               g_WtH + O_UK + (size_t)(bx*256)*KVL,
                               g_WtL + O_UK + (size_t)(bx*256)*KVL, KVL, rr, cc);
            size_t off = (size_t)m * HHD + bx * 256 + cc;
            __half h = __float2half_rn(acc);
            Kch[off] = h;
            Kcl[off] = __float2half_rn(acc - __half2float(h));
        } else if (bx < 16) {
            float acc = dot_hl(cKVh + (size_t)bm*KVL, cKVl + (size_t)bm*KVL,
                               g_WtH + O_UV + (size_t)((bx-8)*256)*KVL,
                               g_WtL + O_UV + (size_t)((bx-8)*256)*KVL, KVL, rr, cc);
            int gcol = (bx - 8) * 256 + cc;
            int hh2 = gcol >> 7, d = gcol & 127;
            int bq = m >> 11, tloc = m & (Tt - 1);
            size_t off = ((size_t)(bq * Hh + hh2) * HD + d) * Tt + tloc;
            __half h = __float2half_rn(acc);
            Vth[off] = h;
            Vtl[off] = __float2half_rn(acc - __half2float(h));
        } else if (bx < 24) {
            float acc = dot_hl(cQh + (size_t)bm*QL, cQl + (size_t)bm*QL,
                               g_WtH + O_UQ + (size_t)((bx-16)*256)*QL,
                               g_WtL + O_UQ + (size_t)((bx-16)*256)*QL, QL, rr, cc);
            size_t off = (size_t)m * HHD + (bx - 16) * 256 + cc;
            __half h = __float2half_rn(acc);
            Qch[off] = h;
            Qcl[off] = __float2half_rn(acc - __half2float(h));
        } else if ((cc & 1) == 0) {
            float x0 = dot_hl(cQh + (size_t)bm*QL, cQl + (size_t)bm*QL,
                              g_WtH + O_QR + (size_t)((bx-24)*256)*QL,
                              g_WtL + O_QR + (size_t)((bx-24)*256)*QL, QL, rr, cc);
            float x1 = dot_hl(cQh + (size_t)bm*QL, cQl + (size_t)bm*QL,
                              g_WtH + O_QR + (size_t)((bx-24)*256)*QL,
                              g_WtL + O_QR + (size_t)((bx-24)*256)*QL, QL, rr, cc + 1);
            int gcol = (bx - 24) * 256 + cc;
            int t = m & (Tt - 1);
            float f = freqs[t * (Rr / 2) + ((gcol & 63) >> 1)], s, c;
            sincosf(f, &s, &c);
            float y0 = x0 * c - x1 * s, y1 = x0 * s + x1 * c;
            size_t off = (size_t)m * HRr + gcol;
            __half h0 = __float2half_rn(y0), h1 = __float2half_rn(y1);
            Qrh[off] = h0; Qrh[off + 1] = h1;
            Qrl[off] = __float2half_rn(y0 - __half2float(h0));
            Qrl[off + 1] = __float2half_rn(y1 - __half2float(h1));
        }
    }
#endif
}

// ---------------- wo: y = AO @ W_O (256x256 tiles) ----------------
__global__ __launch_bounds__(256) void wo_kernel(
    const __grid_constant__ WOMaps maps,
    const __half* __restrict__ AOh, const __half* __restrict__ AOl,
    float* __restrict__ y)
{
    const int bx = blockIdx.x, bm = blockIdx.y * 256;
#if HAS_TCGEN05
    TCtx cx = gemm_tma(&maps.ah, &maps.al, &maps.bh, &maps.bl,
                       HHD, bm, bx * 256);
    const int w = threadIdx.x >> 5, l2 = threadIdx.x & 31;
    const int s2 = w >> 2, sub = w & 3;
    const int m = bm + s2 * 128 + sub * 32 + l2;
    for (int b2 = 0; b2 < 8; b2++) {
        uint32_t r[32];
        LDTM_X32(r, cx.tmem + s2 * 256 + b2 * 32);
        T5_WAIT_LD();
        size_t off = (size_t)m * DM + bx * 256 + b2 * 32;
        #pragma unroll
        for (int j = 0; j < 32; j += 4)
            *reinterpret_cast<float4*>(&y[off + j]) = make_float4(
                __uint_as_float(r[j]), __uint_as_float(r[j+1]),
                __uint_as_float(r[j+2]), __uint_as_float(r[j+3]));
    }
    __syncthreads();
    if (threadIdx.x < 32) T5_DEALLOC(cx.tmem, 512);
#else
    const int tid = threadIdx.x;
    for (int e = tid; e < 256 * 256; e += 256) {
        int rr = e >> 8, cc = e & 255;
        float acc = dot_hl(AOh + (size_t)bm*HHD, AOl + (size_t)bm*HHD,
                           g_WtH + O_O + (size_t)(bx*256)*HHD,
                           g_WtL + O_O + (size_t)(bx*256)*HHD, HHD, rr, cc);
        y[(size_t)(bm + rr) * DM + bx * 256 + cc] = acc;
    }
#endif
}

// ---------------- fused flash attention (round-16 champion, unchanged) ----
__global__ __launch_bounds__(256) void flash_kernel(
    const __half* __restrict__ Qch, const __half* __restrict__ Qcl,
    const __half* __restrict__ Qrh, const __half* __restrict__ Qrl,
    const __half* __restrict__ Kch, const __half* __restrict__ Kcl,
    const __half* __restrict__ Krh, const __half* __restrict__ Krl,
    const __half* __restrict__ Vth, const __half* __restrict__ Vtl,
    __half* __restrict__ AOh, __half* __restrict__ AOl)
{
    const int qt = 15 - blockIdx.x, bh = blockIdx.y;
    const int tid = threadIdx.x;
    const int b = bh >> 4, h = bh & 15;
    const float scale = 0.07216878364870323f;   // 1/sqrt(192)
#if HAS_TCGEN05
    constexpr int T_BYTES = 16384;
    extern __shared__ char smem[];
    MmaCtx cx = mma_begin(smem, 256);
    const uint32_t qbase  = cx.tiles;
    const uint32_t pbase  = qbase + 6 * T_BYTES;
    const uint32_t redmax = pbase + 2 * T_BYTES;
    const uint32_t redsum = redmax + 1024;
    const uint32_t bufb   = redsum + 1024;
    const uint32_t idesc = (1u << 4) | (16u << 17) | (8u << 24);
    const uint32_t tmemS = cx.tmem, tmemO = cx.tmem + 128;
    const size_t qrow0 = (size_t)(b * Tt + qt * 128);

    {
        const __half* qsrc[6] = {
            Qch + qrow0 * HHD + h * HD,       Qcl + qrow0 * HHD + h * HD,
            Qch + qrow0 * HHD + h * HD + 64,  Qcl + qrow0 * HHD + h * HD + 64,
            Qrh + qrow0 * HRr + h * Rr,       Qrl + qrow0 * HRr + h * Rr };
        const int qstr[6] = {HHD, HHD, HHD, HHD, HRr, HRr};
        #pragma unroll
        for (int i = 0; i < 24; i++) {
            int u = i * 256 + tid;
            int t = u >> 10, ul = u & 1023;
            int row = ul >> 3, seg = ul & 7;
            uint4 v = *reinterpret_cast<const uint4*>(
                qsrc[t] + (size_t)row * qstr[t] + seg * 8);
            uint32_t bo = row * 128 + seg * 16;
            sts128(qbase + t * T_BYTES + (bo ^ ((bo >> 3) & 0x70)),
                   v.x, v.y, v.z, v.w);
        }
    }

    const int w = tid >> 5, l2 = tid & 31, sub = w & 3, halfi = w >> 2;
    const int rowl = sub * 32 + l2;
    const int qglob = qt * 128 + rowl;
    float oacc[64];
    #pragma unroll
    for (int j = 0; j < 64; j++) oacc[j] = 0.f;
    float mrow = -INFINITY, lrow = 0.f;
    int u0 = 0, u1 = 0;

    for (int kt = 0; kt <= qt; kt++) {
        const size_t krow0 = (size_t)(b * Tt + kt * 128);
        for (int c = 0; c < 3; c++) {
            const int bid = c & 1;
            int cnt = bid ? u1 : u0;
            const uint32_t st = bufb + bid * 2 * T_BYTES;
            const __half* kh = (c < 2) ? Kch + krow0 * HHD + h * HD + c * 64
                                       : Krh + krow0 * Rr;
            const __half* kl = (c < 2) ? Kcl + krow0 * HHD + h * HD + c * 64
                                       : Krl + krow0 * Rr;
            const int str = (c < 2) ? HHD : Rr;
            uint4 v[8];
            uint32_t da[8];
            #pragma unroll
            for (int i = 0; i < 8; i++) {
                int u = i * 256 + tid;
                int t = u >> 10, ul = u & 1023;
                int row = ul >> 3, seg = ul & 7;
                const __half* src = t ? kl : kh;
                v[i] = *reinterpret_cast<const uint4*>(
                    src + (size_t)row * str + seg * 8);
                uint32_t bo = row * 128 + seg * 16;
                da[i] = st + t * T_BYTES + (bo ^ ((bo >> 3) & 0x70));
            }
            if (cnt > 0) MBAR_WAIT(cx.mb + 8 * bid, (cnt - 1) & 1);
            #pragma unroll
            for (int i = 0; i < 8; i++)
                sts128(da[i], v[i].x, v[i].y, v[i].z, v[i].w);
            FENCE_ASYNC();
            __syncthreads();
            mma_chunk(tmemS, cx.mb + 8 * bid,
                      mk_desc(qbase + (2 * c) * T_BYTES),
                      mk_desc(qbase + (2 * c + 1) * T_BYTES),
                      mk_desc(st), mk_desc(st + T_BYTES), idesc, c == 0);
            if (bid) u1++; else u0++;
        }
        uint4 vv0[8];
        uint32_t vda0[8];
        {
            const __half* vh = Vth + (size_t)bh * HD * Tt + kt * 128;
            const __half* vl = Vtl + (size_t)bh * HD * Tt + kt * 128;
            const uint32_t st = bufb;
            #pragma unroll
            for (int i = 0; i < 8; i++) {
                int u = i * 256 + tid;
                int t = u >> 10, ul = u & 1023;
                int row = ul >> 3, seg = ul & 7;
                const __half* src = t ? vl : vh;
                vv0[i] = *reinterpret_cast<const uint4*>(
                    src + (size_t)row * Tt + seg * 8);
                uint32_t bo = row * 128 + seg * 16;
                vda0[i] = st + t * T_BYTES + (bo ^ ((bo >> 3) & 0x70));
            }
        }
        MBAR_WAIT(cx.mb + 0, (u0 - 1) & 1);
        T5_FENCE_AFTER();

        uint32_t sr[32];
        float sv[64];
        LDTM_X32(sr, tmemS + halfi * 64);
        T5_WAIT_LD();
        #pragma unroll
        for (int j = 0; j < 32; j++) sv[j] = __uint_as_float(sr[j]) * scale;
        LDTM_X32(sr, tmemS + halfi * 64 + 32);
        T5_WAIT_LD();
        #pragma unroll
        for (int j = 0; j < 32; j++) sv[32 + j] = __uint_as_float(sr[j]) * scale;
        T5_FENCE_BEFORE();
        if (kt == qt) {
            int cbase = kt * 128 + halfi * 64;
            #pragma unroll
            for (int j = 0; j < 64; j++)
                if (cbase + j > qglob) sv[j] = -INFINITY;
        }
        float pmax = -INFINITY;
        #pragma unroll
        for (int j = 0; j < 64; j++) pmax = fmaxf(pmax, sv[j]);
        asm volatile("st.shared.f32 [%0], %1;"
                     :: "r"(redmax + (halfi * 128 + rowl) * 4), "f"(pmax) : "memory");
        __syncthreads();
        float omax;
        asm volatile("ld.shared.f32 %0, [%1];"
                     : "=f"(omax) : "r"(redmax + ((1 - halfi) * 128 + rowl) * 4));
        float mnew = fmaxf(mrow, fmaxf(pmax, omax));
        float alpha = __expf(mrow - mnew);
        mrow = mnew;
        float psum = 0.f;
        uint32_t pw[32];
        #pragma unroll
        for (int j = 0; j < 32; j++) {
            float p0 = __expf(sv[2 * j] - mnew);
            float p1 = __expf(sv[2 * j + 1] - mnew);
            psum += p0 + p1;
            pw[j] = ((uint32_t)__half_as_ushort(__float2half_rn(p1)) << 16)
                  | __half_as_ushort(__float2half_rn(p0));
        }
        #pragma unroll
        for (int sgm = 0; sgm < 8; sgm++) {
            uint32_t bo = rowl * 128 + sgm * 16;
            sts128(pbase + halfi * T_BYTES + (bo ^ ((bo >> 3) & 0x70)),
                   pw[sgm * 4], pw[sgm * 4 + 1], pw[sgm * 4 + 2], pw[sgm * 4 + 3]);
        }
        asm volatile("st.shared.f32 [%0], %1;"
                     :: "r"(redsum + (halfi * 128 + rowl) * 4), "f"(psum) : "memory");
        FENCE_ASYNC();
        __syncthreads();
        float osum;
        asm volatile("ld.shared.f32 %0, [%1];"
                     : "=f"(osum) : "r"(redsum + ((1 - halfi) * 128 + rowl) * 4));
        lrow = lrow * alpha + psum + osum;

        #pragma unroll
        for (int i = 0; i < 8; i++)
            sts128(vda0[i], vv0[i].x, vv0[i].y, vv0[i].z, vv0[i].w);
        FENCE_ASYNC();
        __syncthreads();
        if (tid < 32 && elect1()) {
            uint64_t pd = mk_desc(pbase);
            uint64_t vhd = mk_desc(bufb), vld = mk_desc(bufb + T_BYTES);
            #pragma unroll
            for (int q = 0; q < 4; q++)
                mma_f16(tmemO, pd + 2 * q, vhd + 2 * q, idesc, q == 0 ? 0u : 1u);
            #pragma unroll
            for (int q = 0; q < 4; q++)
                mma_f16(tmemO, pd + 2 * q, vld + 2 * q, idesc, 1u);
            T5_COMMIT(cx.mb + 0);
        }
        u0++;

        {
            const uint32_t st = bufb + 2 * T_BYTES;
            const __half* vh = Vth + (size_t)bh * HD * Tt + kt * 128 + 64;
            const __half* vl = Vtl + (size_t)bh * HD * Tt + kt * 128 + 64;
            uint4 v[8];
            uint32_t da[8];
            #pragma unroll
            for (int i = 0; i < 8; i++) {
                int u = i * 256 + tid;
                int t = u >> 10, ul = u & 1023;
                int row = ul >> 3, seg = ul & 7;
                const __half* src = t ? vl : vh;
                v[i] = *reinterpret_cast<const uint4*>(
                    src + (size_t)row * Tt + seg * 8);
                uint32_t bo = row * 128 + seg * 16;
                da[i] = st + t * T_BYTES + (bo ^ ((bo >> 3) & 0x70));
            }
            MBAR_WAIT(cx.mb + 8, (u1 - 1) & 1);
            #pragma unroll
            for (int i = 0; i < 8; i++)
                sts128(da[i], v[i].x, v[i].y, v[i].z, v[i].w);
            FENCE_ASYNC();
            __syncthreads();
            if (tid < 32 && elect1()) {
                uint64_t pd = mk_desc(pbase + T_BYTES);
                uint64_t vhd = mk_desc(st), vld = mk_desc(st + T_BYTES);
                #pragma unroll
                for (int q = 0; q < 4; q++)
                    mma_f16(tmemO, pd + 2 * q, vhd + 2 * q, idesc, 1u);
                #pragma unroll
                for (int q = 0; q < 4; q++)
                    mma_f16(tmemO, pd + 2 * q, vld + 2 * q, idesc, 1u);
                T5_COMMIT(cx.mb + 8);
            }
            u1++;
        }
        MBAR_WAIT(cx.mb + 8, (u1 - 1) & 1);
        T5_FENCE_AFTER();
        LDTM_X32(sr, tmemO + halfi * 64);
        T5_WAIT_LD();
        #pragma unroll
        for (int j = 0; j < 32; j++)
            oacc[j] = oacc[j] * alpha + __uint_as_float(sr[j]);
        LDTM_X32(sr, tmemO + halfi * 64 + 32);
        T5_WAIT_LD();
        #pragma unroll
        for (int j = 0; j < 32; j++)
            oacc[32 + j] = oacc[32 + j] * alpha + __uint_as_float(sr[j]);
        T5_FENCE_BEFORE();
        __syncthreads();
    }

    const float invl = 1.0f / lrow;
    const size_t off = (size_t)(b * Tt + qt * 128 + rowl) * HHD + h * HD + halfi * 64;
    #pragma unroll
    for (int j = 0; j < 64; j += 8) {
        uint4 hv, lv;
        split_pair(oacc[j+0] * invl, oacc[j+1] * invl, hv.x, lv.x);
        split_pair(oacc[j+2] * invl, oacc[j+3] * invl, hv.y, lv.y);
        split_pair(oacc[j+4] * invl, oacc[j+5] * invl, hv.z, lv.z);
        split_pair(oacc[j+6] * invl, oacc[j+7] * invl, hv.w, lv.w);
        *reinterpret_cast<uint4*>(&AOh[off + j]) = hv;
        *reinterpret_cast<uint4*>(&AOl[off + j]) = lv;
    }
    __syncthreads();
    if (tid < 32) T5_DEALLOC(cx.tmem, 256);
#else
    for (int e = tid; e < 128 * 128; e += 256) {
        int r = e >> 7, d = e & 127;
        int qg = qt * 128 + r;
        size_t qoC = (size_t)(b * Tt + qg) * HHD + h * HD;
        size_t qoR = (size_t)(b * Tt + qg) * HRr + h * Rr;
        float m = -1e30f;
        for (int k = 0; k <= qg; k++) {
            size_t koC = (size_t)(b * Tt + k) * HHD + h * HD;
            size_t koR = (size_t)(b * Tt + k) * Rr;
            float s = 0.f;
            for (int dd = 0; dd < HD; dd++)
                s += (__half2float(Qch[qoC+dd]) + __half2float(Qcl[qoC+dd]))
                   * (__half2float(Kch[koC+dd]) + __half2float(Kcl[koC+dd]));
            for (int dd = 0; dd < Rr; dd++)
                s += (__half2float(Qrh[qoR+dd]) + __half2float(Qrl[qoR+dd]))
                   * (__half2float(Krh[koR+dd]) + __half2float(Krl[koR+dd]));
            s *= scale;
            if (s > m) m = s;
        }
        float l = 0.f, o = 0.f;
        for (int k = 0; k <= qg; k++) {
            size_t koC = (size_t)(b * Tt + k) * HHD + h * HD;
            size_t koR = (size_t)(b * Tt + k) * Rr;
            float s = 0.f;
            for (int dd = 0; dd < HD; dd++)
                s += (__half2float(Qch[qoC+dd]) + __half2float(Qcl[qoC+dd]))
                   * (__half2float(Kch[koC+dd]) + __half2float(Kcl[koC+dd]));
            for (int dd = 0; dd < Rr; dd++)
                s += (__half2float(Qrh[qoR+dd]) + __half2float(Qrl[qoR+dd]))
                   * (__half2float(Krh[koR+dd]) + __half2float(Krl[koR+dd]));
            float p = expf(s * scale - m);
            l += p;
            o += p * (__half2float(Vth[((size_t)bh*HD + d)*Tt + k])
                    + __half2float(Vtl[((size_t)bh*HD + d)*Tt + k]));
        }
        o /= l;
        size_t off = (size_t)(b * Tt + qg) * HHD + h * HD + d;
        __half hh = __float2half_rn(o);
        AOh[off] = hh;
        AOl[off] = __float2half_rn(o - __half2float(hh));
    }
#endif
}

// ---------------- launch ----------------
#define MMA_SMEM 198656      // ctx + 3 x 64KB stages
#define FLASH_SMEM 202752

typedef CUresult (*EncodeFn)(
    CUtensorMap*, CUtensorMapDataType, cuuint32_t, void*,
    const cuuint64_t*, const cuuint64_t*, const cuuint32_t*, const cuuint32_t*,
    CUtensorMapInterleave, CUtensorMapSwizzle, CUtensorMapL2promotion,
    CUtensorMapFloatOOBfill);

static void enc_map(EncodeFn fn, CUtensorMap* m, const __half* base,
                    uint64_t K, uint64_t rows)
{
    cuuint64_t dims[2] = {K, rows};
    cuuint64_t strides[1] = {K * 2};
    cuuint32_t box[2] = {32, 256};
    cuuint32_t es[2] = {1, 1};
    fn(m, CU_TENSOR_MAP_DATA_TYPE_UINT16, 2, (void*)base,
       dims, strides, box, es,
       CU_TENSOR_MAP_INTERLEAVE_NONE, CU_TENSOR_MAP_SWIZZLE_64B,
       CU_TENSOR_MAP_L2_PROMOTION_L2_128B, CU_TENSOR_MAP_FLOAT_OOB_FILL_NONE);
}

extern "C" void kernel_launch(void* const* d_in, const int* in_sizes, int n_in,
                              void* d_out, int out_size)
{
    const float* x     = (const float*)d_in[0];
    const float* freqs = (const float*)d_in[1];
    const float* W_DKV = (const float*)d_in[2];
    const float* W_UK  = (const float*)d_in[3];
    const float* W_UV  = (const float*)d_in[4];
    const float* W_KR  = (const float*)d_in[5];
    const float* W_DQ  = (const float*)d_in[6];
    const float* W_UQ  = (const float*)d_in[7];
    const float* W_QR  = (const float*)d_in[8];
    const float* W_O   = (const float*)d_in[9];

    float* y   = (float*)d_out;
    float* cKV = y   + (size_t)Bb * Tt * DM;
    float* KRo = cKV + (size_t)Bb * Tt * KVL;

    __half *pxH, *pxL, *pWtH, *pWtL, *pcKVh, *pcKVl, *pcQh, *pcQl;
    __half *pQch, *pQcl, *pQrh, *pQrl, *pKch, *pKcl, *pKrh, *pKrl;
    __half *pVth, *pVtl, *pAOh, *pAOl;
    cudaGetSymbolAddress((void**)&pxH,  g_xH);
    cudaGetSymbolAddress((void**)&pxL,  g_xL);
    cudaGetSymbolAddress((void**)&pWtH, g_WtH);
    cudaGetSymbolAddress((void**)&pWtL, g_WtL);
    cudaGetSymbolAddress((void**)&pcKVh, g_cKVh);
    cudaGetSymbolAddress((void**)&pcKVl, g_cKVl);
    cudaGetSymbolAddress((void**)&pcQh, g_cQh);
    cudaGetSymbolAddress((void**)&pcQl, g_cQl);
    cudaGetSymbolAddress((void**)&pQch, g_Qch);
    cudaGetSymbolAddress((void**)&pQcl, g_Qcl);
    cudaGetSymbolAddress((void**)&pQrh, g_Qrh);
    cudaGetSymbolAddress((void**)&pQrl, g_Qrl);
    cudaGetSymbolAddress((void**)&pKch, g_Kch);
    cudaGetSymbolAddress((void**)&pKcl, g_Kcl);
    cudaGetSymbolAddress((void**)&pKrh, g_Krh);
    cudaGetSymbolAddress((void**)&pKrl, g_Krl);
    cudaGetSymbolAddress((void**)&pVth, g_Vth);
    cudaGetSymbolAddress((void**)&pVtl, g_Vtl);
    cudaGetSymbolAddress((void**)&pAOh, g_AOh);
    cudaGetSymbolAddress((void**)&pAOl, g_AOl);

    // resolve cuTensorMapEncodeTiled via cudart (no -lcuda needed)
    EncodeFn efn = nullptr;
    {
        void* p = nullptr;
        cudaDriverEntryPointQueryResult qr;
        cudaGetDriverEntryPoint("cuTensorMapEncodeTiled", &p,
                                cudaEnableDefault, &qr);
        efn = (EncodeFn)p;
    }

    XMaps xm;
    enc_map(efn, &xm.ah,  pxH, DM, MROWS);
    enc_map(efn, &xm.al,  pxL, DM, MROWS);
    enc_map(efn, &xm.b0h, pWtH + O_DKV, DM, KVL);
    enc_map(efn, &xm.b0l, pWtL + O_DKV, DM, KVL);
    enc_map(efn, &xm.b1h, pWtH + O_DQ,  DM, QL);
    enc_map(efn, &xm.b1l, pWtL + O_DQ,  DM, QL);
    enc_map(efn, &xm.b2h, pWtH + O_KRP, DM, 256);
    enc_map(efn, &xm.b2l, pWtL + O_KRP, DM, 256);

    KQMaps km;
    enc_map(efn, &km.a0h, pcKVh, KVL, MROWS);
    enc_map(efn, &km.a0l, pcKVl, KVL, MROWS);
    enc_map(efn, &km.a1h, pcQh,  QL,  MROWS);
    enc_map(efn, &km.a1l, pcQl,  QL,  MROWS);
    enc_map(efn, &km.w0h, pWtH + O_UK, KVL, HHD);
    enc_map(efn, &km.w0l, pWtL + O_UK, KVL, HHD);
    enc_map(efn, &km.w1h, pWtH + O_UV, KVL, HHD);
    enc_map(efn, &km.w1l, pWtL + O_UV, KVL, HHD);
    enc_map(efn, &km.w2h, pWtH + O_UQ, QL, HHD);
    enc_map(efn, &km.w2l, pWtL + O_UQ, QL, HHD);
    enc_map(efn, &km.w3h, pWtH + O_QR, QL, HRr);
    enc_map(efn, &km.w3l, pWtL + O_QR, QL, HRr);

    WOMaps wm;
    enc_map(efn, &wm.ah, pAOh, HHD, MROWS);
    enc_map(efn, &wm.al, pAOl, HHD, MROWS);
    enc_map(efn, &wm.bh, pWtH + O_O, HHD, DM);
    enc_map(efn, &wm.bl, pWtL + O_O, HHD, DM);

    cudaFuncSetAttribute(xproj_kernel,  cudaFuncAttributeMaxDynamicSharedMemorySize, MMA_SMEM);
    cudaFuncSetAttribute(kqproj_kernel, cudaFuncAttributeMaxDynamicSharedMemorySize, MMA_SMEM);
    cudaFuncSetAttribute(wo_kernel,     cudaFuncAttributeMaxDynamicSharedMemorySize, MMA_SMEM);
    cudaFuncSetAttribute(flash_kernel,  cudaFuncAttributeMaxDynamicSharedMemorySize, FLASH_SMEM);

    // #1: split x
    split_x_kernel<<<(MROWS * DM / 4) / 256, 256>>>(x, pxH, pxL);

    // #2: all weight transposes (KR padded to 256-row tile; pad rows stay 0)
    TSJobs jobs;
    int tiles = 0;
    auto addjob = [&](int i, const float* W, size_t off, int K, int N) {
        jobs.a[i] = {W, pWtH + off, pWtL + off, K, N, tiles};
        tiles += (K / 32) * (N / 32);
    };
    addjob(0, W_DKV, O_DKV, DM, KVL);
    addjob(1, W_UK,  O_UK,  KVL, HHD);
    addjob(2, W_UV,  O_UV,  KVL, HHD);
    addjob(3, W_DQ,  O_DQ,  DM, QL);
    addjob(4, W_UQ,  O_UQ,  QL, HHD);
    addjob(5, W_QR,  O_QR,  QL, HRr);
    addjob(6, W_O,   O_O,   HHD, DM);
    addjob(7, W_KR,  O_KRP, DM, Rr);
    tsplit_all_kernel<<<tiles, 256>>>(jobs);

    // #3: xproj (cKV | cQ | KR+rope), TMA-fed 256x256
    xproj_kernel<<<dim3(7, MROWS/256), 256, MMA_SMEM>>>(
        xm, pxH, pxL, freqs, cKV, pcKVh, pcKVl, pcQh, pcQl, KRo, pKrh, pKrl);
    // #4: merged kv+q projections, TMA-fed 256x256
    kqproj_kernel<<<dim3(28, MROWS/256), 256, MMA_SMEM>>>(
        km, pcKVh, pcKVl, pcQh, pcQl, freqs,
        pKch, pKcl, pVth, pVtl, pQch, pQcl, pQrh, pQrl);
    // #5: fused flash attention
    flash_kernel<<<dim3(16, BH), 256, FLASH_SMEM>>>(
        pQch, pQcl, pQrh, pQrl, pKch, pKcl, pKrh, pKrl, pVth, pVtl, pAOh, pAOl);
    // #6: y = AO @ W_O, TMA-fed 256x256
    wo_kernel<<<dim3(8, MROWS/256), 256, MMA_SMEM>>>(wm, pAOh, pAOl, y);
}